// round 2
// baseline (speedup 1.0000x reference)
#include <cuda_runtime.h>
#include <cstdint>
#include <cstddef>

// ---------------------------------------------------------------------------
// DocumentCrossAttentionMHA: B=8, S=256, K=8, D=512, H=8  (L = S*K = 2048)
// Pipeline:
//   q   = Qin @ Wq^T + bq            [B*L, D]
//   k   = sent @ Wk^T + bk           [B*S, D]
//   v   = sent @ Wv^T + bv           [B*S, D]
//   vt  = per-(b,h) transpose of v   [B,H,hd,S]
//   s   = 0.125 * q_h @ k_h^T        [B,H,L,S]
//   s   = softmax(mask(s))
//   ctx = s @ v_h                    [B,L,D]
//   ao  = ctx @ Wo^T + bo            [B*L, D]   (written over q scratch)
//   out = mean_L( LN(Qin + ao) )     [B, D]
// ---------------------------------------------------------------------------

#define BM 128
#define BN 64
#define BK 16

static const int Bb   = 8;
static const int Ss   = 256;
static const int Dd   = 512;
static const int Hh   = 8;
static const int Ll   = 2048;    // S*K
static const int HD   = 64;      // D/H

__device__ float g_q  [16384 * 512];        // 32 MB  (q, later attn_out)
__device__ float g_k  [ 2048 * 512];        //  4 MB
__device__ float g_v  [ 2048 * 512];        //  4 MB
__device__ float g_vt [64 * 64 * 256];      //  4 MB  [B*H][hd][S]
__device__ float g_s  [64 * 2048 * 256];    // 128 MB [B*H][L][S]
__device__ float g_ctx[16384 * 512];        // 32 MB
__device__ float g_part[8 * 32 * 512];      // 0.5 MB partial LN sums

// ---------------------------------------------------------------------------
// Generalized batched GEMM: C[m][n] = alpha * sum_k A[m][k]*B[n][k] + bias[n]
// Per-z offsets: z -> (bz = z/HH, hz = z%HH), base += bz*s?b + hz*s?h
// Requires M%128==0, N%64==0, Kd%16==0, all bases/lds 16B-aligned.
// ---------------------------------------------------------------------------
__global__ __launch_bounds__(256) void gemm_tn(
    const float* __restrict__ A, const float* __restrict__ B,
    const float* __restrict__ bias, float* __restrict__ C,
    int M, int N, int Kd, int lda, int ldb, int ldc,
    int HH, long sAb, long sAh, long sBb, long sBh, long sCb, long sCh,
    float alpha)
{
    __shared__ float As[BK][BM + 4];
    __shared__ float Bs[BK][BN + 4];

    int z  = blockIdx.z;
    int bz = z / HH, hz = z - bz * HH;
    A += (size_t)bz * sAb + (size_t)hz * sAh;
    B += (size_t)bz * sBb + (size_t)hz * sBh;
    C += (size_t)bz * sCb + (size_t)hz * sCh;

    int m0 = blockIdx.y * BM;
    int n0 = blockIdx.x * BN;
    int tid  = threadIdx.x;
    int tx   = tid & 15;          // N direction (16 * 4 = 64)
    int ty   = tid >> 4;          // M direction (16 * 8 = 128)
    int lrow = tid >> 2;          // 0..63
    int lvec = tid & 3;           // float4 slot within BK

    const float* Ap = A + (size_t)(m0 + lrow) * lda + lvec * 4;
    const float* Bp = B + (size_t)(n0 + lrow) * ldb + lvec * 4;

    float acc[8][4];
#pragma unroll
    for (int i = 0; i < 8; i++)
#pragma unroll
        for (int j = 0; j < 4; j++) acc[i][j] = 0.f;

    for (int k0 = 0; k0 < Kd; k0 += BK) {
        float4 a0 = *(const float4*)(Ap + k0);
        float4 a1 = *(const float4*)(Ap + (size_t)64 * lda + k0);
        float4 b0 = *(const float4*)(Bp + k0);

        As[lvec * 4 + 0][lrow] = a0.x;
        As[lvec * 4 + 1][lrow] = a0.y;
        As[lvec * 4 + 2][lrow] = a0.z;
        As[lvec * 4 + 3][lrow] = a0.w;
        As[lvec * 4 + 0][lrow + 64] = a1.x;
        As[lvec * 4 + 1][lrow + 64] = a1.y;
        As[lvec * 4 + 2][lrow + 64] = a1.z;
        As[lvec * 4 + 3][lrow + 64] = a1.w;
        Bs[lvec * 4 + 0][lrow] = b0.x;
        Bs[lvec * 4 + 1][lrow] = b0.y;
        Bs[lvec * 4 + 2][lrow] = b0.z;
        Bs[lvec * 4 + 3][lrow] = b0.w;
        __syncthreads();

#pragma unroll
        for (int kk = 0; kk < BK; kk++) {
            float af[8], bf[4];
#pragma unroll
            for (int i = 0; i < 8; i++) af[i] = As[kk][ty * 8 + i];
#pragma unroll
            for (int j = 0; j < 4; j++) bf[j] = Bs[kk][tx * 4 + j];
#pragma unroll
            for (int i = 0; i < 8; i++)
#pragma unroll
                for (int j = 0; j < 4; j++) acc[i][j] += af[i] * bf[j];
        }
        __syncthreads();
    }

    float bv[4];
#pragma unroll
    for (int j = 0; j < 4; j++) bv[j] = bias ? bias[n0 + tx * 4 + j] : 0.f;

#pragma unroll
    for (int i = 0; i < 8; i++) {
        float* Cr = C + (size_t)(m0 + ty * 8 + i) * ldc + n0 + tx * 4;
        float4 o;
        o.x = alpha * acc[i][0] + bv[0];
        o.y = alpha * acc[i][1] + bv[1];
        o.z = alpha * acc[i][2] + bv[2];
        o.w = alpha * acc[i][3] + bv[3];
        *(float4*)Cr = o;
    }
}

// ---------------------------------------------------------------------------
// Per-(b,h) transpose: vt[bh][d][j] = v[b][j][h*64+d]
// ---------------------------------------------------------------------------
__global__ void transpose_v(const float* __restrict__ v, float* __restrict__ vt)
{
    __shared__ float t[32][33];
    int bh = blockIdx.z, b = bh >> 3, h = bh & 7;
    int j0 = blockIdx.x * 32;   // over S (8 blocks)
    int d0 = blockIdx.y * 32;   // over hd (2 blocks)
    int tx = threadIdx.x, ty = threadIdx.y;

#pragma unroll
    for (int r = 0; r < 32; r += 8)
        t[ty + r][tx] = v[((size_t)b * Ss + j0 + ty + r) * Dd + h * HD + d0 + tx];
    __syncthreads();
#pragma unroll
    for (int r = 0; r < 32; r += 8)
        vt[((size_t)bh * HD + d0 + ty + r) * Ss + j0 + tx] = t[tx][ty + r];
}

// ---------------------------------------------------------------------------
// Masked softmax, one warp per row of [B*H*L, S=256]
// ---------------------------------------------------------------------------
__global__ __launch_bounds__(256) void softmax_mask(
    float* __restrict__ P, const int* __restrict__ num_sents)
{
    int warp = threadIdx.x >> 5, lane = threadIdx.x & 31;
    long row = (long)blockIdx.x * 8 + warp;           // 131072 rows
    int b = (int)(row >> 14);                         // row / (H*L)
    float* p = P + row * Ss;
    int ns = num_sents[b];

    float v[8];
    float mx = -3.0e38f;
#pragma unroll
    for (int t = 0; t < 8; t++) {
        int j = lane + t * 32;
        float x = p[j];
        v[t] = (j < ns) ? x : -3.0e38f;
        mx = fmaxf(mx, v[t]);
    }
#pragma unroll
    for (int o = 16; o; o >>= 1) mx = fmaxf(mx, __shfl_xor_sync(0xffffffffu, mx, o));

    float s = 0.f;
#pragma unroll
    for (int t = 0; t < 8; t++) { v[t] = __expf(v[t] - mx); s += v[t]; }
#pragma unroll
    for (int o = 16; o; o >>= 1) s += __shfl_xor_sync(0xffffffffu, s, o);

    float inv = 1.f / s;
#pragma unroll
    for (int t = 0; t < 8; t++) p[lane + t * 32] = v[t] * inv;
}

// ---------------------------------------------------------------------------
// Residual + LayerNorm + partial mean over 64 rows per block.
// grid (32 chunks, 8 batches), 512 threads (one per column).
// ---------------------------------------------------------------------------
__global__ __launch_bounds__(512) void epilogue_ln(
    const float* __restrict__ qin, const float* __restrict__ ao,
    const float* __restrict__ lnw, const float* __restrict__ lnb,
    float* __restrict__ part)
{
    __shared__ float r1[16], r2[16], stats[2];
    int b = blockIdx.y, chunk = blockIdx.x;
    int col = threadIdx.x, wid = col >> 5, lane = col & 31;
    float w = lnw[col], bb = lnb[col];
    float acc = 0.f;
    size_t base = ((size_t)b * Ll + chunk * 64) * Dd + col;

    for (int r = 0; r < 64; r++) {
        size_t idx = base + (size_t)r * Dd;
        float x = qin[idx] + ao[idx];
        float s = x, s2 = x * x;
#pragma unroll
        for (int o = 16; o; o >>= 1) {
            s  += __shfl_xor_sync(0xffffffffu, s, o);
            s2 += __shfl_xor_sync(0xffffffffu, s2, o);
        }
        if (lane == 0) { r1[wid] = s; r2[wid] = s2; }
        __syncthreads();
        if (col < 32) {
            float a  = (col < 16) ? r1[col] : 0.f;
            float a2 = (col < 16) ? r2[col] : 0.f;
#pragma unroll
            for (int o = 8; o; o >>= 1) {
                a  += __shfl_xor_sync(0xffffffffu, a, o);
                a2 += __shfl_xor_sync(0xffffffffu, a2, o);
            }
            if (col == 0) { stats[0] = a; stats[1] = a2; }
        }
        __syncthreads();
        float mu  = stats[0] * (1.f / 512.f);
        float var = stats[1] * (1.f / 512.f) - mu * mu;
        float xn  = (x - mu) * rsqrtf(var + 1e-5f);
        acc += xn * w + bb;
    }
    part[((size_t)b * 32 + chunk) * Dd + col] = acc;
}

__global__ void final_reduce(const float* __restrict__ part, float* __restrict__ out)
{
    int b = blockIdx.x, col = threadIdx.x;
    float s = 0.f;
#pragma unroll
    for (int c = 0; c < 32; c++) s += part[((size_t)b * 32 + c) * Dd + col];
    out[b * Dd + col] = s * (1.f / 2048.f);
}

// ---------------------------------------------------------------------------
extern "C" void kernel_launch(void* const* d_in, const int* in_sizes, int n_in,
                              void* d_out, int out_size)
{
    (void)in_sizes; (void)n_in; (void)out_size;
    const float* qin  = (const float*)d_in[0];   // top_word_vecs [B,S,K,D] = [B,L,D]
    const float* sent = (const float*)d_in[1];   // sent_vecs    [B,S,D]
    const int*   ns   = (const int*)  d_in[2];   // num_sents    [B]
    const float* Wq   = (const float*)d_in[3];
    const float* bq   = (const float*)d_in[4];
    const float* Wk   = (const float*)d_in[5];
    const float* bk   = (const float*)d_in[6];
    const float* Wv   = (const float*)d_in[7];
    const float* bvv  = (const float*)d_in[8];
    const float* Wo   = (const float*)d_in[9];
    const float* bo   = (const float*)d_in[10];
    const float* lnw  = (const float*)d_in[11];
    const float* lnb  = (const float*)d_in[12];
    float* out = (float*)d_out;

    float *q, *k, *v, *vt, *s, *ctx, *part;
    cudaGetSymbolAddress((void**)&q,    g_q);
    cudaGetSymbolAddress((void**)&k,    g_k);
    cudaGetSymbolAddress((void**)&v,    g_v);
    cudaGetSymbolAddress((void**)&vt,   g_vt);
    cudaGetSymbolAddress((void**)&s,    g_s);
    cudaGetSymbolAddress((void**)&ctx,  g_ctx);
    cudaGetSymbolAddress((void**)&part, g_part);

    dim3 blk(256);

    // Q projection: [16384,512] = Qin @ Wq^T + bq
    gemm_tn<<<dim3(512 / BN, 16384 / BM, 1), blk>>>(
        qin, Wq, bq, q, 16384, 512, 512, 512, 512, 512,
        1, 0, 0, 0, 0, 0, 0, 1.f);

    // K projection: [2048,512]
    gemm_tn<<<dim3(512 / BN, 2048 / BM, 1), blk>>>(
        sent, Wk, bk, k, 2048, 512, 512, 512, 512, 512,
        1, 0, 0, 0, 0, 0, 0, 1.f);

    // V projection: [2048,512]
    gemm_tn<<<dim3(512 / BN, 2048 / BM, 1), blk>>>(
        sent, Wv, bvv, v, 2048, 512, 512, 512, 512, 512,
        1, 0, 0, 0, 0, 0, 0, 1.f);

    transpose_v<<<dim3(8, 2, 64), dim3(32, 8)>>>(v, vt);

    // Scores: per (b,h): [2048,256] = 0.125 * q_h @ k_h^T
    gemm_tn<<<dim3(256 / BN, 2048 / BM, 64), blk>>>(
        q, k, nullptr, s, 2048, 256, 64, 512, 512, 256,
        8,
        (long)Ll * Dd, (long)HD,          // A: q
        (long)Ss * Dd, (long)HD,          // B: k
        (long)Hh * Ll * Ss, (long)Ll * Ss,// C: s
        0.125f);

    softmax_mask<<<131072 / 8, 256>>>(s, ns);

    // Context: per (b,h): [2048,64] = P @ V  (via Vt, A·B^T form)
    gemm_tn<<<dim3(64 / BN, 2048 / BM, 64), blk>>>(
        s, vt, nullptr, ctx, 2048, 64, 256, 256, 256, 512,
        8,
        (long)Hh * Ll * Ss, (long)Ll * Ss, // A: probs
        (long)Hh * HD * Ss, (long)HD * Ss, // B: vt
        (long)Ll * Dd, (long)HD,           // C: ctx
        1.f);

    // Output projection: attn_out = ctx @ Wo^T + bo  (reuse q scratch)
    gemm_tn<<<dim3(512 / BN, 16384 / BM, 1), blk>>>(
        ctx, Wo, bo, q, 16384, 512, 512, 512, 512, 512,
        1, 0, 0, 0, 0, 0, 0, 1.f);

    // Residual + LN + partial mean, then final reduce (also initializes d_out)
    epilogue_ln<<<dim3(32, 8), 512>>>(qin, q, lnw, lnb, part);
    final_reduce<<<8, 512>>>(part, out);
}

// round 4
// speedup vs baseline: 1.3668x; 1.3668x over previous
#include <cuda_runtime.h>
#include <cuda_bf16.h>
#include <cstdint>
#include <cstddef>

typedef __nv_bfloat16 bf16;

// ======================= portable PTX helpers (sm_80+) =======================
__device__ __forceinline__ uint32_t smem_u32(const void* p) {
    uint32_t a;
    asm("{ .reg .u64 t; cvta.to.shared.u64 t, %1; cvt.u32.u64 %0, t; }" : "=r"(a) : "l"(p));
    return a;
}
__device__ __forceinline__ void cp16(uint32_t dst, const void* src) {
    asm volatile("cp.async.cg.shared.global [%0], [%1], 16;" :: "r"(dst), "l"(src));
}
__device__ __forceinline__ void ldsm4(uint32_t* r, uint32_t a) {
    asm volatile("ldmatrix.sync.aligned.m8n8.x4.shared.b16 {%0,%1,%2,%3}, [%4];"
        : "=r"(r[0]), "=r"(r[1]), "=r"(r[2]), "=r"(r[3]) : "r"(a));
}
__device__ __forceinline__ void ldsm2(uint32_t* r, uint32_t a) {
    asm volatile("ldmatrix.sync.aligned.m8n8.x2.shared.b16 {%0,%1}, [%2];"
        : "=r"(r[0]), "=r"(r[1]) : "r"(a));
}
__device__ __forceinline__ void mma16816(float* c, const uint32_t* a, const uint32_t* b) {
    asm volatile(
        "mma.sync.aligned.m16n8k16.row.col.f32.bf16.bf16.f32 "
        "{%0,%1,%2,%3}, {%4,%5,%6,%7}, {%8,%9}, {%0,%1,%2,%3};"
        : "+f"(c[0]), "+f"(c[1]), "+f"(c[2]), "+f"(c[3])
        : "r"(a[0]), "r"(a[1]), "r"(a[2]), "r"(a[3]), "r"(b[0]), "r"(b[1]));
}

// ======================= constants & scratch =======================
static const int Dd = 512, Ll = 2048;

__device__ uint4 g_qinHL_[2 * 1048576];   // qinH, qinL   (bf16, 16MB each)
__device__ uint4 g_sentHL_[2 * 131072];   // sentH, sentL
__device__ uint4 g_W_[8 * 32768];         // WqH WqL WkH WkL WvH WvL WoH WoL
__device__ uint4 g_qHL_[2 * 1048576];     // qH, qL
__device__ uint4 g_kHL_[2 * 131072];      // kH, kL
__device__ uint4 g_vtHL_[2 * 131072];     // vtH, vtL  [bh][64][256]
__device__ uint4 g_sF_[8388608];          // fp32 scores [bh][L][S]  128MB
__device__ uint4 g_pHL_[2 * 4194304];     // pH, pL (bf16 probs, 64MB each)
__device__ uint4 g_ctxHL_[2 * 1048576];   // ctxH, ctxL
__device__ uint4 g_ao_[2097152];          // fp32 attn_out 32MB
__device__ float g_part_[8 * 32 * 512];

// ---------------------------------------------------------------------------
// Batched multi-term bf16 GEMM via mma.sync:
//   acc[128 x BN] = sum_t sum_k A_t[m][k] * B_t[n][k];  out = alpha*acc + bias
// Per-z batch offsets (z -> bz = z/HH, hz = z%HH).
// Outputs: Cf (fp32) and/or Chi/Clo (bf16 hi + lo residual).
// vmode=1: scatter into vt[(b*8+h)*64+d][jj] (V-projection transpose).
// ---------------------------------------------------------------------------
template<int BN>
__global__ __launch_bounds__(256)
void gemm_mma(const bf16* A0, const bf16* A1, const bf16* A2,
              const bf16* B0, const bf16* B1, const bf16* B2,
              int nterms, const float* __restrict__ bias,
              float* __restrict__ Cf, bf16* __restrict__ Chi, bf16* __restrict__ Clo,
              int Ktot, int lda, int ldb, int ldc,
              int HH, long long sAb, long long sAh, long long sBb, long long sBh,
              long long sCb, long long sCh, float alpha, int vmode)
{
    constexpr int BM = 128, BK = 32;
    constexpr int NT = BN / 32;         // n8 tiles per warp
    constexpr int WN = BN / 4;          // warp n-extent
    __shared__ bf16 As[2][BM * BK];
    __shared__ bf16 Bs[2][BN * BK];

    const int tid = threadIdx.x, warp = tid >> 5, lane = tid & 31;
    const int wm = warp & 1, wn = warp >> 1;

    const bf16* Al[3] = {A0, A1, A2};
    const bf16* Bl[3] = {B0, B1, B2};

    const int z = blockIdx.z;
    const int bz = z / HH, hz = z - bz * HH;
    const long long aoff = (long long)bz * sAb + (long long)hz * sAh;
    const long long boff = (long long)bz * sBb + (long long)hz * sBh;
    const long long coff = (long long)bz * sCb + (long long)hz * sCh;

    const int m0 = blockIdx.y * BM;
    const int n0 = blockIdx.x * BN;

    const int kch = Ktot >> 5;
    const int total = nterms * kch;

    const int lr = tid >> 2, c4 = tid & 3;
    const uint32_t sA0 = smem_u32(&As[0][0]);
    const uint32_t sB0 = smem_u32(&Bs[0][0]);

    float acc[4][NT][4];
#pragma unroll
    for (int i = 0; i < 4; i++)
#pragma unroll
        for (int j = 0; j < NT; j++)
#pragma unroll
            for (int e = 0; e < 4; e++) acc[i][j][e] = 0.f;

    auto prefetch = [&](int chunk, int buf) {
        const int term = chunk / kch;
        const int k0 = (chunk - term * kch) << 5;
        const bf16* Ag = Al[term] + aoff + (size_t)(m0 + lr) * lda + k0 + (c4 << 3);
        const uint32_t sA = sA0 + buf * (BM * BK * 2);
#pragma unroll
        for (int p = 0; p < 2; p++) {
            const int r = lr + p * 64;
            cp16(sA + (((r << 2) + (c4 ^ ((r >> 1) & 3))) << 4), Ag + (size_t)p * 64 * lda);
        }
        const bf16* Bg = Bl[term] + boff + (size_t)(n0 + lr) * ldb + k0 + (c4 << 3);
        const uint32_t sB = sB0 + buf * (BN * BK * 2);
#pragma unroll
        for (int p = 0; p < BN / 64; p++) {
            const int r = lr + p * 64;
            cp16(sB + (((r << 2) + (c4 ^ ((r >> 1) & 3))) << 4), Bg + (size_t)p * 64 * ldb);
        }
        asm volatile("cp.async.commit_group;");
    };

    prefetch(0, 0);
    for (int it = 0; it < total; it++) {
        if (it + 1 < total) {
            prefetch(it + 1, (it + 1) & 1);
            asm volatile("cp.async.wait_group 1;");
        } else {
            asm volatile("cp.async.wait_group 0;");
        }
        __syncthreads();

        const int buf = it & 1;
        const uint32_t sA = sA0 + buf * (BM * BK * 2);
        const uint32_t sB = sB0 + buf * (BN * BK * 2);
#pragma unroll
        for (int kk = 0; kk < 2; kk++) {
            uint32_t af[4][4];
            const int ar = wm * 64 + (lane & 15);
            const int ac = (kk << 1) + (lane >> 4);
#pragma unroll
            for (int mt = 0; mt < 4; mt++) {
                const int r = ar + mt * 16;
                ldsm4(af[mt], sA + (((r << 2) + (ac ^ ((r >> 1) & 3))) << 4));
            }
            uint32_t bfr[NT][2];
            const int br = wn * WN + (lane & 7);
            const int bc = (kk << 1) + ((lane >> 3) & 1);
#pragma unroll
            for (int nt = 0; nt < NT; nt++) {
                const int r = br + nt * 8;
                ldsm2(bfr[nt], sB + (((r << 2) + (bc ^ ((r >> 1) & 3))) << 4));
            }
#pragma unroll
            for (int mt = 0; mt < 4; mt++)
#pragma unroll
                for (int nt = 0; nt < NT; nt++)
                    mma16816(acc[mt][nt], af[mt], bfr[nt]);
        }
        __syncthreads();
    }

    // ---------------- epilogue ----------------
#pragma unroll
    for (int mt = 0; mt < 4; mt++)
#pragma unroll
        for (int nt = 0; nt < NT; nt++) {
            const int gr0 = m0 + wm * 64 + mt * 16 + (lane >> 2);
            const int gc = n0 + wn * WN + nt * 8 + ((lane & 3) << 1);
            const float b0v = bias ? bias[gc] : 0.f;
            const float b1v = bias ? bias[gc + 1] : 0.f;
#pragma unroll
            for (int h2 = 0; h2 < 2; h2++) {
                const int gr = gr0 + h2 * 8;
                const float x0 = alpha * acc[mt][nt][h2 * 2 + 0] + b0v;
                const float x1 = alpha * acc[mt][nt][h2 * 2 + 1] + b1v;
                if (!vmode) {
                    const long long idx = coff + (long long)gr * ldc + gc;
                    if (Cf) { Cf[idx] = x0; Cf[idx + 1] = x1; }
                    if (Chi) {
                        bf16 h0 = __float2bfloat16_rn(x0), h1 = __float2bfloat16_rn(x1);
                        Chi[idx] = h0; Chi[idx + 1] = h1;
                        if (Clo) {
                            Clo[idx] = __float2bfloat16_rn(x0 - __bfloat162float(h0));
                            Clo[idx + 1] = __float2bfloat16_rn(x1 - __bfloat162float(h1));
                        }
                    }
                } else {
                    const int bb = gr >> 8, jj = gr & 255;
#pragma unroll
                    for (int e = 0; e < 2; e++) {
                        const float x = e ? x1 : x0;
                        const int n = gc + e, h = n >> 6, d = n & 63;
                        const size_t off = ((size_t)(bb * 8 + h) * 64 + d) * 256 + jj;
                        bf16 hh = __float2bfloat16_rn(x);
                        Chi[off] = hh;
                        Clo[off] = __float2bfloat16_rn(x - __bfloat162float(hh));
                    }
                }
            }
        }
}

// ======================= small kernels =======================
__global__ void split_kernel(const float* __restrict__ in, bf16* __restrict__ hi,
                             bf16* __restrict__ lo, int n)
{
    int i = blockIdx.x * blockDim.x + threadIdx.x;
    if (i < n) {
        float x = in[i];
        bf16 h = __float2bfloat16_rn(x);
        hi[i] = h;
        lo[i] = __float2bfloat16_rn(x - __bfloat162float(h));
    }
}

__global__ __launch_bounds__(256) void softmax_mask(
    const float* __restrict__ S, bf16* __restrict__ PH, bf16* __restrict__ PL,
    const int* __restrict__ num_sents)
{
    int warp = threadIdx.x >> 5, lane = threadIdx.x & 31;
    long row = (long)blockIdx.x * 8 + warp;
    int b = (int)(row >> 14);
    const float* sp = S + row * 256;
    bf16* ph = PH + row * 256;
    bf16* pl = PL + row * 256;
    int ns = num_sents[b];

    float v[8];
    float mx = -3.0e38f;
#pragma unroll
    for (int t = 0; t < 8; t++) {
        int j = lane + t * 32;
        float x = sp[j];
        v[t] = (j < ns) ? x : -3.0e38f;
        mx = fmaxf(mx, v[t]);
    }
#pragma unroll
    for (int o = 16; o; o >>= 1) mx = fmaxf(mx, __shfl_xor_sync(0xffffffffu, mx, o));
    float s = 0.f;
#pragma unroll
    for (int t = 0; t < 8; t++) { v[t] = __expf(v[t] - mx); s += v[t]; }
#pragma unroll
    for (int o = 16; o; o >>= 1) s += __shfl_xor_sync(0xffffffffu, s, o);
    float inv = 1.f / s;
#pragma unroll
    for (int t = 0; t < 8; t++) {
        float x = v[t] * inv;
        bf16 h = __float2bfloat16_rn(x);
        ph[lane + t * 32] = h;
        pl[lane + t * 32] = __float2bfloat16_rn(x - __bfloat162float(h));
    }
}

__global__ __launch_bounds__(512) void epilogue_ln(
    const float* __restrict__ qin, const float* __restrict__ ao,
    const float* __restrict__ lnw, const float* __restrict__ lnb,
    float* __restrict__ part)
{
    __shared__ float r1[16], r2[16], stats[2];
    int b = blockIdx.y, chunk = blockIdx.x;
    int col = threadIdx.x, wid = col >> 5, lane = col & 31;
    float w = lnw[col], bb = lnb[col];
    float acc = 0.f;
    size_t base = ((size_t)b * Ll + chunk * 64) * Dd + col;

    for (int r = 0; r < 64; r++) {
        size_t idx = base + (size_t)r * Dd;
        float x = qin[idx] + ao[idx];
        float s = x, s2 = x * x;
#pragma unroll
        for (int o = 16; o; o >>= 1) {
            s  += __shfl_xor_sync(0xffffffffu, s, o);
            s2 += __shfl_xor_sync(0xffffffffu, s2, o);
        }
        if (lane == 0) { r1[wid] = s; r2[wid] = s2; }
        __syncthreads();
        if (col < 32) {
            float a  = (col < 16) ? r1[col] : 0.f;
            float a2 = (col < 16) ? r2[col] : 0.f;
#pragma unroll
            for (int o = 8; o; o >>= 1) {
                a  += __shfl_xor_sync(0xffffffffu, a, o);
                a2 += __shfl_xor_sync(0xffffffffu, a2, o);
            }
            if (col == 0) { stats[0] = a; stats[1] = a2; }
        }
        __syncthreads();
        float mu  = stats[0] * (1.f / 512.f);
        float var = stats[1] * (1.f / 512.f) - mu * mu;
        float xn  = (x - mu) * rsqrtf(var + 1e-5f);
        acc += xn * w + bb;
    }
    part[((size_t)b * 32 + chunk) * Dd + col] = acc;
}

__global__ void final_reduce(const float* __restrict__ part, float* __restrict__ out)
{
    int b = blockIdx.x, col = threadIdx.x;
    float s = 0.f;
#pragma unroll
    for (int c = 0; c < 32; c++) s += part[((size_t)b * 32 + c) * Dd + col];
    out[b * Dd + col] = s * (1.f / 2048.f);
}

// ======================= driver =======================
extern "C" void kernel_launch(void* const* d_in, const int* in_sizes, int n_in,
                              void* d_out, int out_size)
{
    (void)in_sizes; (void)n_in; (void)out_size;
    const float* qin  = (const float*)d_in[0];
    const float* sent = (const float*)d_in[1];
    const int*   ns   = (const int*)  d_in[2];
    const float* Wq   = (const float*)d_in[3];
    const float* bq   = (const float*)d_in[4];
    const float* Wk   = (const float*)d_in[5];
    const float* bk   = (const float*)d_in[6];
    const float* Wv   = (const float*)d_in[7];
    const float* bvv  = (const float*)d_in[8];
    const float* Wo   = (const float*)d_in[9];
    const float* bo   = (const float*)d_in[10];
    const float* lnw  = (const float*)d_in[11];
    const float* lnb  = (const float*)d_in[12];
    float* out = (float*)d_out;

    void* p_;
    cudaGetSymbolAddress(&p_, g_qinHL_);  bf16* qinH = (bf16*)p_;  bf16* qinL = qinH + 8388608;
    cudaGetSymbolAddress(&p_, g_sentHL_); bf16* sentH = (bf16*)p_; bf16* sentL = sentH + 1048576;
    cudaGetSymbolAddress(&p_, g_W_);      bf16* W = (bf16*)p_;
    bf16 *WqH = W,            *WqL = W + 262144,   *WkH = W + 2*262144, *WkL = W + 3*262144;
    bf16 *WvH = W + 4*262144, *WvL = W + 5*262144, *WoH = W + 6*262144, *WoL = W + 7*262144;
    cudaGetSymbolAddress(&p_, g_qHL_);   bf16* qH  = (bf16*)p_;  bf16* qL  = qH + 8388608;
    cudaGetSymbolAddress(&p_, g_kHL_);   bf16* kH  = (bf16*)p_;  bf16* kL  = kH + 1048576;
    cudaGetSymbolAddress(&p_, g_vtHL_);  bf16* vtH = (bf16*)p_;  bf16* vtL = vtH + 1048576;
    cudaGetSymbolAddress(&p_, g_sF_);    float* sF = (float*)p_;
    cudaGetSymbolAddress(&p_, g_pHL_);   bf16* pH  = (bf16*)p_;  bf16* pL  = pH + 33554432;
    cudaGetSymbolAddress(&p_, g_ctxHL_); bf16* ctxH = (bf16*)p_; bf16* ctxL = ctxH + 8388608;
    cudaGetSymbolAddress(&p_, g_ao_);    float* ao = (float*)p_;
    cudaGetSymbolAddress(&p_, g_part_);  float* part = (float*)p_;

    // hi/lo splits of inputs
    split_kernel<<<32768, 256>>>(qin,  qinH, qinL, 8388608);
    split_kernel<<<4096,  256>>>(sent, sentH, sentL, 1048576);
    split_kernel<<<1024,  256>>>(Wq, WqH, WqL, 262144);
    split_kernel<<<1024,  256>>>(Wk, WkH, WkL, 262144);
    split_kernel<<<1024,  256>>>(Wv, WvH, WvL, 262144);
    split_kernel<<<1024,  256>>>(Wo, WoH, WoL, 262144);

    // q = Qin @ Wq^T + bq  (3-term split) -> qH,qL
    gemm_mma<128><<<dim3(4, 128, 1), 256>>>(
        qinH, qinH, qinL, WqH, WqL, WqH, 3, bq,
        nullptr, qH, qL, 512, 512, 512, 512,
        1, 0, 0, 0, 0, 0, 0, 1.f, 0);

    // k = sent @ Wk^T + bk -> kH,kL
    gemm_mma<128><<<dim3(4, 16, 1), 256>>>(
        sentH, sentH, sentL, WkH, WkL, WkH, 3, bk,
        nullptr, kH, kL, 512, 512, 512, 512,
        1, 0, 0, 0, 0, 0, 0, 1.f, 0);

    // v = sent @ Wv^T + bv -> vt[bh][d][s] hi/lo (transpose epilogue)
    gemm_mma<128><<<dim3(4, 16, 1), 256>>>(
        sentH, sentH, sentL, WvH, WvL, WvH, 3, bvv,
        nullptr, vtH, vtL, 512, 512, 512, 512,
        1, 0, 0, 0, 0, 0, 0, 1.f, 1);

    // scores = 0.125 * q @ k^T  per (b,h), fp32
    gemm_mma<128><<<dim3(2, 16, 64), 256>>>(
        qH, qH, qL, kH, kL, kH, 3, nullptr,
        sF, nullptr, nullptr, 64, 512, 512, 256,
        8, (long long)Ll * Dd, 64LL, 131072LL, 64LL,
        4194304LL, 524288LL, 0.125f, 0);

    softmax_mask<<<16384, 256>>>(sF, pH, pL, ns);

    // ctx = p @ v  per (b,h) -> ctxH,ctxL
    gemm_mma<64><<<dim3(1, 16, 64), 256>>>(
        pH, pH, pL, vtH, vtL, vtH, 3, nullptr,
        nullptr, ctxH, ctxL, 256, 256, 256, 512,
        8, 4194304LL, 524288LL, 131072LL, 16384LL,
        (long long)Ll * Dd, 64LL, 1.f, 0);

    // attn_out = ctx @ Wo^T + bo -> fp32
    gemm_mma<128><<<dim3(4, 128, 1), 256>>>(
        ctxH, ctxH, ctxL, WoH, WoL, WoH, 3, bo,
        ao, nullptr, nullptr, 512, 512, 512, 512,
        1, 0, 0, 0, 0, 0, 0, 1.f, 0);

    epilogue_ln<<<dim3(32, 8), 512>>>(qin, ao, lnw, lnb, part);
    final_reduce<<<8, 512>>>(part, out);
}

// round 5
// speedup vs baseline: 1.8488x; 1.3527x over previous
#include <cuda_runtime.h>
#include <cuda_bf16.h>
#include <cstdint>
#include <cstddef>

typedef __nv_bfloat16 bf16;

// ======================= portable PTX helpers (sm_80+) =======================
__device__ __forceinline__ uint32_t smem_u32(const void* p) {
    uint32_t a;
    asm("{ .reg .u64 t; cvta.to.shared.u64 t, %1; cvt.u32.u64 %0, t; }" : "=r"(a) : "l"(p));
    return a;
}
__device__ __forceinline__ void cp16(uint32_t dst, const void* src) {
    asm volatile("cp.async.cg.shared.global [%0], [%1], 16;" :: "r"(dst), "l"(src));
}
__device__ __forceinline__ void ldsm4(uint32_t* r, uint32_t a) {
    asm volatile("ldmatrix.sync.aligned.m8n8.x4.shared.b16 {%0,%1,%2,%3}, [%4];"
        : "=r"(r[0]), "=r"(r[1]), "=r"(r[2]), "=r"(r[3]) : "r"(a));
}
__device__ __forceinline__ void ldsm2(uint32_t* r, uint32_t a) {
    asm volatile("ldmatrix.sync.aligned.m8n8.x2.shared.b16 {%0,%1}, [%2];"
        : "=r"(r[0]), "=r"(r[1]) : "r"(a));
}
__device__ __forceinline__ void mma16816(float* c, const uint32_t* a, const uint32_t* b) {
    asm volatile(
        "mma.sync.aligned.m16n8k16.row.col.f32.bf16.bf16.f32 "
        "{%0,%1,%2,%3}, {%4,%5,%6,%7}, {%8,%9}, {%0,%1,%2,%3};"
        : "+f"(c[0]), "+f"(c[1]), "+f"(c[2]), "+f"(c[3])
        : "r"(a[0]), "r"(a[1]), "r"(a[2]), "r"(a[3]), "r"(b[0]), "r"(b[1]));
}

// ======================= constants & scratch =======================
static const int Dd = 512, Ll = 2048;

__device__ uint4 g_qinH_[1048576];        // bf16(Qin) hi          16 MB
__device__ uint4 g_sentHL_[2 * 131072];   // sentH, sentL
__device__ uint4 g_W_[8 * 32768];         // WqH WqL WkH WkL WvH WvL WoH WoL
__device__ uint4 g_qH_[1048576];          // bf16(q)               16 MB
__device__ uint4 g_kHL_[2 * 131072];      // kH, kL
__device__ uint4 g_vtHL_[2 * 131072];     // vtH, vtL [bh][64][256]
__device__ uint4 g_ctxH_[1048576];        // bf16(ctx)             16 MB
__device__ uint4 g_ao_[2097152];          // fp32 attn_out         32 MB
__device__ float g_part_[8 * 32 * 512];

// ---------------------------------------------------------------------------
// Batched multi-term bf16 GEMM via mma.sync, 3-stage cp.async pipeline.
//   acc[128 x BN] = sum_t sum_k A_t[m][k]*B_t[n][k]; out = alpha*acc + bias
// Outputs: Cf (fp32) and/or Chi/Clo (bf16 hi + optional lo residual).
// vmode=1: scatter into vt[(b*8+h)*64+d][jj] (V-projection transpose).
// ---------------------------------------------------------------------------
template<int BN>
__global__ __launch_bounds__(256)
void gemm_mma(const bf16* A0, const bf16* A1, const bf16* A2,
              const bf16* B0, const bf16* B1, const bf16* B2,
              int nterms, const float* __restrict__ bias,
              float* __restrict__ Cf, bf16* __restrict__ Chi, bf16* __restrict__ Clo,
              int Ktot, int lda, int ldb, int ldc,
              int HH, long long sAb, long long sAh, long long sBb, long long sBh,
              long long sCb, long long sCh, float alpha, int vmode)
{
    constexpr int BM = 128, BK = 32;
    constexpr int NT = BN / 32;
    constexpr int WN = BN / 4;
    __shared__ bf16 As[3][BM * BK];
    __shared__ bf16 Bs[3][BN * BK];

    const int tid = threadIdx.x, warp = tid >> 5, lane = tid & 31;
    const int wm = warp & 1, wn = warp >> 1;

    const bf16* Al[3] = {A0, A1, A2};
    const bf16* Bl[3] = {B0, B1, B2};

    const int z = blockIdx.z;
    const int bz = z / HH, hz = z - bz * HH;
    const long long aoff = (long long)bz * sAb + (long long)hz * sAh;
    const long long boff = (long long)bz * sBb + (long long)hz * sBh;
    const long long coff = (long long)bz * sCb + (long long)hz * sCh;

    const int m0 = blockIdx.y * BM;
    const int n0 = blockIdx.x * BN;

    const int kch = Ktot >> 5;
    const int total = nterms * kch;

    const int lr = tid >> 2, c4 = tid & 3;
    const uint32_t sA0 = smem_u32(&As[0][0]);
    const uint32_t sB0 = smem_u32(&Bs[0][0]);

    float acc[4][NT][4];
#pragma unroll
    for (int i = 0; i < 4; i++)
#pragma unroll
        for (int j = 0; j < NT; j++)
#pragma unroll
            for (int e = 0; e < 4; e++) acc[i][j][e] = 0.f;

    auto prefetch = [&](int chunk, int buf) {
        const int term = chunk / kch;
        const int k0 = (chunk - term * kch) << 5;
        const bf16* Ag = Al[term] + aoff + (size_t)(m0 + lr) * lda + k0 + (c4 << 3);
        const uint32_t sA = sA0 + buf * (BM * BK * 2);
#pragma unroll
        for (int p = 0; p < 2; p++) {
            const int r = lr + p * 64;
            cp16(sA + (((r << 2) + (c4 ^ ((r >> 1) & 3))) << 4), Ag + (size_t)p * 64 * lda);
        }
        const bf16* Bg = Bl[term] + boff + (size_t)(n0 + lr) * ldb + k0 + (c4 << 3);
        const uint32_t sB = sB0 + buf * (BN * BK * 2);
#pragma unroll
        for (int p = 0; p < BN / 64; p++) {
            const int r = lr + p * 64;
            cp16(sB + (((r << 2) + (c4 ^ ((r >> 1) & 3))) << 4), Bg + (size_t)p * 64 * ldb);
        }
        asm volatile("cp.async.commit_group;");
    };

    prefetch(0, 0);
    prefetch(1, 1);
    for (int it = 0; it < total; it++) {
        if (it + 1 < total) asm volatile("cp.async.wait_group 1;");
        else                asm volatile("cp.async.wait_group 0;");
        __syncthreads();
        if (it + 2 < total) prefetch(it + 2, (it + 2) % 3);

        const int buf = it % 3;
        const uint32_t sA = sA0 + buf * (BM * BK * 2);
        const uint32_t sB = sB0 + buf * (BN * BK * 2);
#pragma unroll
        for (int kk = 0; kk < 2; kk++) {
            uint32_t af[4][4];
            const int ar = wm * 64 + (lane & 15);
            const int ac = (kk << 1) + (lane >> 4);
#pragma unroll
            for (int mt = 0; mt < 4; mt++) {
                const int r = ar + mt * 16;
                ldsm4(af[mt], sA + (((r << 2) + (ac ^ ((r >> 1) & 3))) << 4));
            }
            uint32_t bfr[NT][2];
            const int br = wn * WN + (lane & 7);
            const int bc = (kk << 1) + ((lane >> 3) & 1);
#pragma unroll
            for (int nt = 0; nt < NT; nt++) {
                const int r = br + nt * 8;
                ldsm2(bfr[nt], sB + (((r << 2) + (bc ^ ((r >> 1) & 3))) << 4));
            }
#pragma unroll
            for (int mt = 0; mt < 4; mt++)
#pragma unroll
                for (int nt = 0; nt < NT; nt++)
                    mma16816(acc[mt][nt], af[mt], bfr[nt]);
        }
    }

    // ---------------- epilogue ----------------
#pragma unroll
    for (int mt = 0; mt < 4; mt++)
#pragma unroll
        for (int nt = 0; nt < NT; nt++) {
            const int gr0 = m0 + wm * 64 + mt * 16 + (lane >> 2);
            const int gc = n0 + wn * WN + nt * 8 + ((lane & 3) << 1);
            const float b0v = bias ? bias[gc] : 0.f;
            const float b1v = bias ? bias[gc + 1] : 0.f;
#pragma unroll
            for (int h2 = 0; h2 < 2; h2++) {
                const int gr = gr0 + h2 * 8;
                const float x0 = alpha * acc[mt][nt][h2 * 2 + 0] + b0v;
                const float x1 = alpha * acc[mt][nt][h2 * 2 + 1] + b1v;
                if (!vmode) {
                    const long long idx = coff + (long long)gr * ldc + gc;
                    if (Cf) { Cf[idx] = x0; Cf[idx + 1] = x1; }
                    if (Chi) {
                        bf16 h0 = __float2bfloat16_rn(x0), h1 = __float2bfloat16_rn(x1);
                        Chi[idx] = h0; Chi[idx + 1] = h1;
                        if (Clo) {
                            Clo[idx] = __float2bfloat16_rn(x0 - __bfloat162float(h0));
                            Clo[idx + 1] = __float2bfloat16_rn(x1 - __bfloat162float(h1));
                        }
                    }
                } else {
                    const int bb = gr >> 8, jj = gr & 255;
#pragma unroll
                    for (int e = 0; e < 2; e++) {
                        const float x = e ? x1 : x0;
                        const int n = gc + e, h = n >> 6, d = n & 63;
                        const size_t off = ((size_t)(bb * 8 + h) * 64 + d) * 256 + jj;
                        bf16 hh = __float2bfloat16_rn(x);
                        Chi[off] = hh;
                        Clo[off] = __float2bfloat16_rn(x - __bfloat162float(hh));
                    }
                }
            }
        }
}

// ---------------------------------------------------------------------------
// Fused attention per (b,h): S = 0.125*q@k^T (2-term k split), masked softmax,
// ctx = P@V (2-term v split). K=S=256 entirely in SMEM. Q tiles of 64 rows,
// 4 tiles per CTA. grid (8, 64), 256 threads.
// SMEM: Q 8K | KH 32K | KL 32K | VH 32K | VL 32K | P 32K  = 168 KB dynamic.
// ---------------------------------------------------------------------------
__global__ __launch_bounds__(256)
void attn_fused(const bf16* __restrict__ qHp, const bf16* __restrict__ kHp,
                const bf16* __restrict__ kLp, const bf16* __restrict__ vtHp,
                const bf16* __restrict__ vtLp, bf16* __restrict__ ctxp,
                const int* __restrict__ nsp)
{
    extern __shared__ char dsm[];
    const uint32_t uQ  = smem_u32(dsm);
    const uint32_t uKH = uQ + 8192;
    const uint32_t uKL = uQ + 40960;
    const uint32_t uVH = uQ + 73728;
    const uint32_t uVL = uQ + 106496;
    const uint32_t uP  = uQ + 139264;
    __shared__ float red[4][64];

    const int tid = threadIdx.x, warp = tid >> 5, lane = tid & 31;
    const int wm = warp & 1, wn = warp >> 1;
    const int bh = blockIdx.y, b = bh >> 3, h = bh & 7;
    const int ns = nsp[b];

    // ---- load K (256x64 hi/lo) and V^T (64x256 hi/lo) ----
    {
        const bf16* gKH = kHp + ((size_t)b * 256) * 512 + h * 64;
        const bf16* gKL = kLp + ((size_t)b * 256) * 512 + h * 64;
#pragma unroll
        for (int t = 0; t < 8; t++) {
            int id = tid + (t << 8);
            int r = id >> 3, u = id & 7;
            uint32_t off = (uint32_t)((r * 8 + (u ^ (r & 7))) << 4);
            cp16(uKH + off, gKH + (size_t)r * 512 + u * 8);
            cp16(uKL + off, gKL + (size_t)r * 512 + u * 8);
        }
        const bf16* gVH = vtHp + (size_t)bh * 16384;
        const bf16* gVL = vtLp + (size_t)bh * 16384;
#pragma unroll
        for (int t = 0; t < 8; t++) {
            int id = tid + (t << 8);
            int r = id >> 5, u = id & 31;
            uint32_t off = (uint32_t)((r * 32 + (u ^ ((r & 7) << 2))) << 4);
            cp16(uVH + off, gVH + (size_t)r * 256 + u * 8);
            cp16(uVL + off, gVL + (size_t)r * 256 + u * 8);
        }
        asm volatile("cp.async.commit_group;");
    }

    for (int tile = 0; tile < 4; tile++) {
        const int q0 = (blockIdx.x * 4 + tile) * 64;
        __syncthreads();   // protect sQ/sP reuse from previous tile
        {
            const bf16* gQ = qHp + ((size_t)b * 2048 + q0) * 512 + h * 64;
#pragma unroll
            for (int t = 0; t < 2; t++) {
                int id = tid + (t << 8);
                int r = id >> 3, u = id & 7;
                uint32_t off = (uint32_t)((r * 8 + (u ^ (r & 7))) << 4);
                cp16(uQ + off, gQ + (size_t)r * 512 + u * 8);
            }
            asm volatile("cp.async.commit_group;");
            asm volatile("cp.async.wait_group 0;");
        }
        __syncthreads();

        // ---- S[64x256] = q @ (kH|kL)^T, warp tile 32m x 64n ----
        float acc[2][8][4];
#pragma unroll
        for (int i = 0; i < 2; i++)
#pragma unroll
            for (int j = 0; j < 8; j++)
#pragma unroll
                for (int e = 0; e < 4; e++) acc[i][j][e] = 0.f;

#pragma unroll
        for (int term = 0; term < 2; term++) {
            const uint32_t kb = term ? uKL : uKH;
#pragma unroll
            for (int kk = 0; kk < 4; kk++) {
                uint32_t af[2][4];
#pragma unroll
                for (int mt = 0; mt < 2; mt++) {
                    int r = wm * 32 + mt * 16 + (lane & 15);
                    int u = kk * 2 + (lane >> 4);
                    ldsm4(af[mt], uQ + (uint32_t)((r * 8 + (u ^ (r & 7))) << 4));
                }
                uint32_t bfr[8][2];
#pragma unroll
                for (int nt = 0; nt < 8; nt++) {
                    int r = wn * 64 + nt * 8 + (lane & 7);
                    int u = kk * 2 + ((lane >> 3) & 1);
                    ldsm2(bfr[nt], kb + (uint32_t)((r * 8 + (u ^ (r & 7))) << 4));
                }
#pragma unroll
                for (int mt = 0; mt < 2; mt++)
#pragma unroll
                    for (int nt = 0; nt < 8; nt++)
                        mma16816(acc[mt][nt], af[mt], bfr[nt]);
            }
        }

        // ---- mask + row max ----
        float mxv[2][2] = {{-3.0e38f, -3.0e38f}, {-3.0e38f, -3.0e38f}};
#pragma unroll
        for (int mt = 0; mt < 2; mt++)
#pragma unroll
            for (int nt = 0; nt < 8; nt++) {
                const int cb = wn * 64 + nt * 8 + ((lane & 3) << 1);
#pragma unroll
                for (int hf = 0; hf < 2; hf++)
#pragma unroll
                    for (int e = 0; e < 2; e++) {
                        float x = (cb + e < ns) ? 0.125f * acc[mt][nt][hf * 2 + e] : -3.0e38f;
                        acc[mt][nt][hf * 2 + e] = x;
                        mxv[mt][hf] = fmaxf(mxv[mt][hf], x);
                    }
            }
#pragma unroll
        for (int mt = 0; mt < 2; mt++)
#pragma unroll
            for (int hf = 0; hf < 2; hf++) {
                mxv[mt][hf] = fmaxf(mxv[mt][hf], __shfl_xor_sync(0xffffffffu, mxv[mt][hf], 1));
                mxv[mt][hf] = fmaxf(mxv[mt][hf], __shfl_xor_sync(0xffffffffu, mxv[mt][hf], 2));
            }
        if ((lane & 3) == 0) {
#pragma unroll
            for (int mt = 0; mt < 2; mt++)
#pragma unroll
                for (int hf = 0; hf < 2; hf++)
                    red[wn][wm * 32 + mt * 16 + (lane >> 2) + hf * 8] = mxv[mt][hf];
        }
        __syncthreads();

        // ---- exp + row sum ----
        float smv[2][2];
#pragma unroll
        for (int mt = 0; mt < 2; mt++)
#pragma unroll
            for (int hf = 0; hf < 2; hf++) {
                const int r = wm * 32 + mt * 16 + (lane >> 2) + hf * 8;
                const float mx = fmaxf(fmaxf(red[0][r], red[1][r]), fmaxf(red[2][r], red[3][r]));
                float s = 0.f;
#pragma unroll
                for (int nt = 0; nt < 8; nt++)
#pragma unroll
                    for (int e = 0; e < 2; e++) {
                        float p = __expf(acc[mt][nt][hf * 2 + e] - mx);
                        acc[mt][nt][hf * 2 + e] = p;
                        s += p;
                    }
                smv[mt][hf] = s;
            }
#pragma unroll
        for (int mt = 0; mt < 2; mt++)
#pragma unroll
            for (int hf = 0; hf < 2; hf++) {
                smv[mt][hf] += __shfl_xor_sync(0xffffffffu, smv[mt][hf], 1);
                smv[mt][hf] += __shfl_xor_sync(0xffffffffu, smv[mt][hf], 2);
            }
        __syncthreads();   // all max reads done before red overwrite
        if ((lane & 3) == 0) {
#pragma unroll
            for (int mt = 0; mt < 2; mt++)
#pragma unroll
                for (int hf = 0; hf < 2; hf++)
                    red[wn][wm * 32 + mt * 16 + (lane >> 2) + hf * 8] = smv[mt][hf];
        }
        __syncthreads();

        // ---- normalize and write P (bf16) to SMEM ----
#pragma unroll
        for (int mt = 0; mt < 2; mt++)
#pragma unroll
            for (int hf = 0; hf < 2; hf++) {
                const int r = wm * 32 + mt * 16 + (lane >> 2) + hf * 8;
                const float tot = red[0][r] + red[1][r] + red[2][r] + red[3][r];
                const float inv = 1.f / tot;
#pragma unroll
                for (int nt = 0; nt < 8; nt++) {
                    const int c = wn * 64 + nt * 8 + ((lane & 3) << 1);
                    __nv_bfloat162 pr;
                    pr.x = __float2bfloat16_rn(acc[mt][nt][hf * 2 + 0] * inv);
                    pr.y = __float2bfloat16_rn(acc[mt][nt][hf * 2 + 1] * inv);
                    uint32_t addr = uP + (uint32_t)(((r * 32 + ((c >> 3) ^ ((r & 7) << 2))) << 4)
                                                    + ((c & 7) << 1));
                    asm volatile("st.shared.b32 [%0], %1;" :: "r"(addr), "r"(*(uint32_t*)&pr));
                }
            }
        __syncthreads();

        // ---- ctx[64x64] = P @ V (terms VH, VL), warp tile 32m x 16n ----
        float acc2[2][2][4];
#pragma unroll
        for (int i = 0; i < 2; i++)
#pragma unroll
            for (int j = 0; j < 2; j++)
#pragma unroll
                for (int e = 0; e < 4; e++) acc2[i][j][e] = 0.f;

#pragma unroll
        for (int term = 0; term < 2; term++) {
            const uint32_t vb = term ? uVL : uVH;
            for (int kk = 0; kk < 16; kk++) {
                uint32_t af[2][4];
#pragma unroll
                for (int mt = 0; mt < 2; mt++) {
                    int r = wm * 32 + mt * 16 + (lane & 15);
                    int u = kk * 2 + (lane >> 4);
                    ldsm4(af[mt], uP + (uint32_t)((r * 32 + (u ^ ((r & 7) << 2))) << 4));
                }
                uint32_t bf2[2][2];
#pragma unroll
                for (int nt = 0; nt < 2; nt++) {
                    int r = wn * 16 + nt * 8 + (lane & 7);
                    int u = kk * 2 + ((lane >> 3) & 1);
                    ldsm2(bf2[nt], vb + (uint32_t)((r * 32 + (u ^ ((r & 7) << 2))) << 4));
                }
#pragma unroll
                for (int mt = 0; mt < 2; mt++)
#pragma unroll
                    for (int nt = 0; nt < 2; nt++)
                        mma16816(acc2[mt][nt], af[mt], bf2[nt]);
            }
        }

        // ---- store ctx (single bf16) ----
#pragma unroll
        for (int mt = 0; mt < 2; mt++)
#pragma unroll
            for (int nt = 0; nt < 2; nt++)
#pragma unroll
                for (int hf = 0; hf < 2; hf++) {
                    const int qrow = q0 + wm * 32 + mt * 16 + (lane >> 2) + hf * 8;
                    const int d = wn * 16 + nt * 8 + ((lane & 3) << 1);
                    __nv_bfloat162 o;
                    o.x = __float2bfloat16_rn(acc2[mt][nt][hf * 2 + 0]);
                    o.y = __float2bfloat16_rn(acc2[mt][nt][hf * 2 + 1]);
                    *(__nv_bfloat162*)(ctxp + ((size_t)b * 2048 + qrow) * 512 + h * 64 + d) = o;
                }
    }
}

// ======================= small kernels =======================
__global__ void split_kernel(const float* __restrict__ in, bf16* __restrict__ hi,
                             bf16* __restrict__ lo, int n)
{
    int i = blockIdx.x * blockDim.x + threadIdx.x;
    if (i < n) {
        float x = in[i];
        bf16 h = __float2bfloat16_rn(x);
        hi[i] = h;
        if (lo) lo[i] = __float2bfloat16_rn(x - __bfloat162float(h));
    }
}

__global__ __launch_bounds__(512) void epilogue_ln(
    const float* __restrict__ qin, const float* __restrict__ ao,
    const float* __restrict__ lnw, const float* __restrict__ lnb,
    float* __restrict__ part)
{
    __shared__ float r1[16], r2[16], stats[2];
    int b = blockIdx.y, chunk = blockIdx.x;
    int col = threadIdx.x, wid = col >> 5, lane = col & 31;
    float w = lnw[col], bb = lnb[col];
    float acc = 0.f;
    size_t base = ((size_t)b * Ll + chunk * 64) * Dd + col;

    for (int r = 0; r < 64; r++) {
        size_t idx = base + (size_t)r * Dd;
        float x = qin[idx] + ao[idx];
        float s = x, s2 = x * x;
#pragma unroll
        for (int o = 16; o; o >>= 1) {
            s  += __shfl_xor_sync(0xffffffffu, s, o);
            s2 += __shfl_xor_sync(0xffffffffu, s2, o);
        }
        if (lane == 0) { r1[wid] = s; r2[wid] = s2; }
        __syncthreads();
        if (col < 32) {
            float a  = (col < 16) ? r1[col] : 0.f;
            float a2 = (col < 16) ? r2[col] : 0.f;
#pragma unroll
            for (int o = 8; o; o >>= 1) {
                a  += __shfl_xor_sync(0xffffffffu, a, o);
                a2 += __shfl_xor_sync(0xffffffffu, a2, o);
            }
            if (col == 0) { stats[0] = a; stats[1] = a2; }
        }
        __syncthreads();
        float mu  = stats[0] * (1.f / 512.f);
        float var = stats[1] * (1.f / 512.f) - mu * mu;
        float xn  = (x - mu) * rsqrtf(var + 1e-5f);
        acc += xn * w + bb;
    }
    part[((size_t)b * 32 + chunk) * Dd + col] = acc;
}

__global__ void final_reduce(const float* __restrict__ part, float* __restrict__ out)
{
    int b = blockIdx.x, col = threadIdx.x;
    float s = 0.f;
#pragma unroll
    for (int c = 0; c < 32; c++) s += part[((size_t)b * 32 + c) * Dd + col];
    out[b * Dd + col] = s * (1.f / 2048.f);
}

// ======================= driver =======================
extern "C" void kernel_launch(void* const* d_in, const int* in_sizes, int n_in,
                              void* d_out, int out_size)
{
    (void)in_sizes; (void)n_in; (void)out_size;
    const float* qin  = (const float*)d_in[0];
    const float* sent = (const float*)d_in[1];
    const int*   ns   = (const int*)  d_in[2];
    const float* Wq   = (const float*)d_in[3];
    const float* bq   = (const float*)d_in[4];
    const float* Wk   = (const float*)d_in[5];
    const float* bk   = (const float*)d_in[6];
    const float* Wv   = (const float*)d_in[7];
    const float* bvv  = (const float*)d_in[8];
    const float* Wo   = (const float*)d_in[9];
    const float* bo   = (const float*)d_in[10];
    const float* lnw  = (const float*)d_in[11];
    const float* lnb  = (const float*)d_in[12];
    float* out = (float*)d_out;

    void* p_;
    cudaGetSymbolAddress(&p_, g_qinH_);   bf16* qinH = (bf16*)p_;
    cudaGetSymbolAddress(&p_, g_sentHL_); bf16* sentH = (bf16*)p_; bf16* sentL = sentH + 1048576;
    cudaGetSymbolAddress(&p_, g_W_);      bf16* W = (bf16*)p_;
    bf16 *WqH = W,            *WqL = W + 262144,   *WkH = W + 2*262144, *WkL = W + 3*262144;
    bf16 *WvH = W + 4*262144, *WvL = W + 5*262144, *WoH = W + 6*262144, *WoL = W + 7*262144;
    cudaGetSymbolAddress(&p_, g_qH_);    bf16* qH  = (bf16*)p_;
    cudaGetSymbolAddress(&p_, g_kHL_);   bf16* kH  = (bf16*)p_;  bf16* kL  = kH + 1048576;
    cudaGetSymbolAddress(&p_, g_vtHL_);  bf16* vtH = (bf16*)p_;  bf16* vtL = vtH + 1048576;
    cudaGetSymbolAddress(&p_, g_ctxH_);  bf16* ctxH = (bf16*)p_;
    cudaGetSymbolAddress(&p_, g_ao_);    float* ao = (float*)p_;
    cudaGetSymbolAddress(&p_, g_part_);  float* part = (float*)p_;

    cudaFuncSetAttribute(attn_fused, cudaFuncAttributeMaxDynamicSharedMemorySize, 172032);

    // splits (qin: hi only)
    split_kernel<<<32768, 256>>>(qin,  qinH, nullptr, 8388608);
    split_kernel<<<4096,  256>>>(sent, sentH, sentL, 1048576);
    split_kernel<<<1024,  256>>>(Wq, WqH, WqL, 262144);
    split_kernel<<<1024,  256>>>(Wk, WkH, WkL, 262144);
    split_kernel<<<1024,  256>>>(Wv, WvH, WvL, 262144);
    split_kernel<<<1024,  256>>>(Wo, WoH, WoL, 262144);

    // q = QinH @ (WqH + WqL)^T + bq  (2 terms) -> qH (bf16)
    gemm_mma<128><<<dim3(4, 128, 1), 256>>>(
        qinH, qinH, nullptr, WqH, WqL, nullptr, 2, bq,
        nullptr, qH, nullptr, 512, 512, 512, 512,
        1, 0, 0, 0, 0, 0, 0, 1.f, 0);

    // k = sent @ Wk^T + bk  (3 terms) -> kH,kL
    gemm_mma<128><<<dim3(4, 16, 1), 256>>>(
        sentH, sentH, sentL, WkH, WkL, WkH, 3, bk,
        nullptr, kH, kL, 512, 512, 512, 512,
        1, 0, 0, 0, 0, 0, 0, 1.f, 0);

    // v = sent @ Wv^T + bv  (3 terms) -> vt[bh][d][s] hi/lo
    gemm_mma<128><<<dim3(4, 16, 1), 256>>>(
        sentH, sentH, sentL, WvH, WvL, WvH, 3, bvv,
        nullptr, vtH, vtL, 512, 512, 512, 512,
        1, 0, 0, 0, 0, 0, 0, 1.f, 1);

    // fused attention -> ctxH (bf16)
    attn_fused<<<dim3(8, 64), 256, 172032>>>(qH, kH, kL, vtH, vtL, ctxH, ns);

    // attn_out = ctx @ (WoH + WoL)^T + bo  (2 terms) -> fp32
    gemm_mma<128><<<dim3(4, 128, 1), 256>>>(
        ctxH, ctxH, nullptr, WoH, WoL, nullptr, 2, bo,
        ao, nullptr, nullptr, 512, 512, 512, 512,
        1, 0, 0, 0, 0, 0, 0, 1.f, 0);

    epilogue_ln<<<dim3(32, 8), 512>>>(qin, ao, lnw, lnb, part);
    final_reduce<<<8, 512>>>(part, out);
}

// round 8
// speedup vs baseline: 1.8501x; 1.0007x over previous
#include <cuda_runtime.h>
#include <cuda_bf16.h>
#include <cstdint>
#include <cstddef>

typedef __nv_bfloat16 bf16;

// ======================= portable PTX helpers (sm_80+) =======================
__device__ __forceinline__ uint32_t smem_u32(const void* p) {
    uint32_t a;
    asm("{ .reg .u64 t; cvta.to.shared.u64 t, %1; cvt.u32.u64 %0, t; }" : "=r"(a) : "l"(p));
    return a;
}
__device__ __forceinline__ void cp16(uint32_t dst, const void* src) {
    asm volatile("cp.async.cg.shared.global [%0], [%1], 16;" :: "r"(dst), "l"(src));
}
__device__ __forceinline__ void ldsm4(uint32_t* r, uint32_t a) {
    asm volatile("ldmatrix.sync.aligned.m8n8.x4.shared.b16 {%0,%1,%2,%3}, [%4];"
        : "=r"(r[0]), "=r"(r[1]), "=r"(r[2]), "=r"(r[3]) : "r"(a));
}
__device__ __forceinline__ void ldsm2(uint32_t* r, uint32_t a) {
    asm volatile("ldmatrix.sync.aligned.m8n8.x2.shared.b16 {%0,%1}, [%2];"
        : "=r"(r[0]), "=r"(r[1]) : "r"(a));
}
__device__ __forceinline__ void mma16816(float* c, const uint32_t* a, const uint32_t* b) {
    asm volatile(
        "mma.sync.aligned.m16n8k16.row.col.f32.bf16.bf16.f32 "
        "{%0,%1,%2,%3}, {%4,%5,%6,%7}, {%8,%9}, {%0,%1,%2,%3};"
        : "+f"(c[0]), "+f"(c[1]), "+f"(c[2]), "+f"(c[3])
        : "r"(a[0]), "r"(a[1]), "r"(a[2]), "r"(a[3]), "r"(b[0]), "r"(b[1]));
}

// ======================= constants & scratch =======================
static const int Dd = 512, Ll = 2048;

__device__ uint4 g_qinH_[1048576];        // bf16(Qin)             16 MB
__device__ uint4 g_sentHL_[2 * 131072];   // sentH, sentL
__device__ uint4 g_W_[8 * 32768];         // WqH WqL WkH WkL WvH WvL WoH WoL
__device__ uint4 g_qH_[1048576];          // bf16(q)               16 MB
__device__ uint4 g_kHL_[2 * 131072];      // kH, kL
__device__ uint4 g_vtHL_[2 * 131072];     // vtH, vtL [bh][64][256]
__device__ uint4 g_ctxH_[1048576];        // bf16(ctx)             16 MB
__device__ uint4 g_ao_[2097152];          // fp32 attn_out         32 MB
__device__ float g_part_[8 * 32 * 512];

// ---------------------------------------------------------------------------
// Generic multi-term bf16 GEMM, 64-wide warp tiles, 3-stage cp.async.
//   acc[BM x BN] = sum_t sum_k A_t[m][k]*B_t[n][k]; out = alpha*acc + bias
// Warps: (BM/WM) x (BN/WN) == 8.   vmode=1: V-proj transpose scatter.
// ---------------------------------------------------------------------------
template<int BM, int BN, int WM, int WN>
__global__ __launch_bounds__(256, 1)
void gemm_mma(const bf16* A0, const bf16* A1, const bf16* A2,
              const bf16* B0, const bf16* B1, const bf16* B2,
              int nterms, const float* __restrict__ bias,
              float* __restrict__ Cf, bf16* __restrict__ Chi, bf16* __restrict__ Clo,
              int Ktot, int lda, int ldb, int ldc,
              int HH, long long sAb, long long sAh, long long sBb, long long sBh,
              long long sCb, long long sCh, float alpha, int vmode)
{
    constexpr int BK = 32;
    constexpr int WARPS_N = BN / WN;
    constexpr int MT = WM / 16, NT = WN / 8;
    constexpr int ASZ = BM * BK * 2, BSZ = BN * BK * 2;
    static_assert((BM / WM) * (BN / WN) == 8, "8 warps");

    extern __shared__ char dynsm[];
    const uint32_t sA0 = smem_u32(dynsm);
    const uint32_t sB0 = sA0 + 3 * ASZ;

    const int tid = threadIdx.x, warp = tid >> 5, lane = tid & 31;
    const int wm = warp / WARPS_N, wn = warp % WARPS_N;

    const bf16* Al[3] = {A0, A1, A2};
    const bf16* Bl[3] = {B0, B1, B2};

    const int z = blockIdx.z;
    const int bz = z / HH, hz = z - bz * HH;
    const long long aoff = (long long)bz * sAb + (long long)hz * sAh;
    const long long boff = (long long)bz * sBb + (long long)hz * sBh;
    const long long coff = (long long)bz * sCb + (long long)hz * sCh;

    const int m0 = blockIdx.y * BM;
    const int n0 = blockIdx.x * BN;

    const int kch = Ktot >> 5;
    const int total = nterms * kch;

    const int lr = tid >> 2, c4 = tid & 3;

    float acc[MT][NT][4];
#pragma unroll
    for (int i = 0; i < MT; i++)
#pragma unroll
        for (int j = 0; j < NT; j++)
#pragma unroll
            for (int e = 0; e < 4; e++) acc[i][j][e] = 0.f;

    auto prefetch = [&](int chunk, int buf) {
        const int term = chunk / kch;
        const int k0 = (chunk - term * kch) << 5;
        const bf16* Ag = Al[term] + aoff + (size_t)(m0 + lr) * lda + k0 + (c4 << 3);
        const uint32_t sA = sA0 + buf * ASZ;
#pragma unroll
        for (int p = 0; p < BM / 64; p++) {
            const int r = lr + p * 64;
            cp16(sA + (((r << 2) + (c4 ^ ((r >> 1) & 3))) << 4), Ag + (size_t)p * 64 * lda);
        }
        const bf16* Bg = Bl[term] + boff + (size_t)(n0 + lr) * ldb + k0 + (c4 << 3);
        const uint32_t sB = sB0 + buf * BSZ;
#pragma unroll
        for (int p = 0; p < BN / 64; p++) {
            const int r = lr + p * 64;
            cp16(sB + (((r << 2) + (c4 ^ ((r >> 1) & 3))) << 4), Bg + (size_t)p * 64 * ldb);
        }
        asm volatile("cp.async.commit_group;");
    };

    prefetch(0, 0);
    prefetch(1, 1);
    for (int it = 0; it < total; it++) {
        if (it + 1 < total) asm volatile("cp.async.wait_group 1;");
        else                asm volatile("cp.async.wait_group 0;");
        __syncthreads();
        if (it + 2 < total) prefetch(it + 2, (it + 2) % 3);

        const int buf = it % 3;
        const uint32_t sA = sA0 + buf * ASZ;
        const uint32_t sB = sB0 + buf * BSZ;
#pragma unroll
        for (int kk = 0; kk < 2; kk++) {
            uint32_t af[MT][4];
#pragma unroll
            for (int mt = 0; mt < MT; mt++) {
                const int r = wm * WM + mt * 16 + (lane & 15);
                const int u = (kk << 1) + (lane >> 4);
                ldsm4(af[mt], sA + (((r << 2) + (u ^ ((r >> 1) & 3))) << 4));
            }
            uint32_t bfr[NT][2];
#pragma unroll
            for (int np = 0; np < NT / 2; np++) {
                const int r = wn * WN + np * 16 + ((lane >> 4) << 3) + (lane & 7);
                const int u = (kk << 1) + ((lane >> 3) & 1);
                ldsm4(&bfr[np * 2][0], sB + (((r << 2) + (u ^ ((r >> 1) & 3))) << 4));
            }
#pragma unroll
            for (int mt = 0; mt < MT; mt++)
#pragma unroll
                for (int nt = 0; nt < NT; nt++)
                    mma16816(acc[mt][nt], af[mt], bfr[nt]);
        }
    }

    // ---------------- epilogue ----------------
#pragma unroll
    for (int mt = 0; mt < MT; mt++)
#pragma unroll
        for (int nt = 0; nt < NT; nt++) {
            const int gr0 = m0 + wm * WM + mt * 16 + (lane >> 2);
            const int gc = n0 + wn * WN + nt * 8 + ((lane & 3) << 1);
            const float b0v = bias ? bias[gc] : 0.f;
            const float b1v = bias ? bias[gc + 1] : 0.f;
#pragma unroll
            for (int h2 = 0; h2 < 2; h2++) {
                const int gr = gr0 + h2 * 8;
                const float x0 = alpha * acc[mt][nt][h2 * 2 + 0] + b0v;
                const float x1 = alpha * acc[mt][nt][h2 * 2 + 1] + b1v;
                if (!vmode) {
                    const long long idx = coff + (long long)gr * ldc + gc;
                    if (Cf) { Cf[idx] = x0; Cf[idx + 1] = x1; }
                    if (Chi) {
                        bf16 h0 = __float2bfloat16_rn(x0), h1 = __float2bfloat16_rn(x1);
                        Chi[idx] = h0; Chi[idx + 1] = h1;
                        if (Clo) {
                            Clo[idx] = __float2bfloat16_rn(x0 - __bfloat162float(h0));
                            Clo[idx + 1] = __float2bfloat16_rn(x1 - __bfloat162float(h1));
                        }
                    }
                } else {
                    const int bb = gr >> 8, jj = gr & 255;
#pragma unroll
                    for (int e = 0; e < 2; e++) {
                        const float x = e ? x1 : x0;
                        const int n = gc + e, h = n >> 6, d = n & 63;
                        const size_t off = ((size_t)(bb * 8 + h) * 64 + d) * 256 + jj;
                        bf16 hh = __float2bfloat16_rn(x);
                        Chi[off] = hh;
                        Clo[off] = __float2bfloat16_rn(x - __bfloat162float(hh));
                    }
                }
            }
        }
}

// ---------------------------------------------------------------------------
// Fused attention per (b,h) — R5-PROVEN VERSION (172 KB SMEM, 64-row Q tiles).
// S-phase: 8 warps 2x4 -> 32x64 tiles.  P@V: 8 warps 2x4 -> 32x16 tiles.
// SMEM: Q 8K | KH 32K | KL 32K | VH 32K | VL 32K | P 32K = 168 KB dynamic.
// ---------------------------------------------------------------------------
__global__ __launch_bounds__(256)
void attn_fused(const bf16* __restrict__ qHp, const bf16* __restrict__ kHp,
                const bf16* __restrict__ kLp, const bf16* __restrict__ vtHp,
                const bf16* __restrict__ vtLp, bf16* __restrict__ ctxp,
                const int* __restrict__ nsp)
{
    extern __shared__ char dsm[];
    const uint32_t uQ  = smem_u32(dsm);
    const uint32_t uKH = uQ + 8192;
    const uint32_t uKL = uQ + 40960;
    const uint32_t uVH = uQ + 73728;
    const uint32_t uVL = uQ + 106496;
    const uint32_t uP  = uQ + 139264;
    __shared__ float red[4][64];

    const int tid = threadIdx.x, warp = tid >> 5, lane = tid & 31;
    const int wm = warp & 1, wn = warp >> 1;
    const int bh = blockIdx.y, b = bh >> 3, h = bh & 7;
    const int ns = nsp[b];

    // ---- load K (256x64 hi/lo) and V^T (64x256 hi/lo) ----
    {
        const bf16* gKH = kHp + ((size_t)b * 256) * 512 + h * 64;
        const bf16* gKL = kLp + ((size_t)b * 256) * 512 + h * 64;
#pragma unroll
        for (int t = 0; t < 8; t++) {
            int id = tid + (t << 8);
            int r = id >> 3, u = id & 7;
            uint32_t off = (uint32_t)((r * 8 + (u ^ (r & 7))) << 4);
            cp16(uKH + off, gKH + (size_t)r * 512 + u * 8);
            cp16(uKL + off, gKL + (size_t)r * 512 + u * 8);
        }
        const bf16* gVH = vtHp + (size_t)bh * 16384;
        const bf16* gVL = vtLp + (size_t)bh * 16384;
#pragma unroll
        for (int t = 0; t < 8; t++) {
            int id = tid + (t << 8);
            int r = id >> 5, u = id & 31;
            uint32_t off = (uint32_t)((r * 32 + (u ^ ((r & 7) << 2))) << 4);
            cp16(uVH + off, gVH + (size_t)r * 256 + u * 8);
            cp16(uVL + off, gVL + (size_t)r * 256 + u * 8);
        }
        asm volatile("cp.async.commit_group;");
    }

    for (int tile = 0; tile < 4; tile++) {
        const int q0 = (blockIdx.x * 4 + tile) * 64;
        __syncthreads();   // protect uQ/uP reuse from previous tile
        {
            const bf16* gQ = qHp + ((size_t)b * 2048 + q0) * 512 + h * 64;
#pragma unroll
            for (int t = 0; t < 2; t++) {
                int id = tid + (t << 8);
                int r = id >> 3, u = id & 7;
                uint32_t off = (uint32_t)((r * 8 + (u ^ (r & 7))) << 4);
                cp16(uQ + off, gQ + (size_t)r * 512 + u * 8);
            }
            asm volatile("cp.async.commit_group;");
            asm volatile("cp.async.wait_group 0;");
        }
        __syncthreads();

        // ---- S[64x256] = q @ (kH|kL)^T, warp tile 32m x 64n ----
        float acc[2][8][4];
#pragma unroll
        for (int i = 0; i < 2; i++)
#pragma unroll
            for (int j = 0; j < 8; j++)
#pragma unroll
                for (int e = 0; e < 4; e++) acc[i][j][e] = 0.f;

#pragma unroll
        for (int term = 0; term < 2; term++) {
            const uint32_t kb = term ? uKL : uKH;
#pragma unroll
            for (int kk = 0; kk < 4; kk++) {
                uint32_t af[2][4];
#pragma unroll
                for (int mt = 0; mt < 2; mt++) {
                    int r = wm * 32 + mt * 16 + (lane & 15);
                    int u = kk * 2 + (lane >> 4);
                    ldsm4(af[mt], uQ + (uint32_t)((r * 8 + (u ^ (r & 7))) << 4));
                }
                uint32_t bfr[8][2];
#pragma unroll
                for (int nt = 0; nt < 8; nt++) {
                    int r = wn * 64 + nt * 8 + (lane & 7);
                    int u = kk * 2 + ((lane >> 3) & 1);
                    ldsm2(bfr[nt], kb + (uint32_t)((r * 8 + (u ^ (r & 7))) << 4));
                }
#pragma unroll
                for (int mt = 0; mt < 2; mt++)
#pragma unroll
                    for (int nt = 0; nt < 8; nt++)
                        mma16816(acc[mt][nt], af[mt], bfr[nt]);
            }
        }

        // ---- mask + row max ----
        float mxv[2][2] = {{-3.0e38f, -3.0e38f}, {-3.0e38f, -3.0e38f}};
#pragma unroll
        for (int mt = 0; mt < 2; mt++)
#pragma unroll
            for (int nt = 0; nt < 8; nt++) {
                const int cb = wn * 64 + nt * 8 + ((lane & 3) << 1);
#pragma unroll
                for (int hf = 0; hf < 2; hf++)
#pragma unroll
                    for (int e = 0; e < 2; e++) {
                        float x = (cb + e < ns) ? 0.125f * acc[mt][nt][hf * 2 + e] : -3.0e38f;
                        acc[mt][nt][hf * 2 + e] = x;
                        mxv[mt][hf] = fmaxf(mxv[mt][hf], x);
                    }
            }
#pragma unroll
        for (int mt = 0; mt < 2; mt++)
#pragma unroll
            for (int hf = 0; hf < 2; hf++) {
                mxv[mt][hf] = fmaxf(mxv[mt][hf], __shfl_xor_sync(0xffffffffu, mxv[mt][hf], 1));
                mxv[mt][hf] = fmaxf(mxv[mt][hf], __shfl_xor_sync(0xffffffffu, mxv[mt][hf], 2));
            }
        if ((lane & 3) == 0) {
#pragma unroll
            for (int mt = 0; mt < 2; mt++)
#pragma unroll
                for (int hf = 0; hf < 2; hf++)
                    red[wn][wm * 32 + mt * 16 + (lane >> 2) + hf * 8] = mxv[mt][hf];
        }
        __syncthreads();

        // ---- exp + row sum ----
        float smv[2][2];
#pragma unroll
        for (int mt = 0; mt < 2; mt++)
#pragma unroll
            for (int hf = 0; hf < 2; hf++) {
                const int r = wm * 32 + mt * 16 + (lane >> 2) + hf * 8;
                const float mx = fmaxf(fmaxf(red[0][r], red[1][r]), fmaxf(red[2][r], red[3][r]));
                float s = 0.f;
#pragma unroll
                for (int nt = 0; nt < 8; nt++)
#pragma unroll
                    for (int e = 0; e < 2; e++) {
                        float p = __expf(acc[mt][nt][hf * 2 + e] - mx);
                        acc[mt][nt][hf * 2 + e] = p;
                        s += p;
                    }
                smv[mt][hf] = s;
            }
#pragma unroll
        for (int mt = 0; mt < 2; mt++)
#pragma unroll
            for (int hf = 0; hf < 2; hf++) {
                smv[mt][hf] += __shfl_xor_sync(0xffffffffu, smv[mt][hf], 1);
                smv[mt][hf] += __shfl_xor_sync(0xffffffffu, smv[mt][hf], 2);
            }
        __syncthreads();   // all max reads done before red overwrite
        if ((lane & 3) == 0) {
#pragma unroll
            for (int mt = 0; mt < 2; mt++)
#pragma unroll
                for (int hf = 0; hf < 2; hf++)
                    red[wn][wm * 32 + mt * 16 + (lane >> 2) + hf * 8] = smv[mt][hf];
        }
        __syncthreads();

        // ---- normalize and write P (bf16) to SMEM ----
#pragma unroll
        for (int mt = 0; mt < 2; mt++)
#pragma unroll
            for (int hf = 0; hf < 2; hf++) {
                const int r = wm * 32 + mt * 16 + (lane >> 2) + hf * 8;
                const float tot = red[0][r] + red[1][r] + red[2][r] + red[3][r];
                const float inv = 1.f / tot;
#pragma unroll
                for (int nt = 0; nt < 8; nt++) {
                    const int c = wn * 64 + nt * 8 + ((lane & 3) << 1);
                    __nv_bfloat162 pr;
                    pr.x = __float2bfloat16_rn(acc[mt][nt][hf * 2 + 0] * inv);
                    pr.y = __float2bfloat16_rn(acc[mt][nt][hf * 2 + 1] * inv);
                    uint32_t addr = uP + (uint32_t)(((r * 32 + ((c >> 3) ^ ((r & 7) << 2))) << 4)
                                                    + ((c & 7) << 1));
                    asm volatile("st.shared.b32 [%0], %1;" :: "r"(addr), "r"(*(uint32_t*)&pr));
                }
            }
        __syncthreads();

        // ---- ctx[64x64] = P @ V (terms VH, VL), warp tile 32m x 16n ----
        float acc2[2][2][4];
#pragma unroll
        for (int i = 0; i < 2; i++)
#pragma unroll
            for (int j = 0; j < 2; j++)
#pragma unroll
                for (int e = 0; e < 4; e++) acc2[i][j][e] = 0.f;

#pragma unroll
        for (int term = 0; term < 2; term++) {
            const uint32_t vb = term ? uVL : uVH;
            for (int kk = 0; kk < 16; kk++) {
                uint32_t af[2][4];
#pragma unroll
                for (int mt = 0; mt < 2; mt++) {
                    int r = wm * 32 + mt * 16 + (lane & 15);
                    int u = kk * 2 + (lane >> 4);
                    ldsm4(af[mt], uP + (uint32_t)((r * 32 + (u ^ ((r & 7) << 2))) << 4));
                }
                uint32_t bf2[2][2];
#pragma unroll
                for (int nt = 0; nt < 2; nt++) {
                    int r = wn * 16 + nt * 8 + (lane & 7);
                    int u = kk * 2 + ((lane >> 3) & 1);
                    ldsm2(bf2[nt], vb + (uint32_t)((r * 32 + (u ^ ((r & 7) << 2))) << 4));
                }
#pragma unroll
                for (int mt = 0; mt < 2; mt++)
#pragma unroll
                    for (int nt = 0; nt < 2; nt++)
                        mma16816(acc2[mt][nt], af[mt], bf2[nt]);
            }
        }

        // ---- store ctx (single bf16) ----
#pragma unroll
        for (int mt = 0; mt < 2; mt++)
#pragma unroll
            for (int nt = 0; nt < 2; nt++)
#pragma unroll
                for (int hf = 0; hf < 2; hf++) {
                    const int qrow = q0 + wm * 32 + mt * 16 + (lane >> 2) + hf * 8;
                    const int d = wn * 16 + nt * 8 + ((lane & 3) << 1);
                    __nv_bfloat162 o;
                    o.x = __float2bfloat16_rn(acc2[mt][nt][hf * 2 + 0]);
                    o.y = __float2bfloat16_rn(acc2[mt][nt][hf * 2 + 1]);
                    *(__nv_bfloat162*)(ctxp + ((size_t)b * 2048 + qrow) * 512 + h * 64 + d) = o;
                }
    }
}

// ======================= small kernels =======================
__global__ void split_kernel(const float* __restrict__ in, bf16* __restrict__ hi,
                             bf16* __restrict__ lo, int n)
{
    int i = blockIdx.x * blockDim.x + threadIdx.x;
    if (i < n) {
        float x = in[i];
        bf16 h = __float2bfloat16_rn(x);
        hi[i] = h;
        if (lo) lo[i] = __float2bfloat16_rn(x - __bfloat162float(h));
    }
}

__global__ void split_weights(const float* __restrict__ w0, const float* __restrict__ w1,
                              const float* __restrict__ w2, const float* __restrict__ w3,
                              bf16* __restrict__ base)
{
    int y = blockIdx.y;
    const float* src = (y == 0) ? w0 : (y == 1) ? w1 : (y == 2) ? w2 : w3;
    bf16* hi = base + (size_t)y * 2 * 262144;
    bf16* lo = hi + 262144;
    int i = blockIdx.x * blockDim.x + threadIdx.x;
    if (i < 262144) {
        float x = src[i];
        bf16 h = __float2bfloat16_rn(x);
        hi[i] = h;
        lo[i] = __float2bfloat16_rn(x - __bfloat162float(h));
    }
}

__global__ __launch_bounds__(512) void epilogue_ln(
    const float* __restrict__ qin, const float* __restrict__ ao,
    const float* __restrict__ lnw, const float* __restrict__ lnb,
    float* __restrict__ part)
{
    __shared__ float r1[16], r2[16], stats[2];
    int b = blockIdx.y, chunk = blockIdx.x;
    int col = threadIdx.x, wid = col >> 5, lane = col & 31;
    float w = lnw[col], bb = lnb[col];
    float acc = 0.f;
    size_t base = ((size_t)b * Ll + chunk * 64) * Dd + col;

    for (int r = 0; r < 64; r++) {
        size_t idx = base + (size_t)r * Dd;
        float x = qin[idx] + ao[idx];
        float s = x, s2 = x * x;
#pragma unroll
        for (int o = 16; o; o >>= 1) {
            s  += __shfl_xor_sync(0xffffffffu, s, o);
            s2 += __shfl_xor_sync(0xffffffffu, s2, o);
        }
        if (lane == 0) { r1[wid] = s; r2[wid] = s2; }
        __syncthreads();
        if (col < 32) {
            float a  = (col < 16) ? r1[col] : 0.f;
            float a2 = (col < 16) ? r2[col] : 0.f;
#pragma unroll
            for (int o = 8; o; o >>= 1) {
                a  += __shfl_xor_sync(0xffffffffu, a, o);
                a2 += __shfl_xor_sync(0xffffffffu, a2, o);
            }
            if (col == 0) { stats[0] = a; stats[1] = a2; }
        }
        __syncthreads();
        float mu  = stats[0] * (1.f / 512.f);
        float var = stats[1] * (1.f / 512.f) - mu * mu;
        float xn  = (x - mu) * rsqrtf(var + 1e-5f);
        acc += xn * w + bb;
    }
    part[((size_t)b * 32 + chunk) * Dd + col] = acc;
}

__global__ void final_reduce(const float* __restrict__ part, float* __restrict__ out)
{
    int b = blockIdx.x, col = threadIdx.x;
    float s = 0.f;
#pragma unroll
    for (int c = 0; c < 32; c++) s += part[((size_t)b * 32 + c) * Dd + col];
    out[b * Dd + col] = s * (1.f / 2048.f);
}

// ======================= driver =======================
extern "C" void kernel_launch(void* const* d_in, const int* in_sizes, int n_in,
                              void* d_out, int out_size)
{
    (void)in_sizes; (void)n_in; (void)out_size;
    const float* qin  = (const float*)d_in[0];
    const float* sent = (const float*)d_in[1];
    const int*   ns   = (const int*)  d_in[2];
    const float* Wq   = (const float*)d_in[3];
    const float* bq   = (const float*)d_in[4];
    const float* Wk   = (const float*)d_in[5];
    const float* bk   = (const float*)d_in[6];
    const float* Wv   = (const float*)d_in[7];
    const float* bvv  = (const float*)d_in[8];
    const float* Wo   = (const float*)d_in[9];
    const float* bo   = (const float*)d_in[10];
    const float* lnw  = (const float*)d_in[11];
    const float* lnb  = (const float*)d_in[12];
    float* out = (float*)d_out;

    void* p_;
    cudaGetSymbolAddress(&p_, g_qinH_);   bf16* qinH = (bf16*)p_;
    cudaGetSymbolAddress(&p_, g_sentHL_); bf16* sentH = (bf16*)p_; bf16* sentL = sentH + 1048576;
    cudaGetSymbolAddress(&p_, g_W_);      bf16* W = (bf16*)p_;
    bf16 *WqH = W,            *WqL = W + 262144,   *WkH = W + 2*262144, *WkL = W + 3*262144;
    bf16 *WvH = W + 4*262144, *WvL = W + 5*262144, *WoH = W + 6*262144, *WoL = W + 7*262144;
    cudaGetSymbolAddress(&p_, g_qH_);    bf16* qH  = (bf16*)p_;
    cudaGetSymbolAddress(&p_, g_kHL_);   bf16* kH  = (bf16*)p_;  bf16* kL  = kH + 1048576;
    cudaGetSymbolAddress(&p_, g_vtHL_);  bf16* vtH = (bf16*)p_;  bf16* vtL = vtH + 1048576;
    cudaGetSymbolAddress(&p_, g_ctxH_);  bf16* ctxH = (bf16*)p_;
    cudaGetSymbolAddress(&p_, g_ao_);    float* ao = (float*)p_;
    cudaGetSymbolAddress(&p_, g_part_);  float* part = (float*)p_;

    constexpr int SM_BIG = 3 * (256 * 64 + 128 * 64);   // 73728
    constexpr int SM_KV  = 3 * (64 * 64 + 128 * 64);    // 36864
    cudaFuncSetAttribute((const void*)gemm_mma<256,128,64,64>,
                         cudaFuncAttributeMaxDynamicSharedMemorySize, SM_BIG);
    cudaFuncSetAttribute((const void*)gemm_mma<64,128,32,32>,
                         cudaFuncAttributeMaxDynamicSharedMemorySize, SM_KV);
    cudaFuncSetAttribute((const void*)attn_fused,
                         cudaFuncAttributeMaxDynamicSharedMemorySize, 172032);

    // splits
    split_kernel<<<32768, 256>>>(qin,  qinH, nullptr, 8388608);
    split_kernel<<<4096,  256>>>(sent, sentH, sentL, 1048576);
    split_weights<<<dim3(1024, 4), 256>>>(Wq, Wk, Wv, Wo, W);

    // q = QinH @ (WqH + WqL)^T + bq  (2 terms) -> qH (bf16)
    gemm_mma<256,128,64,64><<<dim3(4, 64, 1), 256, SM_BIG>>>(
        qinH, qinH, nullptr, WqH, WqL, nullptr, 2, bq,
        nullptr, qH, nullptr, 512, 512, 512, 512,
        1, 0, 0, 0, 0, 0, 0, 1.f, 0);

    // k = sent @ Wk^T + bk  (3 terms) -> kH,kL
    gemm_mma<64,128,32,32><<<dim3(4, 32, 1), 256, SM_KV>>>(
        sentH, sentH, sentL, WkH, WkL, WkH, 3, bk,
        nullptr, kH, kL, 512, 512, 512, 512,
        1, 0, 0, 0, 0, 0, 0, 1.f, 0);

    // v = sent @ Wv^T + bv  (3 terms) -> vt[bh][d][s] hi/lo
    gemm_mma<64,128,32,32><<<dim3(4, 32, 1), 256, SM_KV>>>(
        sentH, sentH, sentL, WvH, WvL, WvH, 3, bvv,
        nullptr, vtH, vtL, 512, 512, 512, 512,
        1, 0, 0, 0, 0, 0, 0, 1.f, 1);

    // fused attention -> ctxH (bf16)
    attn_fused<<<dim3(8, 64), 256, 172032>>>(qH, kH, kL, vtH, vtL, ctxH, ns);

    // attn_out = ctx @ (WoH + WoL)^T + bo  (2 terms) -> fp32
    gemm_mma<256,128,64,64><<<dim3(4, 64, 1), 256, SM_BIG>>>(
        ctxH, ctxH, nullptr, WoH, WoL, nullptr, 2, bo,
        ao, nullptr, nullptr, 512, 512, 512, 512,
        1, 0, 0, 0, 0, 0, 0, 1.f, 0);

    epilogue_ln<<<dim3(32, 8), 512>>>(qin, ao, lnw, lnb, part);
    final_reduce<<<8, 512>>>(part, out);
}

// round 9
// speedup vs baseline: 2.1413x; 1.1574x over previous
#include <cuda_runtime.h>
#include <cuda_bf16.h>
#include <cstdint>
#include <cstddef>

typedef __nv_bfloat16 bf16;

// ======================= portable PTX helpers (sm_80+) =======================
__device__ __forceinline__ uint32_t smem_u32(const void* p) {
    uint32_t a;
    asm("{ .reg .u64 t; cvta.to.shared.u64 t, %1; cvt.u32.u64 %0, t; }" : "=r"(a) : "l"(p));
    return a;
}
__device__ __forceinline__ void cp16(uint32_t dst, const void* src) {
    asm volatile("cp.async.cg.shared.global [%0], [%1], 16;" :: "r"(dst), "l"(src));
}
__device__ __forceinline__ void ldsm4(uint32_t* r, uint32_t a) {
    asm volatile("ldmatrix.sync.aligned.m8n8.x4.shared.b16 {%0,%1,%2,%3}, [%4];"
        : "=r"(r[0]), "=r"(r[1]), "=r"(r[2]), "=r"(r[3]) : "r"(a));
}
__device__ __forceinline__ void mma16816(float* c, const uint32_t* a, const uint32_t* b) {
    asm volatile(
        "mma.sync.aligned.m16n8k16.row.col.f32.bf16.bf16.f32 "
        "{%0,%1,%2,%3}, {%4,%5,%6,%7}, {%8,%9}, {%0,%1,%2,%3};"
        : "+f"(c[0]), "+f"(c[1]), "+f"(c[2]), "+f"(c[3])
        : "r"(a[0]), "r"(a[1]), "r"(a[2]), "r"(a[3]), "r"(b[0]), "r"(b[1]));
}
__device__ __forceinline__ uint32_t packbf2(float lo, float hi) {
    __nv_bfloat162 p;
    p.x = __float2bfloat16_rn(lo);
    p.y = __float2bfloat16_rn(hi);
    return *(uint32_t*)&p;
}

// ======================= constants & scratch =======================
static const int Dd = 512, Ll = 2048;

__device__ uint4 g_qinH_[1048576];        // bf16(Qin)             16 MB
__device__ uint4 g_sentHL_[2 * 131072];   // sentH, sentL
__device__ uint4 g_W_[8 * 32768];         // WqH WqL WkH WkL WvH WvL WoH WoL
__device__ uint4 g_qH_[1048576];          // bf16(q)               16 MB
__device__ uint4 g_kHL_[2 * 131072];      // kH, kL
__device__ uint4 g_vtHL_[2 * 131072];     // vtH, vtL [bh][64][256]
__device__ uint4 g_ctxH_[1048576];        // bf16(ctx)             16 MB
__device__ uint4 g_ao_[2097152];          // fp32 attn_out         32 MB
__device__ float g_part_[8 * 32 * 512];

// ---------------------------------------------------------------------------
// Generic multi-term bf16 GEMM, 3-stage cp.async, 2 CTAs/SM.
//   acc[BM x BN] = sum_t sum_k A_t[m][k]*B_t[n][k]; out = alpha*acc + bias
// Warps: (BM/WM) x (BN/WN) == 8.   vmode=1: V-proj transpose scatter.
// ---------------------------------------------------------------------------
template<int BM, int BN, int WM, int WN>
__global__ __launch_bounds__(256, 2)
void gemm_mma(const bf16* A0, const bf16* A1, const bf16* A2,
              const bf16* B0, const bf16* B1, const bf16* B2,
              int nterms, const float* __restrict__ bias,
              float* __restrict__ Cf, bf16* __restrict__ Chi, bf16* __restrict__ Clo,
              int Ktot, int lda, int ldb, int ldc,
              int HH, long long sAb, long long sAh, long long sBb, long long sBh,
              long long sCb, long long sCh, float alpha, int vmode)
{
    constexpr int BK = 32;
    constexpr int WARPS_N = BN / WN;
    constexpr int MT = WM / 16, NT = WN / 8;
    constexpr int ASZ = BM * BK * 2, BSZ = BN * BK * 2;
    static_assert((BM / WM) * (BN / WN) == 8, "8 warps");

    extern __shared__ char dynsm[];
    const uint32_t sA0 = smem_u32(dynsm);
    const uint32_t sB0 = sA0 + 3 * ASZ;

    const int tid = threadIdx.x, warp = tid >> 5, lane = tid & 31;
    const int wm = warp / WARPS_N, wn = warp % WARPS_N;

    const bf16* Al[3] = {A0, A1, A2};
    const bf16* Bl[3] = {B0, B1, B2};

    const int z = blockIdx.z;
    const int bz = z / HH, hz = z - bz * HH;
    const long long aoff = (long long)bz * sAb + (long long)hz * sAh;
    const long long boff = (long long)bz * sBb + (long long)hz * sBh;
    const long long coff = (long long)bz * sCb + (long long)hz * sCh;

    const int m0 = blockIdx.y * BM;
    const int n0 = blockIdx.x * BN;

    const int kch = Ktot >> 5;
    const int total = nterms * kch;

    const int lr = tid >> 2, c4 = tid & 3;

    float acc[MT][NT][4];
#pragma unroll
    for (int i = 0; i < MT; i++)
#pragma unroll
        for (int j = 0; j < NT; j++)
#pragma unroll
            for (int e = 0; e < 4; e++) acc[i][j][e] = 0.f;

    auto prefetch = [&](int chunk, int buf) {
        const int term = chunk / kch;
        const int k0 = (chunk - term * kch) << 5;
        const bf16* Ag = Al[term] + aoff + (size_t)(m0 + lr) * lda + k0 + (c4 << 3);
        const uint32_t sA = sA0 + buf * ASZ;
#pragma unroll
        for (int p = 0; p < BM / 64; p++) {
            const int r = lr + p * 64;
            cp16(sA + (((r << 2) + (c4 ^ ((r >> 1) & 3))) << 4), Ag + (size_t)p * 64 * lda);
        }
        const bf16* Bg = Bl[term] + boff + (size_t)(n0 + lr) * ldb + k0 + (c4 << 3);
        const uint32_t sB = sB0 + buf * BSZ;
#pragma unroll
        for (int p = 0; p < BN / 64; p++) {
            const int r = lr + p * 64;
            cp16(sB + (((r << 2) + (c4 ^ ((r >> 1) & 3))) << 4), Bg + (size_t)p * 64 * ldb);
        }
        asm volatile("cp.async.commit_group;");
    };

    prefetch(0, 0);
    prefetch(1, 1);
    for (int it = 0; it < total; it++) {
        if (it + 1 < total) asm volatile("cp.async.wait_group 1;");
        else                asm volatile("cp.async.wait_group 0;");
        __syncthreads();
        if (it + 2 < total) prefetch(it + 2, (it + 2) % 3);

        const int buf = it % 3;
        const uint32_t sA = sA0 + buf * ASZ;
        const uint32_t sB = sB0 + buf * BSZ;
#pragma unroll
        for (int kk = 0; kk < 2; kk++) {
            uint32_t af[MT][4];
#pragma unroll
            for (int mt = 0; mt < MT; mt++) {
                const int r = wm * WM + mt * 16 + (lane & 15);
                const int u = (kk << 1) + (lane >> 4);
                ldsm4(af[mt], sA + (((r << 2) + (u ^ ((r >> 1) & 3))) << 4));
            }
            uint32_t bfr[NT][2];
#pragma unroll
            for (int np = 0; np < NT / 2; np++) {
                const int r = wn * WN + np * 16 + ((lane >> 4) << 3) + (lane & 7);
                const int u = (kk << 1) + ((lane >> 3) & 1);
                ldsm4(&bfr[np * 2][0], sB + (((r << 2) + (u ^ ((r >> 1) & 3))) << 4));
            }
#pragma unroll
            for (int mt = 0; mt < MT; mt++)
#pragma unroll
                for (int nt = 0; nt < NT; nt++)
                    mma16816(acc[mt][nt], af[mt], bfr[nt]);
        }
    }

    // ---------------- epilogue ----------------
#pragma unroll
    for (int mt = 0; mt < MT; mt++)
#pragma unroll
        for (int nt = 0; nt < NT; nt++) {
            const int gr0 = m0 + wm * WM + mt * 16 + (lane >> 2);
            const int gc = n0 + wn * WN + nt * 8 + ((lane & 3) << 1);
            const float b0v = bias ? bias[gc] : 0.f;
            const float b1v = bias ? bias[gc + 1] : 0.f;
#pragma unroll
            for (int h2 = 0; h2 < 2; h2++) {
                const int gr = gr0 + h2 * 8;
                const float x0 = alpha * acc[mt][nt][h2 * 2 + 0] + b0v;
                const float x1 = alpha * acc[mt][nt][h2 * 2 + 1] + b1v;
                if (!vmode) {
                    const long long idx = coff + (long long)gr * ldc + gc;
                    if (Cf) { Cf[idx] = x0; Cf[idx + 1] = x1; }
                    if (Chi) {
                        bf16 h0 = __float2bfloat16_rn(x0), h1 = __float2bfloat16_rn(x1);
                        Chi[idx] = h0; Chi[idx + 1] = h1;
                        if (Clo) {
                            Clo[idx] = __float2bfloat16_rn(x0 - __bfloat162float(h0));
                            Clo[idx + 1] = __float2bfloat16_rn(x1 - __bfloat162float(h1));
                        }
                    }
                } else {
                    const int bb = gr >> 8, jj = gr & 255;
#pragma unroll
                    for (int e = 0; e < 2; e++) {
                        const float x = e ? x1 : x0;
                        const int n = gc + e, h = n >> 6, d = n & 63;
                        const size_t off = ((size_t)(bb * 8 + h) * 64 + d) * 256 + jj;
                        bf16 hh = __float2bfloat16_rn(x);
                        Chi[off] = hh;
                        Clo[off] = __float2bfloat16_rn(x - __bfloat162float(hh));
                    }
                }
            }
        }
}

// ---------------------------------------------------------------------------
// Fused attention, FA2-style register path. One CTA = one (b,h) x 128 Q rows.
// 8 warps, warp w owns rows [16w,16w+16): full 256-col S rows -> softmax is
// warp-local (quad shfl only); P stays in registers (C-frag -> A-frag repack).
// SMEM: Q 16K | KH 32K | KL 32K | VH 32K | VL 32K = 144 KB. grid (16, 64).
// ---------------------------------------------------------------------------
__global__ __launch_bounds__(256, 1)
void attn_fused(const bf16* __restrict__ qHp, const bf16* __restrict__ kHp,
                const bf16* __restrict__ kLp, const bf16* __restrict__ vtHp,
                const bf16* __restrict__ vtLp, bf16* __restrict__ ctxp,
                const int* __restrict__ nsp)
{
    extern __shared__ char dsm[];
    const uint32_t uQ  = smem_u32(dsm);
    const uint32_t uKH = uQ + 16384;
    const uint32_t uKL = uQ + 49152;
    const uint32_t uVH = uQ + 81920;
    const uint32_t uVL = uQ + 114688;

    const int tid = threadIdx.x, warp = tid >> 5, lane = tid & 31;
    const int bh = blockIdx.y, b = bh >> 3, h = bh & 7;
    const int ns = nsp[b];
    const int q0 = blockIdx.x * 128;

    // ---- loads: Q(128x64), K(256x64 hi/lo), V^T(64x256 hi/lo) ----
    {
        const bf16* gQ = qHp + ((size_t)b * 2048 + q0) * 512 + h * 64;
#pragma unroll
        for (int t = 0; t < 4; t++) {
            int id = tid + (t << 8);
            int r = id >> 3, u = id & 7;
            cp16(uQ + (uint32_t)((r * 8 + (u ^ (r & 7))) << 4), gQ + (size_t)r * 512 + u * 8);
        }
        const bf16* gKH = kHp + ((size_t)b * 256) * 512 + h * 64;
        const bf16* gKL = kLp + ((size_t)b * 256) * 512 + h * 64;
#pragma unroll
        for (int t = 0; t < 8; t++) {
            int id = tid + (t << 8);
            int r = id >> 3, u = id & 7;
            uint32_t off = (uint32_t)((r * 8 + (u ^ (r & 7))) << 4);
            cp16(uKH + off, gKH + (size_t)r * 512 + u * 8);
            cp16(uKL + off, gKL + (size_t)r * 512 + u * 8);
        }
        const bf16* gVH = vtHp + (size_t)bh * 16384;
        const bf16* gVL = vtLp + (size_t)bh * 16384;
#pragma unroll
        for (int t = 0; t < 8; t++) {
            int id = tid + (t << 8);
            int r = id >> 5, u = id & 31;
            uint32_t off = (uint32_t)((r * 32 + (u ^ ((r & 7) << 2))) << 4);
            cp16(uVH + off, gVH + (size_t)r * 256 + u * 8);
            cp16(uVL + off, gVL + (size_t)r * 256 + u * 8);
        }
        asm volatile("cp.async.commit_group;");
        asm volatile("cp.async.wait_group 0;");
    }
    __syncthreads();

    // ---- S[16x256] per warp = q @ (kH|kL)^T ----
    float acc[32][4];
#pragma unroll
    for (int j = 0; j < 32; j++)
#pragma unroll
        for (int e = 0; e < 4; e++) acc[j][e] = 0.f;

#pragma unroll
    for (int term = 0; term < 2; term++) {
        const uint32_t kb = term ? uKL : uKH;
#pragma unroll
        for (int kk = 0; kk < 4; kk++) {
            uint32_t af[4];
            {
                int r = warp * 16 + (lane & 15);
                int u = kk * 2 + (lane >> 4);
                ldsm4(af, uQ + (uint32_t)((r * 8 + (u ^ (r & 7))) << 4));
            }
#pragma unroll
            for (int nc = 0; nc < 4; nc++) {
                uint32_t bfr[8][2];
#pragma unroll
                for (int np = 0; np < 4; np++) {
                    int r = nc * 64 + np * 16 + ((lane >> 4) << 3) + (lane & 7);
                    int u = kk * 2 + ((lane >> 3) & 1);
                    ldsm4(&bfr[np * 2][0], kb + (uint32_t)((r * 8 + (u ^ (r & 7))) << 4));
                }
#pragma unroll
                for (int nt = 0; nt < 8; nt++)
                    mma16816(acc[nc * 8 + nt], af, bfr[nt]);
            }
        }
    }

    // ---- mask + warp-local softmax (rows owned by quads) ----
    float mx[2] = {-3.0e38f, -3.0e38f};
#pragma unroll
    for (int nt = 0; nt < 32; nt++) {
        const int cb = nt * 8 + ((lane & 3) << 1);
#pragma unroll
        for (int hf = 0; hf < 2; hf++)
#pragma unroll
            for (int e = 0; e < 2; e++) {
                float x = (cb + e < ns) ? 0.125f * acc[nt][hf * 2 + e] : -3.0e38f;
                acc[nt][hf * 2 + e] = x;
                mx[hf] = fmaxf(mx[hf], x);
            }
    }
#pragma unroll
    for (int hf = 0; hf < 2; hf++) {
        mx[hf] = fmaxf(mx[hf], __shfl_xor_sync(0xffffffffu, mx[hf], 1));
        mx[hf] = fmaxf(mx[hf], __shfl_xor_sync(0xffffffffu, mx[hf], 2));
    }
    float sm[2] = {0.f, 0.f};
#pragma unroll
    for (int nt = 0; nt < 32; nt++)
#pragma unroll
        for (int hf = 0; hf < 2; hf++)
#pragma unroll
            for (int e = 0; e < 2; e++) {
                float p = __expf(acc[nt][hf * 2 + e] - mx[hf]);
                acc[nt][hf * 2 + e] = p;
                sm[hf] += p;
            }
#pragma unroll
    for (int hf = 0; hf < 2; hf++) {
        sm[hf] += __shfl_xor_sync(0xffffffffu, sm[hf], 1);
        sm[hf] += __shfl_xor_sync(0xffffffffu, sm[hf], 2);
    }
    const float inv0 = 1.f / sm[0], inv1 = 1.f / sm[1];

    // ---- pack P (C-frag -> A-frag): pa[kt][0..3] covers k=16kt..16kt+15 ----
    uint32_t pa[64];
#pragma unroll
    for (int kt = 0; kt < 16; kt++) {
        const int t0 = 2 * kt, t1 = 2 * kt + 1;
        pa[kt * 4 + 0] = packbf2(acc[t0][0] * inv0, acc[t0][1] * inv0);
        pa[kt * 4 + 1] = packbf2(acc[t0][2] * inv1, acc[t0][3] * inv1);
        pa[kt * 4 + 2] = packbf2(acc[t1][0] * inv0, acc[t1][1] * inv0);
        pa[kt * 4 + 3] = packbf2(acc[t1][2] * inv1, acc[t1][3] * inv1);
    }

    // ---- ctx[16x64] per warp = P @ (VH + VL) ----
    float cacc[8][4];
#pragma unroll
    for (int j = 0; j < 8; j++)
#pragma unroll
        for (int e = 0; e < 4; e++) cacc[j][e] = 0.f;

#pragma unroll
    for (int term = 0; term < 2; term++) {
        const uint32_t vb = term ? uVL : uVH;
#pragma unroll
        for (int kt = 0; kt < 16; kt++) {
            uint32_t bf2[8][2];
#pragma unroll
            for (int np = 0; np < 4; np++) {
                int r = np * 16 + ((lane >> 4) << 3) + (lane & 7);
                int u = kt * 2 + ((lane >> 3) & 1);
                ldsm4(&bf2[np * 2][0], vb + (uint32_t)((r * 32 + (u ^ ((r & 7) << 2))) << 4));
            }
#pragma unroll
            for (int nt = 0; nt < 8; nt++)
                mma16816(cacc[nt], &pa[kt * 4], bf2[nt]);
        }
    }

    // ---- store ctx (bf16) ----
#pragma unroll
    for (int nt = 0; nt < 8; nt++)
#pragma unroll
        for (int hf = 0; hf < 2; hf++) {
            const int qrow = q0 + warp * 16 + (lane >> 2) + hf * 8;
            const int d = nt * 8 + ((lane & 3) << 1);
            __nv_bfloat162 o;
            o.x = __float2bfloat16_rn(cacc[nt][hf * 2 + 0]);
            o.y = __float2bfloat16_rn(cacc[nt][hf * 2 + 1]);
            *(__nv_bfloat162*)(ctxp + ((size_t)b * 2048 + qrow) * 512 + h * 64 + d) = o;
        }
}

// ======================= small kernels =======================
__global__ void split_kernel(const float* __restrict__ in, bf16* __restrict__ hi,
                             bf16* __restrict__ lo, int n)
{
    int i = blockIdx.x * blockDim.x + threadIdx.x;
    if (i < n) {
        float x = in[i];
        bf16 h = __float2bfloat16_rn(x);
        hi[i] = h;
        if (lo) lo[i] = __float2bfloat16_rn(x - __bfloat162float(h));
    }
}

__global__ void split_weights(const float* __restrict__ w0, const float* __restrict__ w1,
                              const float* __restrict__ w2, const float* __restrict__ w3,
                              bf16* __restrict__ base)
{
    int y = blockIdx.y;
    const float* src = (y == 0) ? w0 : (y == 1) ? w1 : (y == 2) ? w2 : w3;
    bf16* hi = base + (size_t)y * 2 * 262144;
    bf16* lo = hi + 262144;
    int i = blockIdx.x * blockDim.x + threadIdx.x;
    if (i < 262144) {
        float x = src[i];
        bf16 h = __float2bfloat16_rn(x);
        hi[i] = h;
        lo[i] = __float2bfloat16_rn(x - __bfloat162float(h));
    }
}

__global__ __launch_bounds__(512) void epilogue_ln(
    const float* __restrict__ qin, const float* __restrict__ ao,
    const float* __restrict__ lnw, const float* __restrict__ lnb,
    float* __restrict__ part)
{
    __shared__ float r1[16], r2[16], stats[2];
    int b = blockIdx.y, chunk = blockIdx.x;
    int col = threadIdx.x, wid = col >> 5, lane = col & 31;
    float w = lnw[col], bb = lnb[col];
    float acc = 0.f;
    size_t base = ((size_t)b * Ll + chunk * 64) * Dd + col;

    for (int r = 0; r < 64; r++) {
        size_t idx = base + (size_t)r * Dd;
        float x = qin[idx] + ao[idx];
        float s = x, s2 = x * x;
#pragma unroll
        for (int o = 16; o; o >>= 1) {
            s  += __shfl_xor_sync(0xffffffffu, s, o);
            s2 += __shfl_xor_sync(0xffffffffu, s2, o);
        }
        if (lane == 0) { r1[wid] = s; r2[wid] = s2; }
        __syncthreads();
        if (col < 32) {
            float a  = (col < 16) ? r1[col] : 0.f;
            float a2 = (col < 16) ? r2[col] : 0.f;
#pragma unroll
            for (int o = 8; o; o >>= 1) {
                a  += __shfl_xor_sync(0xffffffffu, a, o);
                a2 += __shfl_xor_sync(0xffffffffu, a2, o);
            }
            if (col == 0) { stats[0] = a; stats[1] = a2; }
        }
        __syncthreads();
        float mu  = stats[0] * (1.f / 512.f);
        float var = stats[1] * (1.f / 512.f) - mu * mu;
        float xn  = (x - mu) * rsqrtf(var + 1e-5f);
        acc += xn * w + bb;
    }
    part[((size_t)b * 32 + chunk) * Dd + col] = acc;
}

__global__ void final_reduce(const float* __restrict__ part, float* __restrict__ out)
{
    int b = blockIdx.x, col = threadIdx.x;
    float s = 0.f;
#pragma unroll
    for (int c = 0; c < 32; c++) s += part[((size_t)b * 32 + c) * Dd + col];
    out[b * Dd + col] = s * (1.f / 2048.f);
}

// ======================= driver =======================
extern "C" void kernel_launch(void* const* d_in, const int* in_sizes, int n_in,
                              void* d_out, int out_size)
{
    (void)in_sizes; (void)n_in; (void)out_size;
    const float* qin  = (const float*)d_in[0];
    const float* sent = (const float*)d_in[1];
    const int*   ns   = (const int*)  d_in[2];
    const float* Wq   = (const float*)d_in[3];
    const float* bq   = (const float*)d_in[4];
    const float* Wk   = (const float*)d_in[5];
    const float* bk   = (const float*)d_in[6];
    const float* Wv   = (const float*)d_in[7];
    const float* bvv  = (const float*)d_in[8];
    const float* Wo   = (const float*)d_in[9];
    const float* bo   = (const float*)d_in[10];
    const float* lnw  = (const float*)d_in[11];
    const float* lnb  = (const float*)d_in[12];
    float* out = (float*)d_out;

    void* p_;
    cudaGetSymbolAddress(&p_, g_qinH_);   bf16* qinH = (bf16*)p_;
    cudaGetSymbolAddress(&p_, g_sentHL_); bf16* sentH = (bf16*)p_; bf16* sentL = sentH + 1048576;
    cudaGetSymbolAddress(&p_, g_W_);      bf16* W = (bf16*)p_;
    bf16 *WqH = W,            *WqL = W + 262144,   *WkH = W + 2*262144, *WkL = W + 3*262144;
    bf16 *WvH = W + 4*262144, *WvL = W + 5*262144, *WoH = W + 6*262144, *WoL = W + 7*262144;
    cudaGetSymbolAddress(&p_, g_qH_);    bf16* qH  = (bf16*)p_;
    cudaGetSymbolAddress(&p_, g_kHL_);   bf16* kH  = (bf16*)p_;  bf16* kL  = kH + 1048576;
    cudaGetSymbolAddress(&p_, g_vtHL_);  bf16* vtH = (bf16*)p_;  bf16* vtL = vtH + 1048576;
    cudaGetSymbolAddress(&p_, g_ctxH_);  bf16* ctxH = (bf16*)p_;
    cudaGetSymbolAddress(&p_, g_ao_);    float* ao = (float*)p_;
    cudaGetSymbolAddress(&p_, g_part_);  float* part = (float*)p_;

    constexpr int SM_QO = 3 * (128 * 64 + 128 * 64);    // 49152
    constexpr int SM_KV = 3 * (64 * 64 + 128 * 64);     // 36864
    cudaFuncSetAttribute((const void*)gemm_mma<128,128,32,64>,
                         cudaFuncAttributeMaxDynamicSharedMemorySize, SM_QO);
    cudaFuncSetAttribute((const void*)gemm_mma<64,128,32,32>,
                         cudaFuncAttributeMaxDynamicSharedMemorySize, SM_KV);
    cudaFuncSetAttribute((const void*)attn_fused,
                         cudaFuncAttributeMaxDynamicSharedMemorySize, 147456);

    // splits
    split_kernel<<<32768, 256>>>(qin,  qinH, nullptr, 8388608);
    split_kernel<<<4096,  256>>>(sent, sentH, sentL, 1048576);
    split_weights<<<dim3(1024, 4), 256>>>(Wq, Wk, Wv, Wo, W);

    // q = QinH @ (WqH + WqL)^T + bq  (2 terms) -> qH (bf16)
    gemm_mma<128,128,32,64><<<dim3(4, 128, 1), 256, SM_QO>>>(
        qinH, qinH, nullptr, WqH, WqL, nullptr, 2, bq,
        nullptr, qH, nullptr, 512, 512, 512, 512,
        1, 0, 0, 0, 0, 0, 0, 1.f, 0);

    // k = sent @ Wk^T + bk  (3 terms) -> kH,kL
    gemm_mma<64,128,32,32><<<dim3(4, 32, 1), 256, SM_KV>>>(
        sentH, sentH, sentL, WkH, WkL, WkH, 3, bk,
        nullptr, kH, kL, 512, 512, 512, 512,
        1, 0, 0, 0, 0, 0, 0, 1.f, 0);

    // v = sent @ Wv^T + bv  (3 terms) -> vt[bh][d][s] hi/lo
    gemm_mma<64,128,32,32><<<dim3(4, 32, 1), 256, SM_KV>>>(
        sentH, sentH, sentL, WvH, WvL, WvH, 3, bvv,
        nullptr, vtH, vtL, 512, 512, 512, 512,
        1, 0, 0, 0, 0, 0, 0, 1.f, 1);

    // fused attention -> ctxH (bf16)
    attn_fused<<<dim3(16, 64), 256, 147456>>>(qH, kH, kL, vtH, vtL, ctxH, ns);

    // attn_out = ctx @ (WoH + WoL)^T + bo  (2 terms) -> fp32
    gemm_mma<128,128,32,64><<<dim3(4, 128, 1), 256, SM_QO>>>(
        ctxH, ctxH, nullptr, WoH, WoL, nullptr, 2, bo,
        ao, nullptr, nullptr, 512, 512, 512, 512,
        1, 0, 0, 0, 0, 0, 0, 1.f, 0);

    epilogue_ln<<<dim3(32, 8), 512>>>(qin, ao, lnw, lnb, part);
    final_reduce<<<8, 512>>>(part, out);
}

// round 10
// speedup vs baseline: 2.6172x; 1.2222x over previous
#include <cuda_runtime.h>
#include <cuda_bf16.h>
#include <cstdint>
#include <cstddef>

typedef __nv_bfloat16 bf16;

// ======================= portable PTX helpers (sm_80+) =======================
__device__ __forceinline__ uint32_t smem_u32(const void* p) {
    uint32_t a;
    asm("{ .reg .u64 t; cvta.to.shared.u64 t, %1; cvt.u32.u64 %0, t; }" : "=r"(a) : "l"(p));
    return a;
}
__device__ __forceinline__ void cp16(uint32_t dst, const void* src) {
    asm volatile("cp.async.cg.shared.global [%0], [%1], 16;" :: "r"(dst), "l"(src));
}
__device__ __forceinline__ void ldsm4(uint32_t* r, uint32_t a) {
    asm volatile("ldmatrix.sync.aligned.m8n8.x4.shared.b16 {%0,%1,%2,%3}, [%4];"
        : "=r"(r[0]), "=r"(r[1]), "=r"(r[2]), "=r"(r[3]) : "r"(a));
}
__device__ __forceinline__ void mma16816(float* c, const uint32_t* a, const uint32_t* b) {
    asm volatile(
        "mma.sync.aligned.m16n8k16.row.col.f32.bf16.bf16.f32 "
        "{%0,%1,%2,%3}, {%4,%5,%6,%7}, {%8,%9}, {%0,%1,%2,%3};"
        : "+f"(c[0]), "+f"(c[1]), "+f"(c[2]), "+f"(c[3])
        : "r"(a[0]), "r"(a[1]), "r"(a[2]), "r"(a[3]), "r"(b[0]), "r"(b[1]));
}
__device__ __forceinline__ uint32_t packbf2(float lo, float hi) {
    __nv_bfloat162 p;
    p.x = __float2bfloat16_rn(lo);
    p.y = __float2bfloat16_rn(hi);
    return *(uint32_t*)&p;
}

// ======================= constants & scratch =======================
static const int Dd = 512, Ll = 2048;

__device__ uint4 g_qinH_[1048576];        // bf16(Qin)             16 MB
__device__ uint4 g_sentHL_[2 * 131072];   // sentH, sentL
__device__ uint4 g_W_[8 * 32768];         // WqH WqL WkH WkL WvH WvL WoH WoL
__device__ uint4 g_qH_[1048576];          // bf16(q)               16 MB
__device__ uint4 g_kH_[131072];           // kH
__device__ uint4 g_vtHL_[2 * 131072];     // vtH, vtL [bh][64][256]
__device__ uint4 g_ctxH_[1048576];        // bf16(ctx)             16 MB
__device__ uint4 g_ao_[2097152];          // fp32 attn_out         32 MB
__device__ float g_part_[8 * 32 * 512];

// ---------------------------------------------------------------------------
// Generic multi-term bf16 GEMM, BK=64 chunks, 3-stage cp.async, 2 CTAs/SM.
//   acc[BM x BN] = sum_t sum_k A_t[m][k]*B_t[n][k]; out = alpha*acc + bias
// Warps: (BM/WM) x (BN/WN) == 8.   vmode=1: V-proj transpose scatter.
// SMEM rows are 64 bf16 = 128B, XOR-8 swizzled (u ^ (r&7)).
// ---------------------------------------------------------------------------
template<int BM, int BN, int WM, int WN>
__global__ __launch_bounds__(256, 2)
void gemm_mma(const bf16* A0, const bf16* A1, const bf16* A2,
              const bf16* B0, const bf16* B1, const bf16* B2,
              int nterms, const float* __restrict__ bias,
              float* __restrict__ Cf, bf16* __restrict__ Chi, bf16* __restrict__ Clo,
              int Ktot, int lda, int ldb, int ldc,
              int HH, long long sAb, long long sAh, long long sBb, long long sBh,
              long long sCb, long long sCh, float alpha, int vmode)
{
    constexpr int BK = 64;
    constexpr int WARPS_N = BN / WN;
    constexpr int MT = WM / 16, NT = WN / 8;
    constexpr int ASZ = BM * BK * 2, BSZ = BN * BK * 2;
    static_assert((BM / WM) * (BN / WN) == 8, "8 warps");

    extern __shared__ char dynsm[];
    const uint32_t sA0 = smem_u32(dynsm);
    const uint32_t sB0 = sA0 + 3 * ASZ;

    const int tid = threadIdx.x, warp = tid >> 5, lane = tid & 31;
    const int wm = warp / WARPS_N, wn = warp % WARPS_N;

    const bf16* Al[3] = {A0, A1, A2};
    const bf16* Bl[3] = {B0, B1, B2};

    const int z = blockIdx.z;
    const int bz = z / HH, hz = z - bz * HH;
    const long long aoff = (long long)bz * sAb + (long long)hz * sAh;
    const long long boff = (long long)bz * sBb + (long long)hz * sBh;
    const long long coff = (long long)bz * sCb + (long long)hz * sCh;

    const int m0 = blockIdx.y * BM;
    const int n0 = blockIdx.x * BN;

    const int kch = Ktot >> 6;
    const int total = nterms * kch;

    const int fr = tid >> 3, fu = tid & 7;   // fill: 32 rows per 256-thread pass

    float acc[MT][NT][4];
#pragma unroll
    for (int i = 0; i < MT; i++)
#pragma unroll
        for (int j = 0; j < NT; j++)
#pragma unroll
            for (int e = 0; e < 4; e++) acc[i][j][e] = 0.f;

    auto prefetch = [&](int chunk, int buf) {
        const int term = chunk / kch;
        const int k0 = (chunk - term * kch) << 6;
        const bf16* Ag = Al[term] + aoff + k0;
        const uint32_t sA = sA0 + buf * ASZ;
#pragma unroll
        for (int p = 0; p < BM / 32; p++) {
            const int r = fr + p * 32;
            cp16(sA + (uint32_t)((r * 8 + (fu ^ (r & 7))) << 4),
                 Ag + (size_t)(m0 + r) * lda + fu * 8);
        }
        const bf16* Bg = Bl[term] + boff + k0;
        const uint32_t sB = sB0 + buf * BSZ;
#pragma unroll
        for (int p = 0; p < BN / 32; p++) {
            const int r = fr + p * 32;
            cp16(sB + (uint32_t)((r * 8 + (fu ^ (r & 7))) << 4),
                 Bg + (size_t)(n0 + r) * ldb + fu * 8);
        }
        asm volatile("cp.async.commit_group;");
    };

    prefetch(0, 0);
    prefetch(1, 1);
    for (int it = 0; it < total; it++) {
        if (it + 1 < total) asm volatile("cp.async.wait_group 1;");
        else                asm volatile("cp.async.wait_group 0;");
        __syncthreads();
        if (it + 2 < total) prefetch(it + 2, (it + 2) % 3);

        const int buf = it % 3;
        const uint32_t sA = sA0 + buf * ASZ;
        const uint32_t sB = sB0 + buf * BSZ;
#pragma unroll
        for (int kk = 0; kk < 4; kk++) {
            uint32_t af[MT][4];
#pragma unroll
            for (int mt = 0; mt < MT; mt++) {
                const int r = wm * WM + mt * 16 + (lane & 15);
                const int u = (kk << 1) + (lane >> 4);
                ldsm4(af[mt], sA + (uint32_t)((r * 8 + (u ^ (r & 7))) << 4));
            }
            uint32_t bfr[NT][2];
#pragma unroll
            for (int np = 0; np < NT / 2; np++) {
                const int r = wn * WN + np * 16 + ((lane >> 4) << 3) + (lane & 7);
                const int u = (kk << 1) + ((lane >> 3) & 1);
                ldsm4(&bfr[np * 2][0], sB + (uint32_t)((r * 8 + (u ^ (r & 7))) << 4));
            }
#pragma unroll
            for (int mt = 0; mt < MT; mt++)
#pragma unroll
                for (int nt = 0; nt < NT; nt++)
                    mma16816(acc[mt][nt], af[mt], bfr[nt]);
        }
    }

    // ---------------- epilogue ----------------
#pragma unroll
    for (int mt = 0; mt < MT; mt++)
#pragma unroll
        for (int nt = 0; nt < NT; nt++) {
            const int gr0 = m0 + wm * WM + mt * 16 + (lane >> 2);
            const int gc = n0 + wn * WN + nt * 8 + ((lane & 3) << 1);
            const float b0v = bias ? bias[gc] : 0.f;
            const float b1v = bias ? bias[gc + 1] : 0.f;
#pragma unroll
            for (int h2 = 0; h2 < 2; h2++) {
                const int gr = gr0 + h2 * 8;
                const float x0 = alpha * acc[mt][nt][h2 * 2 + 0] + b0v;
                const float x1 = alpha * acc[mt][nt][h2 * 2 + 1] + b1v;
                if (!vmode) {
                    const long long idx = coff + (long long)gr * ldc + gc;
                    if (Cf) { Cf[idx] = x0; Cf[idx + 1] = x1; }
                    if (Chi) {
                        bf16 h0 = __float2bfloat16_rn(x0), h1 = __float2bfloat16_rn(x1);
                        Chi[idx] = h0; Chi[idx + 1] = h1;
                        if (Clo) {
                            Clo[idx] = __float2bfloat16_rn(x0 - __bfloat162float(h0));
                            Clo[idx + 1] = __float2bfloat16_rn(x1 - __bfloat162float(h1));
                        }
                    }
                } else {
                    const int bb = gr >> 8, jj = gr & 255;
#pragma unroll
                    for (int e = 0; e < 2; e++) {
                        const float x = e ? x1 : x0;
                        const int n = gc + e, h = n >> 6, d = n & 63;
                        const size_t off = ((size_t)(bb * 8 + h) * 64 + d) * 256 + jj;
                        bf16 hh = __float2bfloat16_rn(x);
                        Chi[off] = hh;
                        Clo[off] = __float2bfloat16_rn(x - __bfloat162float(hh));
                    }
                }
            }
        }
}

// ---------------------------------------------------------------------------
// Fused attention, FA2-style register path. One CTA = one (b,h) x 128 Q rows.
// S = 0.125 * qH @ kH^T (single term); ctx = P @ (VH + VL).
// SMEM: Q 16K | KH 32K | VH 32K | VL 32K = 112 KB. grid (16, 64).
// ---------------------------------------------------------------------------
__global__ __launch_bounds__(256, 1)
void attn_fused(const bf16* __restrict__ qHp, const bf16* __restrict__ kHp,
                const bf16* __restrict__ vtHp, const bf16* __restrict__ vtLp,
                bf16* __restrict__ ctxp, const int* __restrict__ nsp)
{
    extern __shared__ char dsm[];
    const uint32_t uQ  = smem_u32(dsm);
    const uint32_t uKH = uQ + 16384;
    const uint32_t uVH = uQ + 49152;
    const uint32_t uVL = uQ + 81920;

    const int tid = threadIdx.x, warp = tid >> 5, lane = tid & 31;
    const int bh = blockIdx.y, b = bh >> 3, h = bh & 7;
    const int ns = nsp[b];
    const int q0 = blockIdx.x * 128;

    // ---- loads: Q(128x64), K(256x64), V^T(64x256 hi/lo) ----
    {
        const bf16* gQ = qHp + ((size_t)b * 2048 + q0) * 512 + h * 64;
#pragma unroll
        for (int t = 0; t < 4; t++) {
            int id = tid + (t << 8);
            int r = id >> 3, u = id & 7;
            cp16(uQ + (uint32_t)((r * 8 + (u ^ (r & 7))) << 4), gQ + (size_t)r * 512 + u * 8);
        }
        const bf16* gKH = kHp + ((size_t)b * 256) * 512 + h * 64;
#pragma unroll
        for (int t = 0; t < 8; t++) {
            int id = tid + (t << 8);
            int r = id >> 3, u = id & 7;
            cp16(uKH + (uint32_t)((r * 8 + (u ^ (r & 7))) << 4), gKH + (size_t)r * 512 + u * 8);
        }
        const bf16* gVH = vtHp + (size_t)bh * 16384;
        const bf16* gVL = vtLp + (size_t)bh * 16384;
#pragma unroll
        for (int t = 0; t < 8; t++) {
            int id = tid + (t << 8);
            int r = id >> 5, u = id & 31;
            uint32_t off = (uint32_t)((r * 32 + (u ^ ((r & 7) << 2))) << 4);
            cp16(uVH + off, gVH + (size_t)r * 256 + u * 8);
            cp16(uVL + off, gVL + (size_t)r * 256 + u * 8);
        }
        asm volatile("cp.async.commit_group;");
        asm volatile("cp.async.wait_group 0;");
    }
    __syncthreads();

    // ---- S[16x256] per warp = q @ kH^T ----
    float acc[32][4];
#pragma unroll
    for (int j = 0; j < 32; j++)
#pragma unroll
        for (int e = 0; e < 4; e++) acc[j][e] = 0.f;

#pragma unroll
    for (int kk = 0; kk < 4; kk++) {
        uint32_t af[4];
        {
            int r = warp * 16 + (lane & 15);
            int u = kk * 2 + (lane >> 4);
            ldsm4(af, uQ + (uint32_t)((r * 8 + (u ^ (r & 7))) << 4));
        }
#pragma unroll
        for (int nc = 0; nc < 4; nc++) {
            uint32_t bfr[8][2];
#pragma unroll
            for (int np = 0; np < 4; np++) {
                int r = nc * 64 + np * 16 + ((lane >> 4) << 3) + (lane & 7);
                int u = kk * 2 + ((lane >> 3) & 1);
                ldsm4(&bfr[np * 2][0], uKH + (uint32_t)((r * 8 + (u ^ (r & 7))) << 4));
            }
#pragma unroll
            for (int nt = 0; nt < 8; nt++)
                mma16816(acc[nc * 8 + nt], af, bfr[nt]);
        }
    }

    // ---- mask + warp-local softmax (rows owned by quads) ----
    float mx[2] = {-3.0e38f, -3.0e38f};
#pragma unroll
    for (int nt = 0; nt < 32; nt++) {
        const int cb = nt * 8 + ((lane & 3) << 1);
#pragma unroll
        for (int hf = 0; hf < 2; hf++)
#pragma unroll
            for (int e = 0; e < 2; e++) {
                float x = (cb + e < ns) ? 0.125f * acc[nt][hf * 2 + e] : -3.0e38f;
                acc[nt][hf * 2 + e] = x;
                mx[hf] = fmaxf(mx[hf], x);
            }
    }
#pragma unroll
    for (int hf = 0; hf < 2; hf++) {
        mx[hf] = fmaxf(mx[hf], __shfl_xor_sync(0xffffffffu, mx[hf], 1));
        mx[hf] = fmaxf(mx[hf], __shfl_xor_sync(0xffffffffu, mx[hf], 2));
    }
    float sm[2] = {0.f, 0.f};
#pragma unroll
    for (int nt = 0; nt < 32; nt++)
#pragma unroll
        for (int hf = 0; hf < 2; hf++)
#pragma unroll
            for (int e = 0; e < 2; e++) {
                float p = __expf(acc[nt][hf * 2 + e] - mx[hf]);
                acc[nt][hf * 2 + e] = p;
                sm[hf] += p;
            }
#pragma unroll
    for (int hf = 0; hf < 2; hf++) {
        sm[hf] += __shfl_xor_sync(0xffffffffu, sm[hf], 1);
        sm[hf] += __shfl_xor_sync(0xffffffffu, sm[hf], 2);
    }
    const float inv0 = 1.f / sm[0], inv1 = 1.f / sm[1];

    // ---- pack P (C-frag -> A-frag) ----
    uint32_t pa[64];
#pragma unroll
    for (int kt = 0; kt < 16; kt++) {
        const int t0 = 2 * kt, t1 = 2 * kt + 1;
        pa[kt * 4 + 0] = packbf2(acc[t0][0] * inv0, acc[t0][1] * inv0);
        pa[kt * 4 + 1] = packbf2(acc[t0][2] * inv1, acc[t0][3] * inv1);
        pa[kt * 4 + 2] = packbf2(acc[t1][0] * inv0, acc[t1][1] * inv0);
        pa[kt * 4 + 3] = packbf2(acc[t1][2] * inv1, acc[t1][3] * inv1);
    }

    // ---- ctx[16x64] per warp = P @ (VH + VL) ----
    float cacc[8][4];
#pragma unroll
    for (int j = 0; j < 8; j++)
#pragma unroll
        for (int e = 0; e < 4; e++) cacc[j][e] = 0.f;

#pragma unroll
    for (int term = 0; term < 2; term++) {
        const uint32_t vb = term ? uVL : uVH;
#pragma unroll
        for (int kt = 0; kt < 16; kt++) {
            uint32_t bf2[8][2];
#pragma unroll
            for (int np = 0; np < 4; np++) {
                int r = np * 16 + ((lane >> 4) << 3) + (lane & 7);
                int u = kt * 2 + ((lane >> 3) & 1);
                ldsm4(&bf2[np * 2][0], vb + (uint32_t)((r * 32 + (u ^ ((r & 7) << 2))) << 4));
            }
#pragma unroll
            for (int nt = 0; nt < 8; nt++)
                mma16816(cacc[nt], &pa[kt * 4], bf2[nt]);
        }
    }

    // ---- store ctx (bf16) ----
#pragma unroll
    for (int nt = 0; nt < 8; nt++)
#pragma unroll
        for (int hf = 0; hf < 2; hf++) {
            const int qrow = q0 + warp * 16 + (lane >> 2) + hf * 8;
            const int d = nt * 8 + ((lane & 3) << 1);
            __nv_bfloat162 o;
            o.x = __float2bfloat16_rn(cacc[nt][hf * 2 + 0]);
            o.y = __float2bfloat16_rn(cacc[nt][hf * 2 + 1]);
            *(__nv_bfloat162*)(ctxp + ((size_t)b * 2048 + qrow) * 512 + h * 64 + d) = o;
        }
}

// ======================= small kernels =======================
__global__ void split_kernel(const float* __restrict__ in, bf16* __restrict__ hi,
                             bf16* __restrict__ lo, int n)
{
    int i = blockIdx.x * blockDim.x + threadIdx.x;
    if (i < n) {
        float x = in[i];
        bf16 h = __float2bfloat16_rn(x);
        hi[i] = h;
        if (lo) lo[i] = __float2bfloat16_rn(x - __bfloat162float(h));
    }
}

__global__ void split_weights(const float* __restrict__ w0, const float* __restrict__ w1,
                              const float* __restrict__ w2, const float* __restrict__ w3,
                              bf16* __restrict__ base)
{
    int y = blockIdx.y;
    const float* src = (y == 0) ? w0 : (y == 1) ? w1 : (y == 2) ? w2 : w3;
    bf16* hi = base + (size_t)y * 2 * 262144;
    bf16* lo = hi + 262144;
    int i = blockIdx.x * blockDim.x + threadIdx.x;
    if (i < 262144) {
        float x = src[i];
        bf16 h = __float2bfloat16_rn(x);
        hi[i] = h;
        lo[i] = __float2bfloat16_rn(x - __bfloat162float(h));
    }
}

__global__ __launch_bounds__(512) void epilogue_ln(
    const float* __restrict__ qin, const float* __restrict__ ao,
    const float* __restrict__ lnw, const float* __restrict__ lnb,
    float* __restrict__ part)
{
    __shared__ float r1[16], r2[16], stats[2];
    int b = blockIdx.y, chunk = blockIdx.x;
    int col = threadIdx.x, wid = col >> 5, lane = col & 31;
    float w = lnw[col], bb = lnb[col];
    float acc = 0.f;
    size_t base = ((size_t)b * Ll + chunk * 64) * Dd + col;

    for (int r = 0; r < 64; r++) {
        size_t idx = base + (size_t)r * Dd;
        float x = qin[idx] + ao[idx];
        float s = x, s2 = x * x;
#pragma unroll
        for (int o = 16; o; o >>= 1) {
            s  += __shfl_xor_sync(0xffffffffu, s, o);
            s2 += __shfl_xor_sync(0xffffffffu, s2, o);
        }
        if (lane == 0) { r1[wid] = s; r2[wid] = s2; }
        __syncthreads();
        if (col < 32) {
            float a  = (col < 16) ? r1[col] : 0.f;
            float a2 = (col < 16) ? r2[col] : 0.f;
#pragma unroll
            for (int o = 8; o; o >>= 1) {
                a  += __shfl_xor_sync(0xffffffffu, a, o);
                a2 += __shfl_xor_sync(0xffffffffu, a2, o);
            }
            if (col == 0) { stats[0] = a; stats[1] = a2; }
        }
        __syncthreads();
        float mu  = stats[0] * (1.f / 512.f);
        float var = stats[1] * (1.f / 512.f) - mu * mu;
        float xn  = (x - mu) * rsqrtf(var + 1e-5f);
        acc += xn * w + bb;
    }
    part[((size_t)b * 32 + chunk) * Dd + col] = acc;
}

__global__ void final_reduce(const float* __restrict__ part, float* __restrict__ out)
{
    int b = blockIdx.x, col = threadIdx.x;
    float s = 0.f;
#pragma unroll
    for (int c = 0; c < 32; c++) s += part[((size_t)b * 32 + c) * Dd + col];
    out[b * Dd + col] = s * (1.f / 2048.f);
}

// ======================= driver =======================
extern "C" void kernel_launch(void* const* d_in, const int* in_sizes, int n_in,
                              void* d_out, int out_size)
{
    (void)in_sizes; (void)n_in; (void)out_size;
    const float* qin  = (const float*)d_in[0];
    const float* sent = (const float*)d_in[1];
    const int*   ns   = (const int*)  d_in[2];
    const float* Wq   = (const float*)d_in[3];
    const float* bq   = (const float*)d_in[4];
    const float* Wk   = (const float*)d_in[5];
    const float* bk   = (const float*)d_in[6];
    const float* Wv   = (const float*)d_in[7];
    const float* bvv  = (const float*)d_in[8];
    const float* Wo   = (const float*)d_in[9];
    const float* bo   = (const float*)d_in[10];
    const float* lnw  = (const float*)d_in[11];
    const float* lnb  = (const float*)d_in[12];
    float* out = (float*)d_out;

    void* p_;
    cudaGetSymbolAddress(&p_, g_qinH_);   bf16* qinH = (bf16*)p_;
    cudaGetSymbolAddress(&p_, g_sentHL_); bf16* sentH = (bf16*)p_; bf16* sentL = sentH + 1048576;
    cudaGetSymbolAddress(&p_, g_W_);      bf16* W = (bf16*)p_;
    bf16 *WqH = W,            *WkH = W + 2*262144;
    bf16 *WvH = W + 4*262144, *WvL = W + 5*262144, *WoH = W + 6*262144, *WoL = W + 7*262144;
    cudaGetSymbolAddress(&p_, g_qH_);    bf16* qH  = (bf16*)p_;
    cudaGetSymbolAddress(&p_, g_kH_);    bf16* kH  = (bf16*)p_;
    cudaGetSymbolAddress(&p_, g_vtHL_);  bf16* vtH = (bf16*)p_;  bf16* vtL = vtH + 1048576;
    cudaGetSymbolAddress(&p_, g_ctxH_);  bf16* ctxH = (bf16*)p_;
    cudaGetSymbolAddress(&p_, g_ao_);    float* ao = (float*)p_;
    cudaGetSymbolAddress(&p_, g_part_);  float* part = (float*)p_;

    constexpr int SM_QO = 3 * (128 * 128 + 128 * 128);  // 98304 (BK=64, bf16)
    constexpr int SM_KV = 3 * (64 * 128 + 128 * 128);   // 73728
    cudaFuncSetAttribute((const void*)gemm_mma<128,128,32,64>,
                         cudaFuncAttributeMaxDynamicSharedMemorySize, SM_QO);
    cudaFuncSetAttribute((const void*)gemm_mma<64,128,32,32>,
                         cudaFuncAttributeMaxDynamicSharedMemorySize, SM_KV);
    cudaFuncSetAttribute((const void*)attn_fused,
                         cudaFuncAttributeMaxDynamicSharedMemorySize, 114688);

    // splits
    split_kernel<<<32768, 256>>>(qin,  qinH, nullptr, 8388608);
    split_kernel<<<4096,  256>>>(sent, sentH, sentL, 1048576);
    split_weights<<<dim3(1024, 4), 256>>>(Wq, Wk, Wv, Wo, W);

    // q = QinH @ WqH^T + bq  (1 term) -> qH (bf16)
    gemm_mma<128,128,32,64><<<dim3(4, 128, 1), 256, SM_QO>>>(
        qinH, nullptr, nullptr, WqH, nullptr, nullptr, 1, bq,
        nullptr, qH, nullptr, 512, 512, 512, 512,
        1, 0, 0, 0, 0, 0, 0, 1.f, 0);

    // k = sentH @ WkH^T + bk  (1 term) -> kH (bf16)
    gemm_mma<64,128,32,32><<<dim3(4, 32, 1), 256, SM_KV>>>(
        sentH, nullptr, nullptr, WkH, nullptr, nullptr, 1, bk,
        nullptr, kH, nullptr, 512, 512, 512, 512,
        1, 0, 0, 0, 0, 0, 0, 1.f, 0);

    // v = sent @ Wv^T + bv  (3 terms) -> vt[bh][d][s] hi/lo
    gemm_mma<64,128,32,32><<<dim3(4, 32, 1), 256, SM_KV>>>(
        sentH, sentH, sentL, WvH, WvL, WvH, 3, bvv,
        nullptr, vtH, vtL, 512, 512, 512, 512,
        1, 0, 0, 0, 0, 0, 0, 1.f, 1);

    // fused attention (1-term scores) -> ctxH (bf16)
    attn_fused<<<dim3(16, 64), 256, 114688>>>(qH, kH, vtH, vtL, ctxH, ns);

    // attn_out = ctx @ (WoH + WoL)^T + bo  (2 terms) -> fp32
    gemm_mma<128,128,32,64><<<dim3(4, 128, 1), 256, SM_QO>>>(
        ctxH, ctxH, nullptr, WoH, WoL, nullptr, 2, bo,
        ao, nullptr, nullptr, 512, 512, 512, 512,
        1, 0, 0, 0, 0, 0, 0, 1.f, 0);

    epilogue_ln<<<dim3(32, 8), 512>>>(qin, ao, lnw, lnb, part);
    final_reduce<<<8, 512>>>(part, out);
}

// round 11
// speedup vs baseline: 2.7236x; 1.0407x over previous
#include <cuda_runtime.h>
#include <cuda_bf16.h>
#include <cstdint>
#include <cstddef>

typedef __nv_bfloat16 bf16;

// ======================= portable PTX helpers (sm_80+) =======================
__device__ __forceinline__ uint32_t smem_u32(const void* p) {
    uint32_t a;
    asm("{ .reg .u64 t; cvta.to.shared.u64 t, %1; cvt.u32.u64 %0, t; }" : "=r"(a) : "l"(p));
    return a;
}
__device__ __forceinline__ void cp16(uint32_t dst, const void* src) {
    asm volatile("cp.async.cg.shared.global [%0], [%1], 16;" :: "r"(dst), "l"(src));
}
__device__ __forceinline__ void ldsm4(uint32_t* r, uint32_t a) {
    asm volatile("ldmatrix.sync.aligned.m8n8.x4.shared.b16 {%0,%1,%2,%3}, [%4];"
        : "=r"(r[0]), "=r"(r[1]), "=r"(r[2]), "=r"(r[3]) : "r"(a));
}
__device__ __forceinline__ void mma16816(float* c, const uint32_t* a, const uint32_t* b) {
    asm volatile(
        "mma.sync.aligned.m16n8k16.row.col.f32.bf16.bf16.f32 "
        "{%0,%1,%2,%3}, {%4,%5,%6,%7}, {%8,%9}, {%0,%1,%2,%3};"
        : "+f"(c[0]), "+f"(c[1]), "+f"(c[2]), "+f"(c[3])
        : "r"(a[0]), "r"(a[1]), "r"(a[2]), "r"(a[3]), "r"(b[0]), "r"(b[1]));
}
__device__ __forceinline__ uint32_t packbf2(float lo, float hi) {
    __nv_bfloat162 p;
    p.x = __float2bfloat16_rn(lo);
    p.y = __float2bfloat16_rn(hi);
    return *(uint32_t*)&p;
}

// ======================= constants & scratch =======================
static const int Dd = 512, Ll = 2048;

__device__ uint4 g_qinH_[1048576];        // bf16(Qin)             16 MB
__device__ uint4 g_sentHL_[2 * 131072];   // sentH, sentL
__device__ uint4 g_W_[8 * 32768];         // WqH WqL WkH WkL WvH WvL WoH WoL
__device__ uint4 g_qH_[1048576];          // bf16(q)               16 MB
__device__ uint4 g_kH_[131072];           // kH
__device__ uint4 g_vtHL_[2 * 131072];     // vtH, vtL [bh][64][256]
__device__ uint4 g_ctxH_[1048576];        // bf16(ctx)             16 MB
__device__ uint4 g_ao_[2097152];          // bf16 attn_out (16 MB used)
__device__ float g_part_[8 * 32 * 512];

// ---------------------------------------------------------------------------
// Generic multi-term bf16 GEMM, BK=64 chunks, 3-stage cp.async, 2 CTAs/SM.
//   acc[BM x BN] = sum_t sum_k A_t[m][k]*B_t[n][k]; out = alpha*acc + bias
// Warps: (BM/WM) x (BN/WN) == 8.   vmode=1: V-proj transpose scatter.
// SMEM rows are 64 bf16 = 128B, XOR-8 swizzled (u ^ (r&7)).
// ---------------------------------------------------------------------------
template<int BM, int BN, int WM, int WN>
__global__ __launch_bounds__(256, 2)
void gemm_mma(const bf16* A0, const bf16* A1, const bf16* A2,
              const bf16* B0, const bf16* B1, const bf16* B2,
              int nterms, const float* __restrict__ bias,
              float* __restrict__ Cf, bf16* __restrict__ Chi, bf16* __restrict__ Clo,
              int Ktot, int lda, int ldb, int ldc,
              int HH, long long sAb, long long sAh, long long sBb, long long sBh,
              long long sCb, long long sCh, float alpha, int vmode)
{
    constexpr int BK = 64;
    constexpr int WARPS_N = BN / WN;
    constexpr int MT = WM / 16, NT = WN / 8;
    constexpr int ASZ = BM * BK * 2, BSZ = BN * BK * 2;
    static_assert((BM / WM) * (BN / WN) == 8, "8 warps");

    extern __shared__ char dynsm[];
    const uint32_t sA0 = smem_u32(dynsm);
    const uint32_t sB0 = sA0 + 3 * ASZ;

    const int tid = threadIdx.x, warp = tid >> 5, lane = tid & 31;
    const int wm = warp / WARPS_N, wn = warp % WARPS_N;

    const bf16* Al[3] = {A0, A1, A2};
    const bf16* Bl[3] = {B0, B1, B2};

    const int z = blockIdx.z;
    const int bz = z / HH, hz = z - bz * HH;
    const long long aoff = (long long)bz * sAb + (long long)hz * sAh;
    const long long boff = (long long)bz * sBb + (long long)hz * sBh;
    const long long coff = (long long)bz * sCb + (long long)hz * sCh;

    const int m0 = blockIdx.y * BM;
    const int n0 = blockIdx.x * BN;

    const int kch = Ktot >> 6;
    const int total = nterms * kch;

    const int fr = tid >> 3, fu = tid & 7;

    float acc[MT][NT][4];
#pragma unroll
    for (int i = 0; i < MT; i++)
#pragma unroll
        for (int j = 0; j < NT; j++)
#pragma unroll
            for (int e = 0; e < 4; e++) acc[i][j][e] = 0.f;

    auto prefetch = [&](int chunk, int buf) {
        const int term = chunk / kch;
        const int k0 = (chunk - term * kch) << 6;
        const bf16* Ag = Al[term] + aoff + k0;
        const uint32_t sA = sA0 + buf * ASZ;
#pragma unroll
        for (int p = 0; p < BM / 32; p++) {
            const int r = fr + p * 32;
            cp16(sA + (uint32_t)((r * 8 + (fu ^ (r & 7))) << 4),
                 Ag + (size_t)(m0 + r) * lda + fu * 8);
        }
        const bf16* Bg = Bl[term] + boff + k0;
        const uint32_t sB = sB0 + buf * BSZ;
#pragma unroll
        for (int p = 0; p < BN / 32; p++) {
            const int r = fr + p * 32;
            cp16(sB + (uint32_t)((r * 8 + (fu ^ (r & 7))) << 4),
                 Bg + (size_t)(n0 + r) * ldb + fu * 8);
        }
        asm volatile("cp.async.commit_group;");
    };

    prefetch(0, 0);
    prefetch(1, 1);
    for (int it = 0; it < total; it++) {
        if (it + 1 < total) asm volatile("cp.async.wait_group 1;");
        else                asm volatile("cp.async.wait_group 0;");
        __syncthreads();
        if (it + 2 < total) prefetch(it + 2, (it + 2) % 3);

        const int buf = it % 3;
        const uint32_t sA = sA0 + buf * ASZ;
        const uint32_t sB = sB0 + buf * BSZ;
#pragma unroll
        for (int kk = 0; kk < 4; kk++) {
            uint32_t af[MT][4];
#pragma unroll
            for (int mt = 0; mt < MT; mt++) {
                const int r = wm * WM + mt * 16 + (lane & 15);
                const int u = (kk << 1) + (lane >> 4);
                ldsm4(af[mt], sA + (uint32_t)((r * 8 + (u ^ (r & 7))) << 4));
            }
            uint32_t bfr[NT][2];
#pragma unroll
            for (int np = 0; np < NT / 2; np++) {
                const int r = wn * WN + np * 16 + ((lane >> 4) << 3) + (lane & 7);
                const int u = (kk << 1) + ((lane >> 3) & 1);
                ldsm4(&bfr[np * 2][0], sB + (uint32_t)((r * 8 + (u ^ (r & 7))) << 4));
            }
#pragma unroll
            for (int mt = 0; mt < MT; mt++)
#pragma unroll
                for (int nt = 0; nt < NT; nt++)
                    mma16816(acc[mt][nt], af[mt], bfr[nt]);
        }
    }

    // ---------------- epilogue ----------------
#pragma unroll
    for (int mt = 0; mt < MT; mt++)
#pragma unroll
        for (int nt = 0; nt < NT; nt++) {
            const int gr0 = m0 + wm * WM + mt * 16 + (lane >> 2);
            const int gc = n0 + wn * WN + nt * 8 + ((lane & 3) << 1);
            const float b0v = bias ? bias[gc] : 0.f;
            const float b1v = bias ? bias[gc + 1] : 0.f;
#pragma unroll
            for (int h2 = 0; h2 < 2; h2++) {
                const int gr = gr0 + h2 * 8;
                const float x0 = alpha * acc[mt][nt][h2 * 2 + 0] + b0v;
                const float x1 = alpha * acc[mt][nt][h2 * 2 + 1] + b1v;
                if (!vmode) {
                    const long long idx = coff + (long long)gr * ldc + gc;
                    if (Cf) { Cf[idx] = x0; Cf[idx + 1] = x1; }
                    if (Chi) {
                        bf16 h0 = __float2bfloat16_rn(x0), h1 = __float2bfloat16_rn(x1);
                        Chi[idx] = h0; Chi[idx + 1] = h1;
                        if (Clo) {
                            Clo[idx] = __float2bfloat16_rn(x0 - __bfloat162float(h0));
                            Clo[idx + 1] = __float2bfloat16_rn(x1 - __bfloat162float(h1));
                        }
                    }
                } else {
                    const int bb = gr >> 8, jj = gr & 255;
#pragma unroll
                    for (int e = 0; e < 2; e++) {
                        const float x = e ? x1 : x0;
                        const int n = gc + e, h = n >> 6, d = n & 63;
                        const size_t off = ((size_t)(bb * 8 + h) * 64 + d) * 256 + jj;
                        bf16 hh = __float2bfloat16_rn(x);
                        Chi[off] = hh;
                        Clo[off] = __float2bfloat16_rn(x - __bfloat162float(hh));
                    }
                }
            }
        }
}

// ---------------------------------------------------------------------------
// Dual-B GEMM for o-proj: ao = A @ (B0^T) + A @ (B1^T) + bias, bf16 out.
// A chunk loaded ONCE per K-chunk, both B terms streamed alongside.
// BM=128, BN=128, WM=32, WN=64, BK=64. 2-stage, 48KB/stage, 2 CTAs/SM.
// ---------------------------------------------------------------------------
__global__ __launch_bounds__(256, 2)
void gemm_dual(const bf16* __restrict__ A, const bf16* __restrict__ B0,
               const bf16* __restrict__ B1, const float* __restrict__ bias,
               bf16* __restrict__ C)
{
    constexpr int STG = 49152;            // A 16K + B0 16K + B1 16K
    extern __shared__ char dynsm[];
    const uint32_t s0 = smem_u32(dynsm);

    const int tid = threadIdx.x, warp = tid >> 5, lane = tid & 31;
    const int wm = warp >> 1, wn = warp & 1;   // 4x2 warps -> WM=32, WN=64

    const int m0 = blockIdx.y * 128;
    const int n0 = blockIdx.x * 128;
    const int fr = tid >> 3, fu = tid & 7;

    float acc[2][8][4];
#pragma unroll
    for (int i = 0; i < 2; i++)
#pragma unroll
        for (int j = 0; j < 8; j++)
#pragma unroll
            for (int e = 0; e < 4; e++) acc[i][j][e] = 0.f;

    auto prefetch = [&](int chunk, int buf) {
        const int k0 = chunk << 6;
        const uint32_t base = s0 + buf * STG;
#pragma unroll
        for (int p = 0; p < 4; p++) {
            const int r = fr + p * 32;
            const uint32_t off = (uint32_t)((r * 8 + (fu ^ (r & 7))) << 4);
            cp16(base + off,         A  + (size_t)(m0 + r) * 512 + k0 + fu * 8);
            cp16(base + 16384 + off, B0 + (size_t)(n0 + r) * 512 + k0 + fu * 8);
            cp16(base + 32768 + off, B1 + (size_t)(n0 + r) * 512 + k0 + fu * 8);
        }
        asm volatile("cp.async.commit_group;");
    };

    prefetch(0, 0);
    for (int it = 0; it < 8; it++) {
        asm volatile("cp.async.wait_group 0;");
        __syncthreads();
        if (it + 1 < 8) prefetch(it + 1, (it + 1) & 1);

        const uint32_t base = s0 + (it & 1) * STG;
#pragma unroll
        for (int kk = 0; kk < 4; kk++) {
            uint32_t af[2][4];
#pragma unroll
            for (int mt = 0; mt < 2; mt++) {
                const int r = wm * 32 + mt * 16 + (lane & 15);
                const int u = (kk << 1) + (lane >> 4);
                ldsm4(af[mt], base + (uint32_t)((r * 8 + (u ^ (r & 7))) << 4));
            }
#pragma unroll
            for (int term = 0; term < 2; term++) {
                const uint32_t sB = base + 16384 + term * 16384;
                uint32_t bfr[8][2];
#pragma unroll
                for (int np = 0; np < 4; np++) {
                    const int r = wn * 64 + np * 16 + ((lane >> 4) << 3) + (lane & 7);
                    const int u = (kk << 1) + ((lane >> 3) & 1);
                    ldsm4(&bfr[np * 2][0], sB + (uint32_t)((r * 8 + (u ^ (r & 7))) << 4));
                }
#pragma unroll
                for (int mt = 0; mt < 2; mt++)
#pragma unroll
                    for (int nt = 0; nt < 8; nt++)
                        mma16816(acc[mt][nt], af[mt], bfr[nt]);
            }
        }
    }

    // epilogue: bias + bf16 store
#pragma unroll
    for (int mt = 0; mt < 2; mt++)
#pragma unroll
        for (int nt = 0; nt < 8; nt++) {
            const int gr0 = m0 + wm * 32 + mt * 16 + (lane >> 2);
            const int gc = n0 + wn * 64 + nt * 8 + ((lane & 3) << 1);
            const float b0v = bias[gc], b1v = bias[gc + 1];
#pragma unroll
            for (int h2 = 0; h2 < 2; h2++) {
                const int gr = gr0 + h2 * 8;
                __nv_bfloat162 o;
                o.x = __float2bfloat16_rn(acc[mt][nt][h2 * 2 + 0] + b0v);
                o.y = __float2bfloat16_rn(acc[mt][nt][h2 * 2 + 1] + b1v);
                *(__nv_bfloat162*)(C + (size_t)gr * 512 + gc) = o;
            }
        }
}

// ---------------------------------------------------------------------------
// Fused attention, FA2-style register path (unchanged from R10).
// ---------------------------------------------------------------------------
__global__ __launch_bounds__(256, 1)
void attn_fused(const bf16* __restrict__ qHp, const bf16* __restrict__ kHp,
                const bf16* __restrict__ vtHp, const bf16* __restrict__ vtLp,
                bf16* __restrict__ ctxp, const int* __restrict__ nsp)
{
    extern __shared__ char dsm[];
    const uint32_t uQ  = smem_u32(dsm);
    const uint32_t uKH = uQ + 16384;
    const uint32_t uVH = uQ + 49152;
    const uint32_t uVL = uQ + 81920;

    const int tid = threadIdx.x, warp = tid >> 5, lane = tid & 31;
    const int bh = blockIdx.y, b = bh >> 3, h = bh & 7;
    const int ns = nsp[b];
    const int q0 = blockIdx.x * 128;

    {
        const bf16* gQ = qHp + ((size_t)b * 2048 + q0) * 512 + h * 64;
#pragma unroll
        for (int t = 0; t < 4; t++) {
            int id = tid + (t << 8);
            int r = id >> 3, u = id & 7;
            cp16(uQ + (uint32_t)((r * 8 + (u ^ (r & 7))) << 4), gQ + (size_t)r * 512 + u * 8);
        }
        const bf16* gKH = kHp + ((size_t)b * 256) * 512 + h * 64;
#pragma unroll
        for (int t = 0; t < 8; t++) {
            int id = tid + (t << 8);
            int r = id >> 3, u = id & 7;
            cp16(uKH + (uint32_t)((r * 8 + (u ^ (r & 7))) << 4), gKH + (size_t)r * 512 + u * 8);
        }
        const bf16* gVH = vtHp + (size_t)bh * 16384;
        const bf16* gVL = vtLp + (size_t)bh * 16384;
#pragma unroll
        for (int t = 0; t < 8; t++) {
            int id = tid + (t << 8);
            int r = id >> 5, u = id & 31;
            uint32_t off = (uint32_t)((r * 32 + (u ^ ((r & 7) << 2))) << 4);
            cp16(uVH + off, gVH + (size_t)r * 256 + u * 8);
            cp16(uVL + off, gVL + (size_t)r * 256 + u * 8);
        }
        asm volatile("cp.async.commit_group;");
        asm volatile("cp.async.wait_group 0;");
    }
    __syncthreads();

    float acc[32][4];
#pragma unroll
    for (int j = 0; j < 32; j++)
#pragma unroll
        for (int e = 0; e < 4; e++) acc[j][e] = 0.f;

#pragma unroll
    for (int kk = 0; kk < 4; kk++) {
        uint32_t af[4];
        {
            int r = warp * 16 + (lane & 15);
            int u = kk * 2 + (lane >> 4);
            ldsm4(af, uQ + (uint32_t)((r * 8 + (u ^ (r & 7))) << 4));
        }
#pragma unroll
        for (int nc = 0; nc < 4; nc++) {
            uint32_t bfr[8][2];
#pragma unroll
            for (int np = 0; np < 4; np++) {
                int r = nc * 64 + np * 16 + ((lane >> 4) << 3) + (lane & 7);
                int u = kk * 2 + ((lane >> 3) & 1);
                ldsm4(&bfr[np * 2][0], uKH + (uint32_t)((r * 8 + (u ^ (r & 7))) << 4));
            }
#pragma unroll
            for (int nt = 0; nt < 8; nt++)
                mma16816(acc[nc * 8 + nt], af, bfr[nt]);
        }
    }

    float mx[2] = {-3.0e38f, -3.0e38f};
#pragma unroll
    for (int nt = 0; nt < 32; nt++) {
        const int cb = nt * 8 + ((lane & 3) << 1);
#pragma unroll
        for (int hf = 0; hf < 2; hf++)
#pragma unroll
            for (int e = 0; e < 2; e++) {
                float x = (cb + e < ns) ? 0.125f * acc[nt][hf * 2 + e] : -3.0e38f;
                acc[nt][hf * 2 + e] = x;
                mx[hf] = fmaxf(mx[hf], x);
            }
    }
#pragma unroll
    for (int hf = 0; hf < 2; hf++) {
        mx[hf] = fmaxf(mx[hf], __shfl_xor_sync(0xffffffffu, mx[hf], 1));
        mx[hf] = fmaxf(mx[hf], __shfl_xor_sync(0xffffffffu, mx[hf], 2));
    }
    float sm[2] = {0.f, 0.f};
#pragma unroll
    for (int nt = 0; nt < 32; nt++)
#pragma unroll
        for (int hf = 0; hf < 2; hf++)
#pragma unroll
            for (int e = 0; e < 2; e++) {
                float p = __expf(acc[nt][hf * 2 + e] - mx[hf]);
                acc[nt][hf * 2 + e] = p;
                sm[hf] += p;
            }
#pragma unroll
    for (int hf = 0; hf < 2; hf++) {
        sm[hf] += __shfl_xor_sync(0xffffffffu, sm[hf], 1);
        sm[hf] += __shfl_xor_sync(0xffffffffu, sm[hf], 2);
    }
    const float inv0 = 1.f / sm[0], inv1 = 1.f / sm[1];

    uint32_t pa[64];
#pragma unroll
    for (int kt = 0; kt < 16; kt++) {
        const int t0 = 2 * kt, t1 = 2 * kt + 1;
        pa[kt * 4 + 0] = packbf2(acc[t0][0] * inv0, acc[t0][1] * inv0);
        pa[kt * 4 + 1] = packbf2(acc[t0][2] * inv1, acc[t0][3] * inv1);
        pa[kt * 4 + 2] = packbf2(acc[t1][0] * inv0, acc[t1][1] * inv0);
        pa[kt * 4 + 3] = packbf2(acc[t1][2] * inv1, acc[t1][3] * inv1);
    }

    float cacc[8][4];
#pragma unroll
    for (int j = 0; j < 8; j++)
#pragma unroll
        for (int e = 0; e < 4; e++) cacc[j][e] = 0.f;

#pragma unroll
    for (int term = 0; term < 2; term++) {
        const uint32_t vb = term ? uVL : uVH;
#pragma unroll
        for (int kt = 0; kt < 16; kt++) {
            uint32_t bf2[8][2];
#pragma unroll
            for (int np = 0; np < 4; np++) {
                int r = np * 16 + ((lane >> 4) << 3) + (lane & 7);
                int u = kt * 2 + ((lane >> 3) & 1);
                ldsm4(&bf2[np * 2][0], vb + (uint32_t)((r * 32 + (u ^ ((r & 7) << 2))) << 4));
            }
#pragma unroll
            for (int nt = 0; nt < 8; nt++)
                mma16816(cacc[nt], &pa[kt * 4], bf2[nt]);
        }
    }

#pragma unroll
    for (int nt = 0; nt < 8; nt++)
#pragma unroll
        for (int hf = 0; hf < 2; hf++) {
            const int qrow = q0 + warp * 16 + (lane >> 2) + hf * 8;
            const int d = nt * 8 + ((lane & 3) << 1);
            __nv_bfloat162 o;
            o.x = __float2bfloat16_rn(cacc[nt][hf * 2 + 0]);
            o.y = __float2bfloat16_rn(cacc[nt][hf * 2 + 1]);
            *(__nv_bfloat162*)(ctxp + ((size_t)b * 2048 + qrow) * 512 + h * 64 + d) = o;
        }
}

// ======================= small kernels =======================
__global__ void split_kernel(const float* __restrict__ in, bf16* __restrict__ hi,
                             bf16* __restrict__ lo, int n)
{
    int i = blockIdx.x * blockDim.x + threadIdx.x;
    if (i < n) {
        float x = in[i];
        bf16 h = __float2bfloat16_rn(x);
        hi[i] = h;
        if (lo) lo[i] = __float2bfloat16_rn(x - __bfloat162float(h));
    }
}

__global__ void split_weights(const float* __restrict__ w0, const float* __restrict__ w1,
                              const float* __restrict__ w2, const float* __restrict__ w3,
                              bf16* __restrict__ base)
{
    int y = blockIdx.y;
    const float* src = (y == 0) ? w0 : (y == 1) ? w1 : (y == 2) ? w2 : w3;
    bf16* hi = base + (size_t)y * 2 * 262144;
    bf16* lo = hi + 262144;
    int i = blockIdx.x * blockDim.x + threadIdx.x;
    if (i < 262144) {
        float x = src[i];
        bf16 h = __float2bfloat16_rn(x);
        hi[i] = h;
        lo[i] = __float2bfloat16_rn(x - __bfloat162float(h));
    }
}

// residual + LayerNorm + partial row-mean, bf16 inputs (qinH + aoB)
__global__ __launch_bounds__(512) void epilogue_ln(
    const bf16* __restrict__ qinB, const bf16* __restrict__ aoB,
    const float* __restrict__ lnw, const float* __restrict__ lnb,
    float* __restrict__ part)
{
    __shared__ float r1[16], r2[16], stats[2];
    int b = blockIdx.y, chunk = blockIdx.x;
    int col = threadIdx.x, wid = col >> 5, lane = col & 31;
    float w = lnw[col], bb = lnb[col];
    float acc = 0.f;
    size_t base = ((size_t)b * Ll + chunk * 64) * Dd + col;

    for (int r = 0; r < 64; r++) {
        size_t idx = base + (size_t)r * Dd;
        float x = __bfloat162float(qinB[idx]) + __bfloat162float(aoB[idx]);
        float s = x, s2 = x * x;
#pragma unroll
        for (int o = 16; o; o >>= 1) {
            s  += __shfl_xor_sync(0xffffffffu, s, o);
            s2 += __shfl_xor_sync(0xffffffffu, s2, o);
        }
        if (lane == 0) { r1[wid] = s; r2[wid] = s2; }
        __syncthreads();
        if (col < 32) {
            float a  = (col < 16) ? r1[col] : 0.f;
            float a2 = (col < 16) ? r2[col] : 0.f;
#pragma unroll
            for (int o = 8; o; o >>= 1) {
                a  += __shfl_xor_sync(0xffffffffu, a, o);
                a2 += __shfl_xor_sync(0xffffffffu, a2, o);
            }
            if (col == 0) { stats[0] = a; stats[1] = a2; }
        }
        __syncthreads();
        float mu  = stats[0] * (1.f / 512.f);
        float var = stats[1] * (1.f / 512.f) - mu * mu;
        float xn  = (x - mu) * rsqrtf(var + 1e-5f);
        acc += xn * w + bb;
    }
    part[((size_t)b * 32 + chunk) * Dd + col] = acc;
}

__global__ void final_reduce(const float* __restrict__ part, float* __restrict__ out)
{
    int b = blockIdx.x, col = threadIdx.x;
    float s = 0.f;
#pragma unroll
    for (int c = 0; c < 32; c++) s += part[((size_t)b * 32 + c) * Dd + col];
    out[b * Dd + col] = s * (1.f / 2048.f);
}

// ======================= driver =======================
extern "C" void kernel_launch(void* const* d_in, const int* in_sizes, int n_in,
                              void* d_out, int out_size)
{
    (void)in_sizes; (void)n_in; (void)out_size;
    const float* qin  = (const float*)d_in[0];
    const float* sent = (const float*)d_in[1];
    const int*   ns   = (const int*)  d_in[2];
    const float* Wq   = (const float*)d_in[3];
    const float* bq   = (const float*)d_in[4];
    const float* Wk   = (const float*)d_in[5];
    const float* bk   = (const float*)d_in[6];
    const float* Wv   = (const float*)d_in[7];
    const float* bvv  = (const float*)d_in[8];
    const float* Wo   = (const float*)d_in[9];
    const float* bo   = (const float*)d_in[10];
    const float* lnw  = (const float*)d_in[11];
    const float* lnb  = (const float*)d_in[12];
    float* out = (float*)d_out;

    void* p_;
    cudaGetSymbolAddress(&p_, g_qinH_);   bf16* qinH = (bf16*)p_;
    cudaGetSymbolAddress(&p_, g_sentHL_); bf16* sentH = (bf16*)p_; bf16* sentL = sentH + 1048576;
    cudaGetSymbolAddress(&p_, g_W_);      bf16* W = (bf16*)p_;
    bf16 *WqH = W,            *WkH = W + 2*262144;
    bf16 *WvH = W + 4*262144, *WvL = W + 5*262144, *WoH = W + 6*262144, *WoL = W + 7*262144;
    cudaGetSymbolAddress(&p_, g_qH_);    bf16* qH  = (bf16*)p_;
    cudaGetSymbolAddress(&p_, g_kH_);    bf16* kH  = (bf16*)p_;
    cudaGetSymbolAddress(&p_, g_vtHL_);  bf16* vtH = (bf16*)p_;  bf16* vtL = vtH + 1048576;
    cudaGetSymbolAddress(&p_, g_ctxH_);  bf16* ctxH = (bf16*)p_;
    cudaGetSymbolAddress(&p_, g_ao_);    bf16* aoB = (bf16*)p_;
    cudaGetSymbolAddress(&p_, g_part_);  float* part = (float*)p_;

    constexpr int SM_QO = 3 * (128 * 128 + 128 * 128);  // 98304 (BK=64, bf16)
    constexpr int SM_KV = 3 * (64 * 128 + 128 * 128);   // 73728
    constexpr int SM_DU = 2 * 49152;                    // 98304
    cudaFuncSetAttribute((const void*)gemm_mma<128,128,32,64>,
                         cudaFuncAttributeMaxDynamicSharedMemorySize, SM_QO);
    cudaFuncSetAttribute((const void*)gemm_mma<64,128,32,32>,
                         cudaFuncAttributeMaxDynamicSharedMemorySize, SM_KV);
    cudaFuncSetAttribute((const void*)gemm_dual,
                         cudaFuncAttributeMaxDynamicSharedMemorySize, SM_DU);
    cudaFuncSetAttribute((const void*)attn_fused,
                         cudaFuncAttributeMaxDynamicSharedMemorySize, 114688);

    // splits
    split_kernel<<<32768, 256>>>(qin,  qinH, nullptr, 8388608);
    split_kernel<<<4096,  256>>>(sent, sentH, sentL, 1048576);
    split_weights<<<dim3(1024, 4), 256>>>(Wq, Wk, Wv, Wo, W);

    // q = QinH @ WqH^T + bq  (1 term) -> qH (bf16)
    gemm_mma<128,128,32,64><<<dim3(4, 128, 1), 256, SM_QO>>>(
        qinH, nullptr, nullptr, WqH, nullptr, nullptr, 1, bq,
        nullptr, qH, nullptr, 512, 512, 512, 512,
        1, 0, 0, 0, 0, 0, 0, 1.f, 0);

    // k = sentH @ WkH^T + bk  (1 term) -> kH (bf16)
    gemm_mma<64,128,32,32><<<dim3(4, 32, 1), 256, SM_KV>>>(
        sentH, nullptr, nullptr, WkH, nullptr, nullptr, 1, bk,
        nullptr, kH, nullptr, 512, 512, 512, 512,
        1, 0, 0, 0, 0, 0, 0, 1.f, 0);

    // v = sent @ Wv^T + bv  (3 terms) -> vt[bh][d][s] hi/lo
    gemm_mma<64,128,32,32><<<dim3(4, 32, 1), 256, SM_KV>>>(
        sentH, sentH, sentL, WvH, WvL, WvH, 3, bvv,
        nullptr, vtH, vtL, 512, 512, 512, 512,
        1, 0, 0, 0, 0, 0, 0, 1.f, 1);

    // fused attention (1-term scores) -> ctxH (bf16)
    attn_fused<<<dim3(16, 64), 256, 114688>>>(qH, kH, vtH, vtL, ctxH, ns);

    // attn_out = ctx @ (WoH + WoL)^T + bo  (dual-B) -> bf16 aoB
    gemm_dual<<<dim3(4, 128), 256, SM_DU>>>(ctxH, WoH, WoL, bo, aoB);

    // residual + LN + partial mean (bf16 inputs), then final reduce
    epilogue_ln<<<dim3(32, 8), 512>>>(qinH, aoB, lnw, lnb, part);
    final_reduce<<<8, 512>>>(part, out);
}

// round 12
// speedup vs baseline: 3.0261x; 1.1111x over previous
#include <cuda_runtime.h>
#include <cuda_bf16.h>
#include <cstdint>
#include <cstddef>

typedef __nv_bfloat16 bf16;

// ======================= portable PTX helpers (sm_80+) =======================
__device__ __forceinline__ uint32_t smem_u32(const void* p) {
    uint32_t a;
    asm("{ .reg .u64 t; cvta.to.shared.u64 t, %1; cvt.u32.u64 %0, t; }" : "=r"(a) : "l"(p));
    return a;
}
__device__ __forceinline__ void cp16(uint32_t dst, const void* src) {
    asm volatile("cp.async.cg.shared.global [%0], [%1], 16;" :: "r"(dst), "l"(src));
}
__device__ __forceinline__ void ldsm4(uint32_t* r, uint32_t a) {
    asm volatile("ldmatrix.sync.aligned.m8n8.x4.shared.b16 {%0,%1,%2,%3}, [%4];"
        : "=r"(r[0]), "=r"(r[1]), "=r"(r[2]), "=r"(r[3]) : "r"(a));
}
__device__ __forceinline__ void mma16816(float* c, const uint32_t* a, const uint32_t* b) {
    asm volatile(
        "mma.sync.aligned.m16n8k16.row.col.f32.bf16.bf16.f32 "
        "{%0,%1,%2,%3}, {%4,%5,%6,%7}, {%8,%9}, {%0,%1,%2,%3};"
        : "+f"(c[0]), "+f"(c[1]), "+f"(c[2]), "+f"(c[3])
        : "r"(a[0]), "r"(a[1]), "r"(a[2]), "r"(a[3]), "r"(b[0]), "r"(b[1]));
}
__device__ __forceinline__ uint32_t packbf2(float lo, float hi) {
    __nv_bfloat162 p;
    p.x = __float2bfloat16_rn(lo);
    p.y = __float2bfloat16_rn(hi);
    return *(uint32_t*)&p;
}

// ======================= constants & scratch =======================
static const int Dd = 512, Ll = 2048;

__device__ uint4 g_qinH_[1048576];        // bf16(Qin)             16 MB
__device__ uint4 g_sentHL_[2 * 131072];   // sentH, sentL
__device__ uint4 g_W_[8 * 32768];         // WqH WqL WkH WkL WvH WvL WoH WoL
__device__ uint4 g_qH_[1048576];          // bf16(q)               16 MB
__device__ uint4 g_kH_[131072];           // kH
__device__ uint4 g_vtHL_[2 * 131072];     // vtH, vtL [bh][64][256]
__device__ uint4 g_ctxH_[1048576];        // bf16(ctx)             16 MB
__device__ uint4 g_ao_[2097152];          // bf16 attn_out (16 MB used)
__device__ float g_part_[8 * 64 * 512];   // 1 MB LN partials

// ---------------------------------------------------------------------------
// Generic multi-term bf16 GEMM, BK=64 chunks, 3-stage cp.async, 2 CTAs/SM.
// ---------------------------------------------------------------------------
template<int BM, int BN, int WM, int WN>
__global__ __launch_bounds__(256, 2)
void gemm_mma(const bf16* A0, const bf16* A1, const bf16* A2,
              const bf16* B0, const bf16* B1, const bf16* B2,
              int nterms, const float* __restrict__ bias,
              float* __restrict__ Cf, bf16* __restrict__ Chi, bf16* __restrict__ Clo,
              int Ktot, int lda, int ldb, int ldc,
              int HH, long long sAb, long long sAh, long long sBb, long long sBh,
              long long sCb, long long sCh, float alpha, int vmode)
{
    constexpr int BK = 64;
    constexpr int WARPS_N = BN / WN;
    constexpr int MT = WM / 16, NT = WN / 8;
    constexpr int ASZ = BM * BK * 2, BSZ = BN * BK * 2;
    static_assert((BM / WM) * (BN / WN) == 8, "8 warps");

    extern __shared__ char dynsm[];
    const uint32_t sA0 = smem_u32(dynsm);
    const uint32_t sB0 = sA0 + 3 * ASZ;

    const int tid = threadIdx.x, warp = tid >> 5, lane = tid & 31;
    const int wm = warp / WARPS_N, wn = warp % WARPS_N;

    const bf16* Al[3] = {A0, A1, A2};
    const bf16* Bl[3] = {B0, B1, B2};

    const int z = blockIdx.z;
    const int bz = z / HH, hz = z - bz * HH;
    const long long aoff = (long long)bz * sAb + (long long)hz * sAh;
    const long long boff = (long long)bz * sBb + (long long)hz * sBh;
    const long long coff = (long long)bz * sCb + (long long)hz * sCh;

    const int m0 = blockIdx.y * BM;
    const int n0 = blockIdx.x * BN;

    const int kch = Ktot >> 6;
    const int total = nterms * kch;

    const int fr = tid >> 3, fu = tid & 7;

    float acc[MT][NT][4];
#pragma unroll
    for (int i = 0; i < MT; i++)
#pragma unroll
        for (int j = 0; j < NT; j++)
#pragma unroll
            for (int e = 0; e < 4; e++) acc[i][j][e] = 0.f;

    auto prefetch = [&](int chunk, int buf) {
        const int term = chunk / kch;
        const int k0 = (chunk - term * kch) << 6;
        const bf16* Ag = Al[term] + aoff + k0;
        const uint32_t sA = sA0 + buf * ASZ;
#pragma unroll
        for (int p = 0; p < BM / 32; p++) {
            const int r = fr + p * 32;
            cp16(sA + (uint32_t)((r * 8 + (fu ^ (r & 7))) << 4),
                 Ag + (size_t)(m0 + r) * lda + fu * 8);
        }
        const bf16* Bg = Bl[term] + boff + k0;
        const uint32_t sB = sB0 + buf * BSZ;
#pragma unroll
        for (int p = 0; p < BN / 32; p++) {
            const int r = fr + p * 32;
            cp16(sB + (uint32_t)((r * 8 + (fu ^ (r & 7))) << 4),
                 Bg + (size_t)(n0 + r) * ldb + fu * 8);
        }
        asm volatile("cp.async.commit_group;");
    };

    prefetch(0, 0);
    prefetch(1, 1);
    for (int it = 0; it < total; it++) {
        if (it + 1 < total) asm volatile("cp.async.wait_group 1;");
        else                asm volatile("cp.async.wait_group 0;");
        __syncthreads();
        if (it + 2 < total) prefetch(it + 2, (it + 2) % 3);

        const int buf = it % 3;
        const uint32_t sA = sA0 + buf * ASZ;
        const uint32_t sB = sB0 + buf * BSZ;
#pragma unroll
        for (int kk = 0; kk < 4; kk++) {
            uint32_t af[MT][4];
#pragma unroll
            for (int mt = 0; mt < MT; mt++) {
                const int r = wm * WM + mt * 16 + (lane & 15);
                const int u = (kk << 1) + (lane >> 4);
                ldsm4(af[mt], sA + (uint32_t)((r * 8 + (u ^ (r & 7))) << 4));
            }
            uint32_t bfr[NT][2];
#pragma unroll
            for (int np = 0; np < NT / 2; np++) {
                const int r = wn * WN + np * 16 + ((lane >> 4) << 3) + (lane & 7);
                const int u = (kk << 1) + ((lane >> 3) & 1);
                ldsm4(&bfr[np * 2][0], sB + (uint32_t)((r * 8 + (u ^ (r & 7))) << 4));
            }
#pragma unroll
            for (int mt = 0; mt < MT; mt++)
#pragma unroll
                for (int nt = 0; nt < NT; nt++)
                    mma16816(acc[mt][nt], af[mt], bfr[nt]);
        }
    }

    // ---------------- epilogue ----------------
#pragma unroll
    for (int mt = 0; mt < MT; mt++)
#pragma unroll
        for (int nt = 0; nt < NT; nt++) {
            const int gr0 = m0 + wm * WM + mt * 16 + (lane >> 2);
            const int gc = n0 + wn * WN + nt * 8 + ((lane & 3) << 1);
            const float b0v = bias ? bias[gc] : 0.f;
            const float b1v = bias ? bias[gc + 1] : 0.f;
#pragma unroll
            for (int h2 = 0; h2 < 2; h2++) {
                const int gr = gr0 + h2 * 8;
                const float x0 = alpha * acc[mt][nt][h2 * 2 + 0] + b0v;
                const float x1 = alpha * acc[mt][nt][h2 * 2 + 1] + b1v;
                if (!vmode) {
                    const long long idx = coff + (long long)gr * ldc + gc;
                    if (Cf) { Cf[idx] = x0; Cf[idx + 1] = x1; }
                    if (Chi) {
                        bf16 h0 = __float2bfloat16_rn(x0), h1 = __float2bfloat16_rn(x1);
                        Chi[idx] = h0; Chi[idx + 1] = h1;
                        if (Clo) {
                            Clo[idx] = __float2bfloat16_rn(x0 - __bfloat162float(h0));
                            Clo[idx + 1] = __float2bfloat16_rn(x1 - __bfloat162float(h1));
                        }
                    }
                } else {
                    const int bb = gr >> 8, jj = gr & 255;
#pragma unroll
                    for (int e = 0; e < 2; e++) {
                        const float x = e ? x1 : x0;
                        const int n = gc + e, h = n >> 6, d = n & 63;
                        const size_t off = ((size_t)(bb * 8 + h) * 64 + d) * 256 + jj;
                        bf16 hh = __float2bfloat16_rn(x);
                        Chi[off] = hh;
                        Clo[off] = __float2bfloat16_rn(x - __bfloat162float(hh));
                    }
                }
            }
        }
}

// ---------------------------------------------------------------------------
// Dual-B GEMM for o-proj (unchanged from R11).
// ---------------------------------------------------------------------------
__global__ __launch_bounds__(256, 2)
void gemm_dual(const bf16* __restrict__ A, const bf16* __restrict__ B0,
               const bf16* __restrict__ B1, const float* __restrict__ bias,
               bf16* __restrict__ C)
{
    constexpr int STG = 49152;
    extern __shared__ char dynsm[];
    const uint32_t s0 = smem_u32(dynsm);

    const int tid = threadIdx.x, warp = tid >> 5, lane = tid & 31;
    const int wm = warp >> 1, wn = warp & 1;

    const int m0 = blockIdx.y * 128;
    const int n0 = blockIdx.x * 128;
    const int fr = tid >> 3, fu = tid & 7;

    float acc[2][8][4];
#pragma unroll
    for (int i = 0; i < 2; i++)
#pragma unroll
        for (int j = 0; j < 8; j++)
#pragma unroll
            for (int e = 0; e < 4; e++) acc[i][j][e] = 0.f;

    auto prefetch = [&](int chunk, int buf) {
        const int k0 = chunk << 6;
        const uint32_t base = s0 + buf * STG;
#pragma unroll
        for (int p = 0; p < 4; p++) {
            const int r = fr + p * 32;
            const uint32_t off = (uint32_t)((r * 8 + (fu ^ (r & 7))) << 4);
            cp16(base + off,         A  + (size_t)(m0 + r) * 512 + k0 + fu * 8);
            cp16(base + 16384 + off, B0 + (size_t)(n0 + r) * 512 + k0 + fu * 8);
            cp16(base + 32768 + off, B1 + (size_t)(n0 + r) * 512 + k0 + fu * 8);
        }
        asm volatile("cp.async.commit_group;");
    };

    prefetch(0, 0);
    for (int it = 0; it < 8; it++) {
        asm volatile("cp.async.wait_group 0;");
        __syncthreads();
        if (it + 1 < 8) prefetch(it + 1, (it + 1) & 1);

        const uint32_t base = s0 + (it & 1) * STG;
#pragma unroll
        for (int kk = 0; kk < 4; kk++) {
            uint32_t af[2][4];
#pragma unroll
            for (int mt = 0; mt < 2; mt++) {
                const int r = wm * 32 + mt * 16 + (lane & 15);
                const int u = (kk << 1) + (lane >> 4);
                ldsm4(af[mt], base + (uint32_t)((r * 8 + (u ^ (r & 7))) << 4));
            }
#pragma unroll
            for (int term = 0; term < 2; term++) {
                const uint32_t sB = base + 16384 + term * 16384;
                uint32_t bfr[8][2];
#pragma unroll
                for (int np = 0; np < 4; np++) {
                    const int r = wn * 64 + np * 16 + ((lane >> 4) << 3) + (lane & 7);
                    const int u = (kk << 1) + ((lane >> 3) & 1);
                    ldsm4(&bfr[np * 2][0], sB + (uint32_t)((r * 8 + (u ^ (r & 7))) << 4));
                }
#pragma unroll
                for (int mt = 0; mt < 2; mt++)
#pragma unroll
                    for (int nt = 0; nt < 8; nt++)
                        mma16816(acc[mt][nt], af[mt], bfr[nt]);
            }
        }
    }

#pragma unroll
    for (int mt = 0; mt < 2; mt++)
#pragma unroll
        for (int nt = 0; nt < 8; nt++) {
            const int gr0 = m0 + wm * 32 + mt * 16 + (lane >> 2);
            const int gc = n0 + wn * 64 + nt * 8 + ((lane & 3) << 1);
            const float b0v = bias[gc], b1v = bias[gc + 1];
#pragma unroll
            for (int h2 = 0; h2 < 2; h2++) {
                const int gr = gr0 + h2 * 8;
                __nv_bfloat162 o;
                o.x = __float2bfloat16_rn(acc[mt][nt][h2 * 2 + 0] + b0v);
                o.y = __float2bfloat16_rn(acc[mt][nt][h2 * 2 + 1] + b1v);
                *(__nv_bfloat162*)(C + (size_t)gr * 512 + gc) = o;
            }
        }
}

// ---------------------------------------------------------------------------
// Fused attention, FA2 register path; two-phase loads (Q+K commit, V commit).
// ---------------------------------------------------------------------------
__global__ __launch_bounds__(256, 1)
void attn_fused(const bf16* __restrict__ qHp, const bf16* __restrict__ kHp,
                const bf16* __restrict__ vtHp, const bf16* __restrict__ vtLp,
                bf16* __restrict__ ctxp, const int* __restrict__ nsp)
{
    extern __shared__ char dsm[];
    const uint32_t uQ  = smem_u32(dsm);
    const uint32_t uKH = uQ + 16384;
    const uint32_t uVH = uQ + 49152;
    const uint32_t uVL = uQ + 81920;

    const int tid = threadIdx.x, warp = tid >> 5, lane = tid & 31;
    const int bh = blockIdx.y, b = bh >> 3, h = bh & 7;
    const int ns = nsp[b];
    const int q0 = blockIdx.x * 128;

    // commit 1: Q + KH (48 KB)
    {
        const bf16* gQ = qHp + ((size_t)b * 2048 + q0) * 512 + h * 64;
#pragma unroll
        for (int t = 0; t < 4; t++) {
            int id = tid + (t << 8);
            int r = id >> 3, u = id & 7;
            cp16(uQ + (uint32_t)((r * 8 + (u ^ (r & 7))) << 4), gQ + (size_t)r * 512 + u * 8);
        }
        const bf16* gKH = kHp + ((size_t)b * 256) * 512 + h * 64;
#pragma unroll
        for (int t = 0; t < 8; t++) {
            int id = tid + (t << 8);
            int r = id >> 3, u = id & 7;
            cp16(uKH + (uint32_t)((r * 8 + (u ^ (r & 7))) << 4), gKH + (size_t)r * 512 + u * 8);
        }
        asm volatile("cp.async.commit_group;");
    }
    // commit 2: VH + VL (64 KB)
    {
        const bf16* gVH = vtHp + (size_t)bh * 16384;
        const bf16* gVL = vtLp + (size_t)bh * 16384;
#pragma unroll
        for (int t = 0; t < 8; t++) {
            int id = tid + (t << 8);
            int r = id >> 5, u = id & 31;
            uint32_t off = (uint32_t)((r * 32 + (u ^ ((r & 7) << 2))) << 4);
            cp16(uVH + off, gVH + (size_t)r * 256 + u * 8);
            cp16(uVL + off, gVL + (size_t)r * 256 + u * 8);
        }
        asm volatile("cp.async.commit_group;");
    }
    asm volatile("cp.async.wait_group 1;");   // Q+K ready; V still in flight
    __syncthreads();

    float acc[32][4];
#pragma unroll
    for (int j = 0; j < 32; j++)
#pragma unroll
        for (int e = 0; e < 4; e++) acc[j][e] = 0.f;

#pragma unroll
    for (int kk = 0; kk < 4; kk++) {
        uint32_t af[4];
        {
            int r = warp * 16 + (lane & 15);
            int u = kk * 2 + (lane >> 4);
            ldsm4(af, uQ + (uint32_t)((r * 8 + (u ^ (r & 7))) << 4));
        }
#pragma unroll
        for (int nc = 0; nc < 4; nc++) {
            uint32_t bfr[8][2];
#pragma unroll
            for (int np = 0; np < 4; np++) {
                int r = nc * 64 + np * 16 + ((lane >> 4) << 3) + (lane & 7);
                int u = kk * 2 + ((lane >> 3) & 1);
                ldsm4(&bfr[np * 2][0], uKH + (uint32_t)((r * 8 + (u ^ (r & 7))) << 4));
            }
#pragma unroll
            for (int nt = 0; nt < 8; nt++)
                mma16816(acc[nc * 8 + nt], af, bfr[nt]);
        }
    }

    float mx[2] = {-3.0e38f, -3.0e38f};
#pragma unroll
    for (int nt = 0; nt < 32; nt++) {
        const int cb = nt * 8 + ((lane & 3) << 1);
#pragma unroll
        for (int hf = 0; hf < 2; hf++)
#pragma unroll
            for (int e = 0; e < 2; e++) {
                float x = (cb + e < ns) ? 0.125f * acc[nt][hf * 2 + e] : -3.0e38f;
                acc[nt][hf * 2 + e] = x;
                mx[hf] = fmaxf(mx[hf], x);
            }
    }
#pragma unroll
    for (int hf = 0; hf < 2; hf++) {
        mx[hf] = fmaxf(mx[hf], __shfl_xor_sync(0xffffffffu, mx[hf], 1));
        mx[hf] = fmaxf(mx[hf], __shfl_xor_sync(0xffffffffu, mx[hf], 2));
    }
    float sm[2] = {0.f, 0.f};
#pragma unroll
    for (int nt = 0; nt < 32; nt++)
#pragma unroll
        for (int hf = 0; hf < 2; hf++)
#pragma unroll
            for (int e = 0; e < 2; e++) {
                float p = __expf(acc[nt][hf * 2 + e] - mx[hf]);
                acc[nt][hf * 2 + e] = p;
                sm[hf] += p;
            }
#pragma unroll
    for (int hf = 0; hf < 2; hf++) {
        sm[hf] += __shfl_xor_sync(0xffffffffu, sm[hf], 1);
        sm[hf] += __shfl_xor_sync(0xffffffffu, sm[hf], 2);
    }
    const float inv0 = 1.f / sm[0], inv1 = 1.f / sm[1];

    uint32_t pa[64];
#pragma unroll
    for (int kt = 0; kt < 16; kt++) {
        const int t0 = 2 * kt, t1 = 2 * kt + 1;
        pa[kt * 4 + 0] = packbf2(acc[t0][0] * inv0, acc[t0][1] * inv0);
        pa[kt * 4 + 1] = packbf2(acc[t0][2] * inv1, acc[t0][3] * inv1);
        pa[kt * 4 + 2] = packbf2(acc[t1][0] * inv0, acc[t1][1] * inv0);
        pa[kt * 4 + 3] = packbf2(acc[t1][2] * inv1, acc[t1][3] * inv1);
    }

    asm volatile("cp.async.wait_group 0;");   // V ready
    __syncthreads();

    float cacc[8][4];
#pragma unroll
    for (int j = 0; j < 8; j++)
#pragma unroll
        for (int e = 0; e < 4; e++) cacc[j][e] = 0.f;

#pragma unroll
    for (int term = 0; term < 2; term++) {
        const uint32_t vb = term ? uVL : uVH;
#pragma unroll
        for (int kt = 0; kt < 16; kt++) {
            uint32_t bf2[8][2];
#pragma unroll
            for (int np = 0; np < 4; np++) {
                int r = np * 16 + ((lane >> 4) << 3) + (lane & 7);
                int u = kt * 2 + ((lane >> 3) & 1);
                ldsm4(&bf2[np * 2][0], vb + (uint32_t)((r * 32 + (u ^ ((r & 7) << 2))) << 4));
            }
#pragma unroll
            for (int nt = 0; nt < 8; nt++)
                mma16816(cacc[nt], &pa[kt * 4], bf2[nt]);
        }
    }

#pragma unroll
    for (int nt = 0; nt < 8; nt++)
#pragma unroll
        for (int hf = 0; hf < 2; hf++) {
            const int qrow = q0 + warp * 16 + (lane >> 2) + hf * 8;
            const int d = nt * 8 + ((lane & 3) << 1);
            __nv_bfloat162 o;
            o.x = __float2bfloat16_rn(cacc[nt][hf * 2 + 0]);
            o.y = __float2bfloat16_rn(cacc[nt][hf * 2 + 1]);
            *(__nv_bfloat162*)(ctxp + ((size_t)b * 2048 + qrow) * 512 + h * 64 + d) = o;
        }
}

// ======================= small kernels =======================
__global__ void split_kernel(const float* __restrict__ in, bf16* __restrict__ hi,
                             bf16* __restrict__ lo, int n)
{
    int i = blockIdx.x * blockDim.x + threadIdx.x;
    if (i < n) {
        float x = in[i];
        bf16 h = __float2bfloat16_rn(x);
        hi[i] = h;
        if (lo) lo[i] = __float2bfloat16_rn(x - __bfloat162float(h));
    }
}

__global__ void split_weights(const float* __restrict__ w0, const float* __restrict__ w1,
                              const float* __restrict__ w2, const float* __restrict__ w3,
                              bf16* __restrict__ base)
{
    int y = blockIdx.y;
    const float* src = (y == 0) ? w0 : (y == 1) ? w1 : (y == 2) ? w2 : w3;
    bf16* hi = base + (size_t)y * 2 * 262144;
    bf16* lo = hi + 262144;
    int i = blockIdx.x * blockDim.x + threadIdx.x;
    if (i < 262144) {
        float x = src[i];
        bf16 h = __float2bfloat16_rn(x);
        hi[i] = h;
        lo[i] = __float2bfloat16_rn(x - __bfloat162float(h));
    }
}

// Barrier-free residual+LN+partial-mean: one warp per row group; lane owns
// 16 consecutive columns. grid (8 ctas, 8 batches) x 256 thr; warp does 32 rows.
__global__ __launch_bounds__(256) void epilogue_ln(
    const bf16* __restrict__ qinB, const bf16* __restrict__ aoB,
    const float* __restrict__ lnw, const float* __restrict__ lnb,
    float* __restrict__ part)
{
    const int b = blockIdx.y;
    const int warp = threadIdx.x >> 5, lane = threadIdx.x & 31;
    const int wg = blockIdx.x * 8 + warp;          // 0..63

    float lw[16], lb_[16];
#pragma unroll
    for (int i = 0; i < 16; i++) { lw[i] = lnw[lane * 16 + i]; lb_[i] = lnb[lane * 16 + i]; }

    float acc[16];
#pragma unroll
    for (int i = 0; i < 16; i++) acc[i] = 0.f;

    for (int rr = 0; rr < 32; rr++) {
        const size_t rowo = ((size_t)b * 2048 + wg * 32 + rr) * 512 + lane * 16;
        float x[16];
        const uint4 qa = *(const uint4*)(qinB + rowo);
        const uint4 qb = *(const uint4*)(qinB + rowo + 8);
        const uint4 aa = *(const uint4*)(aoB + rowo);
        const uint4 ab = *(const uint4*)(aoB + rowo + 8);
        const bf16* q8a = (const bf16*)&qa; const bf16* q8b = (const bf16*)&qb;
        const bf16* a8a = (const bf16*)&aa; const bf16* a8b = (const bf16*)&ab;
#pragma unroll
        for (int i = 0; i < 8; i++) {
            x[i]     = __bfloat162float(q8a[i]) + __bfloat162float(a8a[i]);
            x[i + 8] = __bfloat162float(q8b[i]) + __bfloat162float(a8b[i]);
        }
        float s = 0.f, s2 = 0.f;
#pragma unroll
        for (int i = 0; i < 16; i++) { s += x[i]; s2 += x[i] * x[i]; }
#pragma unroll
        for (int o = 16; o; o >>= 1) {
            s  += __shfl_xor_sync(0xffffffffu, s, o);
            s2 += __shfl_xor_sync(0xffffffffu, s2, o);
        }
        const float mu = s * (1.f / 512.f);
        const float var = s2 * (1.f / 512.f) - mu * mu;
        const float rs = rsqrtf(var + 1e-5f);
#pragma unroll
        for (int i = 0; i < 16; i++) acc[i] += (x[i] - mu) * rs * lw[i] + lb_[i];
    }
    float* pp = part + ((size_t)b * 64 + wg) * 512 + lane * 16;
#pragma unroll
    for (int i = 0; i < 16; i++) pp[i] = acc[i];
}

__global__ void final_reduce(const float* __restrict__ part, float* __restrict__ out)
{
    int b = blockIdx.x, col = threadIdx.x;
    float s = 0.f;
#pragma unroll
    for (int c = 0; c < 64; c++) s += part[((size_t)b * 64 + c) * Dd + col];
    out[b * Dd + col] = s * (1.f / 2048.f);
}

// ======================= driver =======================
extern "C" void kernel_launch(void* const* d_in, const int* in_sizes, int n_in,
                              void* d_out, int out_size)
{
    (void)in_sizes; (void)n_in; (void)out_size;
    const float* qin  = (const float*)d_in[0];
    const float* sent = (const float*)d_in[1];
    const int*   ns   = (const int*)  d_in[2];
    const float* Wq   = (const float*)d_in[3];
    const float* bq   = (const float*)d_in[4];
    const float* Wk   = (const float*)d_in[5];
    const float* bk   = (const float*)d_in[6];
    const float* Wv   = (const float*)d_in[7];
    const float* bvv  = (const float*)d_in[8];
    const float* Wo   = (const float*)d_in[9];
    const float* bo   = (const float*)d_in[10];
    const float* lnw  = (const float*)d_in[11];
    const float* lnb  = (const float*)d_in[12];
    float* out = (float*)d_out;

    void* p_;
    cudaGetSymbolAddress(&p_, g_qinH_);   bf16* qinH = (bf16*)p_;
    cudaGetSymbolAddress(&p_, g_sentHL_); bf16* sentH = (bf16*)p_; bf16* sentL = sentH + 1048576;
    cudaGetSymbolAddress(&p_, g_W_);      bf16* W = (bf16*)p_;
    bf16 *WqH = W,            *WkH = W + 2*262144;
    bf16 *WvH = W + 4*262144, *WvL = W + 5*262144, *WoH = W + 6*262144, *WoL = W + 7*262144;
    cudaGetSymbolAddress(&p_, g_qH_);    bf16* qH  = (bf16*)p_;
    cudaGetSymbolAddress(&p_, g_kH_);    bf16* kH  = (bf16*)p_;
    cudaGetSymbolAddress(&p_, g_vtHL_);  bf16* vtH = (bf16*)p_;  bf16* vtL = vtH + 1048576;
    cudaGetSymbolAddress(&p_, g_ctxH_);  bf16* ctxH = (bf16*)p_;
    cudaGetSymbolAddress(&p_, g_ao_);    bf16* aoB = (bf16*)p_;
    cudaGetSymbolAddress(&p_, g_part_);  float* part = (float*)p_;

    constexpr int SM_QO = 3 * (128 * 128 + 128 * 128);  // 98304
    constexpr int SM_KV = 3 * (64 * 128 + 128 * 128);   // 73728
    constexpr int SM_DU = 2 * 49152;                    // 98304
    static cudaStream_t sB = nullptr;
    static cudaEvent_t evFork = nullptr, evJoin = nullptr;
    if (!sB) {
        cudaFuncSetAttribute((const void*)gemm_mma<128,128,32,64>,
                             cudaFuncAttributeMaxDynamicSharedMemorySize, SM_QO);
        cudaFuncSetAttribute((const void*)gemm_mma<64,128,32,32>,
                             cudaFuncAttributeMaxDynamicSharedMemorySize, SM_KV);
        cudaFuncSetAttribute((const void*)gemm_dual,
                             cudaFuncAttributeMaxDynamicSharedMemorySize, SM_DU);
        cudaFuncSetAttribute((const void*)attn_fused,
                             cudaFuncAttributeMaxDynamicSharedMemorySize, 114688);
        cudaStreamCreateWithFlags(&sB, cudaStreamNonBlocking);
        cudaEventCreateWithFlags(&evFork, cudaEventDisableTiming);
        cudaEventCreateWithFlags(&evJoin, cudaEventDisableTiming);
    }

    // ---- main stream: qin split + weight splits, then fork ----
    split_kernel<<<32768, 256>>>(qin, qinH, nullptr, 8388608);
    split_weights<<<dim3(1024, 4), 256>>>(Wq, Wk, Wv, Wo, W);
    cudaEventRecord(evFork, 0);

    // ---- side stream: sent split -> k-proj -> v-proj ----
    cudaStreamWaitEvent(sB, evFork, 0);
    split_kernel<<<4096, 256, 0, sB>>>(sent, sentH, sentL, 1048576);
    gemm_mma<64,128,32,32><<<dim3(4, 32, 1), 256, SM_KV, sB>>>(
        sentH, nullptr, nullptr, WkH, nullptr, nullptr, 1, bk,
        nullptr, kH, nullptr, 512, 512, 512, 512,
        1, 0, 0, 0, 0, 0, 0, 1.f, 0);
    gemm_mma<64,128,32,32><<<dim3(4, 32, 1), 256, SM_KV, sB>>>(
        sentH, sentH, sentL, WvH, WvL, WvH, 3, bvv,
        nullptr, vtH, vtL, 512, 512, 512, 512,
        1, 0, 0, 0, 0, 0, 0, 1.f, 1);
    cudaEventRecord(evJoin, sB);

    // ---- main stream: q-proj runs concurrently with side stream ----
    gemm_mma<128,128,32,64><<<dim3(4, 128, 1), 256, SM_QO>>>(
        qinH, nullptr, nullptr, WqH, nullptr, nullptr, 1, bq,
        nullptr, qH, nullptr, 512, 512, 512, 512,
        1, 0, 0, 0, 0, 0, 0, 1.f, 0);
    cudaStreamWaitEvent(0, evJoin, 0);

    // fused attention -> ctxH
    attn_fused<<<dim3(16, 64), 256, 114688>>>(qH, kH, vtH, vtL, ctxH, ns);

    // o-proj (dual-B) -> bf16 aoB
    gemm_dual<<<dim3(4, 128), 256, SM_DU>>>(ctxH, WoH, WoL, bo, aoB);

    // residual + LN + partial mean, final reduce
    epilogue_ln<<<dim3(8, 8), 256>>>(qinH, aoB, lnw, lnb, part);
    final_reduce<<<8, 512>>>(part, out);
}

// round 15
// speedup vs baseline: 3.0281x; 1.0007x over previous
#include <cuda_runtime.h>
#include <cuda_bf16.h>
#include <cstdint>
#include <cstddef>

typedef __nv_bfloat16 bf16;

// ======================= portable PTX helpers (sm_80+) =======================
__device__ __forceinline__ uint32_t smem_u32(const void* p) {
    uint32_t a;
    asm("{ .reg .u64 t; cvta.to.shared.u64 t, %1; cvt.u32.u64 %0, t; }" : "=r"(a) : "l"(p));
    return a;
}
__device__ __forceinline__ void cp16(uint32_t dst, const void* src) {
    asm volatile("cp.async.cg.shared.global [%0], [%1], 16;" :: "r"(dst), "l"(src));
}
__device__ __forceinline__ void ldsm4(uint32_t* r, uint32_t a) {
    asm volatile("ldmatrix.sync.aligned.m8n8.x4.shared.b16 {%0,%1,%2,%3}, [%4];"
        : "=r"(r[0]), "=r"(r[1]), "=r"(r[2]), "=r"(r[3]) : "r"(a));
}
__device__ __forceinline__ void mma16816(float* c, const uint32_t* a, const uint32_t* b) {
    asm volatile(
        "mma.sync.aligned.m16n8k16.row.col.f32.bf16.bf16.f32 "
        "{%0,%1,%2,%3}, {%4,%5,%6,%7}, {%8,%9}, {%0,%1,%2,%3};"
        : "+f"(c[0]), "+f"(c[1]), "+f"(c[2]), "+f"(c[3])
        : "r"(a[0]), "r"(a[1]), "r"(a[2]), "r"(a[3]), "r"(b[0]), "r"(b[1]));
}
__device__ __forceinline__ uint32_t packbf2(float lo, float hi) {
    __nv_bfloat162 p;
    p.x = __float2bfloat16_rn(lo);
    p.y = __float2bfloat16_rn(hi);
    return *(uint32_t*)&p;
}

// ======================= constants & scratch =======================
static const int Dd = 512, Ll = 2048;

__device__ uint4 g_qinH_[1048576];        // bf16(Qin)             16 MB
__device__ uint4 g_sentHL_[2 * 131072];   // sentH, sentL
__device__ uint4 g_W_[8 * 32768];         // WqH WqL WkH WkL WvH WvL WoH WoL
__device__ uint4 g_qH_[1048576];          // bf16(q)               16 MB
__device__ uint4 g_kH_[131072];           // kH
__device__ uint4 g_vtHL_[2 * 131072];     // vtH, vtL [bh][64][256]
__device__ uint4 g_ctxH_[1048576];        // bf16(ctx)             16 MB
__device__ uint4 g_ao_[2097152];          // bf16 attn_out (16 MB used)
__device__ float g_part_[8 * 64 * 512];   // 1 MB LN partials

// ---------------------------------------------------------------------------
// Generic multi-term bf16 GEMM, BK=64 chunks, 3-stage cp.async, 2 CTAs/SM.
// ---------------------------------------------------------------------------
template<int BM, int BN, int WM, int WN>
__global__ __launch_bounds__(256, 2)
void gemm_mma(const bf16* A0, const bf16* A1, const bf16* A2,
              const bf16* B0, const bf16* B1, const bf16* B2,
              int nterms, const float* __restrict__ bias,
              float* __restrict__ Cf, bf16* __restrict__ Chi, bf16* __restrict__ Clo,
              int Ktot, int lda, int ldb, int ldc,
              int HH, long long sAb, long long sAh, long long sBb, long long sBh,
              long long sCb, long long sCh, float alpha, int vmode)
{
    constexpr int BK = 64;
    constexpr int WARPS_N = BN / WN;
    constexpr int MT = WM / 16, NT = WN / 8;
    constexpr int ASZ = BM * BK * 2, BSZ = BN * BK * 2;
    static_assert((BM / WM) * (BN / WN) == 8, "8 warps");

    extern __shared__ char dynsm[];
    const uint32_t sA0 = smem_u32(dynsm);
    const uint32_t sB0 = sA0 + 3 * ASZ;

    const int tid = threadIdx.x, warp = tid >> 5, lane = tid & 31;
    const int wm = warp / WARPS_N, wn = warp % WARPS_N;

    const bf16* Al[3] = {A0, A1, A2};
    const bf16* Bl[3] = {B0, B1, B2};

    const int z = blockIdx.z;
    const int bz = z / HH, hz = z - bz * HH;
    const long long aoff = (long long)bz * sAb + (long long)hz * sAh;
    const long long boff = (long long)bz * sBb + (long long)hz * sBh;
    const long long coff = (long long)bz * sCb + (long long)hz * sCh;

    const int m0 = blockIdx.y * BM;
    const int n0 = blockIdx.x * BN;

    const int kch = Ktot >> 6;
    const int total = nterms * kch;

    const int fr = tid >> 3, fu = tid & 7;

    float acc[MT][NT][4];
#pragma unroll
    for (int i = 0; i < MT; i++)
#pragma unroll
        for (int j = 0; j < NT; j++)
#pragma unroll
            for (int e = 0; e < 4; e++) acc[i][j][e] = 0.f;

    auto prefetch = [&](int chunk, int buf) {
        const int term = chunk / kch;
        const int k0 = (chunk - term * kch) << 6;
        const bf16* Ag = Al[term] + aoff + k0;
        const uint32_t sA = sA0 + buf * ASZ;
#pragma unroll
        for (int p = 0; p < BM / 32; p++) {
            const int r = fr + p * 32;
            cp16(sA + (uint32_t)((r * 8 + (fu ^ (r & 7))) << 4),
                 Ag + (size_t)(m0 + r) * lda + fu * 8);
        }
        const bf16* Bg = Bl[term] + boff + k0;
        const uint32_t sB = sB0 + buf * BSZ;
#pragma unroll
        for (int p = 0; p < BN / 32; p++) {
            const int r = fr + p * 32;
            cp16(sB + (uint32_t)((r * 8 + (fu ^ (r & 7))) << 4),
                 Bg + (size_t)(n0 + r) * ldb + fu * 8);
        }
        asm volatile("cp.async.commit_group;");
    };

    prefetch(0, 0);
    prefetch(1, 1);
    for (int it = 0; it < total; it++) {
        if (it + 1 < total) asm volatile("cp.async.wait_group 1;");
        else                asm volatile("cp.async.wait_group 0;");
        __syncthreads();
        if (it + 2 < total) prefetch(it + 2, (it + 2) % 3);

        const int buf = it % 3;
        const uint32_t sA = sA0 + buf * ASZ;
        const uint32_t sB = sB0 + buf * BSZ;
#pragma unroll
        for (int kk = 0; kk < 4; kk++) {
            uint32_t af[MT][4];
#pragma unroll
            for (int mt = 0; mt < MT; mt++) {
                const int r = wm * WM + mt * 16 + (lane & 15);
                const int u = (kk << 1) + (lane >> 4);
                ldsm4(af[mt], sA + (uint32_t)((r * 8 + (u ^ (r & 7))) << 4));
            }
            uint32_t bfr[NT][2];
#pragma unroll
            for (int np = 0; np < NT / 2; np++) {
                const int r = wn * WN + np * 16 + ((lane >> 4) << 3) + (lane & 7);
                const int u = (kk << 1) + ((lane >> 3) & 1);
                ldsm4(&bfr[np * 2][0], sB + (uint32_t)((r * 8 + (u ^ (r & 7))) << 4));
            }
#pragma unroll
            for (int mt = 0; mt < MT; mt++)
#pragma unroll
                for (int nt = 0; nt < NT; nt++)
                    mma16816(acc[mt][nt], af[mt], bfr[nt]);
        }
    }

    // ---------------- epilogue ----------------
#pragma unroll
    for (int mt = 0; mt < MT; mt++)
#pragma unroll
        for (int nt = 0; nt < NT; nt++) {
            const int gr0 = m0 + wm * WM + mt * 16 + (lane >> 2);
            const int gc = n0 + wn * WN + nt * 8 + ((lane & 3) << 1);
            const float b0v = bias ? bias[gc] : 0.f;
            const float b1v = bias ? bias[gc + 1] : 0.f;
#pragma unroll
            for (int h2 = 0; h2 < 2; h2++) {
                const int gr = gr0 + h2 * 8;
                const float x0 = alpha * acc[mt][nt][h2 * 2 + 0] + b0v;
                const float x1 = alpha * acc[mt][nt][h2 * 2 + 1] + b1v;
                if (!vmode) {
                    const long long idx = coff + (long long)gr * ldc + gc;
                    if (Cf) { Cf[idx] = x0; Cf[idx + 1] = x1; }
                    if (Chi) {
                        bf16 h0 = __float2bfloat16_rn(x0), h1 = __float2bfloat16_rn(x1);
                        Chi[idx] = h0; Chi[idx + 1] = h1;
                        if (Clo) {
                            Clo[idx] = __float2bfloat16_rn(x0 - __bfloat162float(h0));
                            Clo[idx + 1] = __float2bfloat16_rn(x1 - __bfloat162float(h1));
                        }
                    }
                } else {
                    const int bb = gr >> 8, jj = gr & 255;
#pragma unroll
                    for (int e = 0; e < 2; e++) {
                        const float x = e ? x1 : x0;
                        const int n = gc + e, h = n >> 6, d = n & 63;
                        const size_t off = ((size_t)(bb * 8 + h) * 64 + d) * 256 + jj;
                        bf16 hh = __float2bfloat16_rn(x);
                        Chi[off] = hh;
                        Clo[off] = __float2bfloat16_rn(x - __bfloat162float(hh));
                    }
                }
            }
        }
}

// ---------------------------------------------------------------------------
// Dual-B GEMM for o-proj (pointer-shifted for batch halves).
// ---------------------------------------------------------------------------
__global__ __launch_bounds__(256, 2)
void gemm_dual(const bf16* __restrict__ A, const bf16* __restrict__ B0,
               const bf16* __restrict__ B1, const float* __restrict__ bias,
               bf16* __restrict__ C)
{
    constexpr int STG = 49152;
    extern __shared__ char dynsm[];
    const uint32_t s0 = smem_u32(dynsm);

    const int tid = threadIdx.x, warp = tid >> 5, lane = tid & 31;
    const int wm = warp >> 1, wn = warp & 1;

    const int m0 = blockIdx.y * 128;
    const int n0 = blockIdx.x * 128;
    const int fr = tid >> 3, fu = tid & 7;

    float acc[2][8][4];
#pragma unroll
    for (int i = 0; i < 2; i++)
#pragma unroll
        for (int j = 0; j < 8; j++)
#pragma unroll
            for (int e = 0; e < 4; e++) acc[i][j][e] = 0.f;

    auto prefetch = [&](int chunk, int buf) {
        const int k0 = chunk << 6;
        const uint32_t base = s0 + buf * STG;
#pragma unroll
        for (int p = 0; p < 4; p++) {
            const int r = fr + p * 32;
            const uint32_t off = (uint32_t)((r * 8 + (fu ^ (r & 7))) << 4);
            cp16(base + off,         A  + (size_t)(m0 + r) * 512 + k0 + fu * 8);
            cp16(base + 16384 + off, B0 + (size_t)(n0 + r) * 512 + k0 + fu * 8);
            cp16(base + 32768 + off, B1 + (size_t)(n0 + r) * 512 + k0 + fu * 8);
        }
        asm volatile("cp.async.commit_group;");
    };

    prefetch(0, 0);
    for (int it = 0; it < 8; it++) {
        asm volatile("cp.async.wait_group 0;");
        __syncthreads();
        if (it + 1 < 8) prefetch(it + 1, (it + 1) & 1);

        const uint32_t base = s0 + (it & 1) * STG;
#pragma unroll
        for (int kk = 0; kk < 4; kk++) {
            uint32_t af[2][4];
#pragma unroll
            for (int mt = 0; mt < 2; mt++) {
                const int r = wm * 32 + mt * 16 + (lane & 15);
                const int u = (kk << 1) + (lane >> 4);
                ldsm4(af[mt], base + (uint32_t)((r * 8 + (u ^ (r & 7))) << 4));
            }
#pragma unroll
            for (int term = 0; term < 2; term++) {
                const uint32_t sB = base + 16384 + term * 16384;
                uint32_t bfr[8][2];
#pragma unroll
                for (int np = 0; np < 4; np++) {
                    const int r = wn * 64 + np * 16 + ((lane >> 4) << 3) + (lane & 7);
                    const int u = (kk << 1) + ((lane >> 3) & 1);
                    ldsm4(&bfr[np * 2][0], sB + (uint32_t)((r * 8 + (u ^ (r & 7))) << 4));
                }
#pragma unroll
                for (int mt = 0; mt < 2; mt++)
#pragma unroll
                    for (int nt = 0; nt < 8; nt++)
                        mma16816(acc[mt][nt], af[mt], bfr[nt]);
            }
        }
    }

#pragma unroll
    for (int mt = 0; mt < 2; mt++)
#pragma unroll
        for (int nt = 0; nt < 8; nt++) {
            const int gr0 = m0 + wm * 32 + mt * 16 + (lane >> 2);
            const int gc = n0 + wn * 64 + nt * 8 + ((lane & 3) << 1);
            const float b0v = bias[gc], b1v = bias[gc + 1];
#pragma unroll
            for (int h2 = 0; h2 < 2; h2++) {
                const int gr = gr0 + h2 * 8;
                __nv_bfloat162 o;
                o.x = __float2bfloat16_rn(acc[mt][nt][h2 * 2 + 0] + b0v);
                o.y = __float2bfloat16_rn(acc[mt][nt][h2 * 2 + 1] + b1v);
                *(__nv_bfloat162*)(C + (size_t)gr * 512 + gc) = o;
            }
        }
}

// ---------------------------------------------------------------------------
// Fused attention, FA2 register path; bh0 = batch-head offset for halves.
// ---------------------------------------------------------------------------
__global__ __launch_bounds__(256, 1)
void attn_fused(const bf16* __restrict__ qHp, const bf16* __restrict__ kHp,
                const bf16* __restrict__ vtHp, const bf16* __restrict__ vtLp,
                bf16* __restrict__ ctxp, const int* __restrict__ nsp, int bh0)
{
    extern __shared__ char dsm[];
    const uint32_t uQ  = smem_u32(dsm);
    const uint32_t uKH = uQ + 16384;
    const uint32_t uVH = uQ + 49152;
    const uint32_t uVL = uQ + 81920;

    const int tid = threadIdx.x, warp = tid >> 5, lane = tid & 31;
    const int bh = blockIdx.y + bh0, b = bh >> 3, h = bh & 7;
    const int ns = nsp[b];
    const int q0 = blockIdx.x * 128;

    // commit 1: Q + KH (48 KB)
    {
        const bf16* gQ = qHp + ((size_t)b * 2048 + q0) * 512 + h * 64;
#pragma unroll
        for (int t = 0; t < 4; t++) {
            int id = tid + (t << 8);
            int r = id >> 3, u = id & 7;
            cp16(uQ + (uint32_t)((r * 8 + (u ^ (r & 7))) << 4), gQ + (size_t)r * 512 + u * 8);
        }
        const bf16* gKH = kHp + ((size_t)b * 256) * 512 + h * 64;
#pragma unroll
        for (int t = 0; t < 8; t++) {
            int id = tid + (t << 8);
            int r = id >> 3, u = id & 7;
            cp16(uKH + (uint32_t)((r * 8 + (u ^ (r & 7))) << 4), gKH + (size_t)r * 512 + u * 8);
        }
        asm volatile("cp.async.commit_group;");
    }
    // commit 2: VH + VL (64 KB)
    {
        const bf16* gVH = vtHp + (size_t)bh * 16384;
        const bf16* gVL = vtLp + (size_t)bh * 16384;
#pragma unroll
        for (int t = 0; t < 8; t++) {
            int id = tid + (t << 8);
            int r = id >> 5, u = id & 31;
            uint32_t off = (uint32_t)((r * 32 + (u ^ ((r & 7) << 2))) << 4);
            cp16(uVH + off, gVH + (size_t)r * 256 + u * 8);
            cp16(uVL + off, gVL + (size_t)r * 256 + u * 8);
        }
        asm volatile("cp.async.commit_group;");
    }
    asm volatile("cp.async.wait_group 1;");
    __syncthreads();

    float acc[32][4];
#pragma unroll
    for (int j = 0; j < 32; j++)
#pragma unroll
        for (int e = 0; e < 4; e++) acc[j][e] = 0.f;

#pragma unroll
    for (int kk = 0; kk < 4; kk++) {
        uint32_t af[4];
        {
            int r = warp * 16 + (lane & 15);
            int u = kk * 2 + (lane >> 4);
            ldsm4(af, uQ + (uint32_t)((r * 8 + (u ^ (r & 7))) << 4));
        }
#pragma unroll
        for (int nc = 0; nc < 4; nc++) {
            uint32_t bfr[8][2];
#pragma unroll
            for (int np = 0; np < 4; np++) {
                int r = nc * 64 + np * 16 + ((lane >> 4) << 3) + (lane & 7);
                int u = kk * 2 + ((lane >> 3) & 1);
                ldsm4(&bfr[np * 2][0], uKH + (uint32_t)((r * 8 + (u ^ (r & 7))) << 4));
            }
#pragma unroll
            for (int nt = 0; nt < 8; nt++)
                mma16816(acc[nc * 8 + nt], af, bfr[nt]);
        }
    }

    float mx[2] = {-3.0e38f, -3.0e38f};
#pragma unroll
    for (int nt = 0; nt < 32; nt++) {
        const int cb = nt * 8 + ((lane & 3) << 1);
#pragma unroll
        for (int hf = 0; hf < 2; hf++)
#pragma unroll
            for (int e = 0; e < 2; e++) {
                float x = (cb + e < ns) ? 0.125f * acc[nt][hf * 2 + e] : -3.0e38f;
                acc[nt][hf * 2 + e] = x;
                mx[hf] = fmaxf(mx[hf], x);
            }
    }
#pragma unroll
    for (int hf = 0; hf < 2; hf++) {
        mx[hf] = fmaxf(mx[hf], __shfl_xor_sync(0xffffffffu, mx[hf], 1));
        mx[hf] = fmaxf(mx[hf], __shfl_xor_sync(0xffffffffu, mx[hf], 2));
    }
    float sm[2] = {0.f, 0.f};
#pragma unroll
    for (int nt = 0; nt < 32; nt++)
#pragma unroll
        for (int hf = 0; hf < 2; hf++)
#pragma unroll
            for (int e = 0; e < 2; e++) {
                float p = __expf(acc[nt][hf * 2 + e] - mx[hf]);
                acc[nt][hf * 2 + e] = p;
                sm[hf] += p;
            }
#pragma unroll
    for (int hf = 0; hf < 2; hf++) {
        sm[hf] += __shfl_xor_sync(0xffffffffu, sm[hf], 1);
        sm[hf] += __shfl_xor_sync(0xffffffffu, sm[hf], 2);
    }
    const float inv0 = 1.f / sm[0], inv1 = 1.f / sm[1];

    uint32_t pa[64];
#pragma unroll
    for (int kt = 0; kt < 16; kt++) {
        const int t0 = 2 * kt, t1 = 2 * kt + 1;
        pa[kt * 4 + 0] = packbf2(acc[t0][0] * inv0, acc[t0][1] * inv0);
        pa[kt * 4 + 1] = packbf2(acc[t0][2] * inv1, acc[t0][3] * inv1);
        pa[kt * 4 + 2] = packbf2(acc[t1][0] * inv0, acc[t1][1] * inv0);
        pa[kt * 4 + 3] = packbf2(acc[t1][2] * inv1, acc[t1][3] * inv1);
    }

    asm volatile("cp.async.wait_group 0;");
    __syncthreads();

    float cacc[8][4];
#pragma unroll
    for (int j = 0; j < 8; j++)
#pragma unroll
        for (int e = 0; e < 4; e++) cacc[j][e] = 0.f;

#pragma unroll
    for (int term = 0; term < 2; term++) {
        const uint32_t vb = term ? uVL : uVH;
#pragma unroll
        for (int kt = 0; kt < 16; kt++) {
            uint32_t bf2[8][2];
#pragma unroll
            for (int np = 0; np < 4; np++) {
                int r = np * 16 + ((lane >> 4) << 3) + (lane & 7);
                int u = kt * 2 + ((lane >> 3) & 1);
                ldsm4(&bf2[np * 2][0], vb + (uint32_t)((r * 32 + (u ^ ((r & 7) << 2))) << 4));
            }
#pragma unroll
            for (int nt = 0; nt < 8; nt++)
                mma16816(cacc[nt], &pa[kt * 4], bf2[nt]);
        }
    }

#pragma unroll
    for (int nt = 0; nt < 8; nt++)
#pragma unroll
        for (int hf = 0; hf < 2; hf++) {
            const int qrow = q0 + warp * 16 + (lane >> 2) + hf * 8;
            const int d = nt * 8 + ((lane & 3) << 1);
            __nv_bfloat162 o;
            o.x = __float2bfloat16_rn(cacc[nt][hf * 2 + 0]);
            o.y = __float2bfloat16_rn(cacc[nt][hf * 2 + 1]);
            *(__nv_bfloat162*)(ctxp + ((size_t)b * 2048 + qrow) * 512 + h * 64 + d) = o;
        }
}

// ======================= small kernels =======================
__global__ void split_kernel(const float* __restrict__ in, bf16* __restrict__ hi,
                             bf16* __restrict__ lo, int n)
{
    int i = blockIdx.x * blockDim.x + threadIdx.x;
    if (i < n) {
        float x = in[i];
        bf16 h = __float2bfloat16_rn(x);
        hi[i] = h;
        if (lo) lo[i] = __float2bfloat16_rn(x - __bfloat162float(h));
    }
}

__global__ void split_weights(const float* __restrict__ w0, const float* __restrict__ w1,
                              const float* __restrict__ w2, const float* __restrict__ w3,
                              bf16* __restrict__ base)
{
    int y = blockIdx.y;
    const float* src = (y == 0) ? w0 : (y == 1) ? w1 : (y == 2) ? w2 : w3;
    bf16* hi = base + (size_t)y * 2 * 262144;
    bf16* lo = hi + 262144;
    int i = blockIdx.x * blockDim.x + threadIdx.x;
    if (i < 262144) {
        float x = src[i];
        bf16 h = __float2bfloat16_rn(x);
        hi[i] = h;
        lo[i] = __float2bfloat16_rn(x - __bfloat162float(h));
    }
}

// Barrier-free residual+LN+partial-mean (pointer-shifted per half).
__global__ __launch_bounds__(256) void epilogue_ln(
    const bf16* __restrict__ qinB, const bf16* __restrict__ aoB,
    const float* __restrict__ lnw, const float* __restrict__ lnb,
    float* __restrict__ part)
{
    const int b = blockIdx.y;
    const int warp = threadIdx.x >> 5, lane = threadIdx.x & 31;
    const int wg = blockIdx.x * 8 + warp;

    float lw[16], lb_[16];
#pragma unroll
    for (int i = 0; i < 16; i++) { lw[i] = lnw[lane * 16 + i]; lb_[i] = lnb[lane * 16 + i]; }

    float acc[16];
#pragma unroll
    for (int i = 0; i < 16; i++) acc[i] = 0.f;

    for (int rr = 0; rr < 32; rr++) {
        const size_t rowo = ((size_t)b * 2048 + wg * 32 + rr) * 512 + lane * 16;
        float x[16];
        const uint4 qa = *(const uint4*)(qinB + rowo);
        const uint4 qb = *(const uint4*)(qinB + rowo + 8);
        const uint4 aa = *(const uint4*)(aoB + rowo);
        const uint4 ab = *(const uint4*)(aoB + rowo + 8);
        const bf16* q8a = (const bf16*)&qa; const bf16* q8b = (const bf16*)&qb;
        const bf16* a8a = (const bf16*)&aa; const bf16* a8b = (const bf16*)&ab;
#pragma unroll
        for (int i = 0; i < 8; i++) {
            x[i]     = __bfloat162float(q8a[i]) + __bfloat162float(a8a[i]);
            x[i + 8] = __bfloat162float(q8b[i]) + __bfloat162float(a8b[i]);
        }
        float s = 0.f, s2 = 0.f;
#pragma unroll
        for (int i = 0; i < 16; i++) { s += x[i]; s2 += x[i] * x[i]; }
#pragma unroll
        for (int o = 16; o; o >>= 1) {
            s  += __shfl_xor_sync(0xffffffffu, s, o);
            s2 += __shfl_xor_sync(0xffffffffu, s2, o);
        }
        const float mu = s * (1.f / 512.f);
        const float var = s2 * (1.f / 512.f) - mu * mu;
        const float rs = rsqrtf(var + 1e-5f);
#pragma unroll
        for (int i = 0; i < 16; i++) acc[i] += (x[i] - mu) * rs * lw[i] + lb_[i];
    }
    float* pp = part + ((size_t)b * 64 + wg) * 512 + lane * 16;
#pragma unroll
    for (int i = 0; i < 16; i++) pp[i] = acc[i];
}

__global__ void final_reduce(const float* __restrict__ part, float* __restrict__ out)
{
    int b = blockIdx.x, col = threadIdx.x;
    float s = 0.f;
#pragma unroll
    for (int c = 0; c < 64; c++) s += part[((size_t)b * 64 + c) * Dd + col];
    out[b * Dd + col] = s * (1.f / 2048.f);
}

// ======================= driver =======================
extern "C" void kernel_launch(void* const* d_in, const int* in_sizes, int n_in,
                              void* d_out, int out_size)
{
    (void)in_sizes; (void)n_in; (void)out_size;
    const float* qin  = (const float*)d_in[0];
    const float* sent = (const float*)d_in[1];
    const int*   ns   = (const int*)  d_in[2];
    const float* Wq   = (const float*)d_in[3];
    const float* bq   = (const float*)d_in[4];
    const float* Wk   = (const float*)d_in[5];
    const float* bk   = (const float*)d_in[6];
    const float* Wv   = (const float*)d_in[7];
    const float* bvv  = (const float*)d_in[8];
    const float* Wo   = (const float*)d_in[9];
    const float* bo   = (const float*)d_in[10];
    const float* lnw  = (const float*)d_in[11];
    const float* lnb  = (const float*)d_in[12];
    float* out = (float*)d_out;

    void* p_;
    cudaGetSymbolAddress(&p_, g_qinH_);   bf16* qinH = (bf16*)p_;
    cudaGetSymbolAddress(&p_, g_sentHL_); bf16* sentH = (bf16*)p_; bf16* sentL = sentH + 1048576;
    cudaGetSymbolAddress(&p_, g_W_);      bf16* W = (bf16*)p_;
    bf16 *WqH = W,            *WkH = W + 2*262144;
    bf16 *WvH = W + 4*262144, *WvL = W + 5*262144, *WoH = W + 6*262144, *WoL = W + 7*262144;
    cudaGetSymbolAddress(&p_, g_qH_);    bf16* qH  = (bf16*)p_;
    cudaGetSymbolAddress(&p_, g_kH_);    bf16* kH  = (bf16*)p_;
    cudaGetSymbolAddress(&p_, g_vtHL_);  bf16* vtH = (bf16*)p_;  bf16* vtL = vtH + 1048576;
    cudaGetSymbolAddress(&p_, g_ctxH_);  bf16* ctxH = (bf16*)p_;
    cudaGetSymbolAddress(&p_, g_ao_);    bf16* aoB = (bf16*)p_;
    cudaGetSymbolAddress(&p_, g_part_);  float* part = (float*)p_;

    constexpr int SM_QO = 3 * (128 * 128 + 128 * 128);  // 98304
    constexpr int SM_KV = 3 * (64 * 128 + 128 * 128);   // 73728
    constexpr int SM_DU = 2 * 49152;                    // 98304
    const size_t HALF = (size_t)8192 * 512;             // 4 batches of rows

    static cudaStream_t sB = nullptr;
    static cudaEvent_t evRoot = nullptr, evW = nullptr, evQin = nullptr,
                       evKV = nullptr, evE2 = nullptr;
    if (!sB) {
        cudaFuncSetAttribute((const void*)gemm_mma<128,128,32,64>,
                             cudaFuncAttributeMaxDynamicSharedMemorySize, SM_QO);
        cudaFuncSetAttribute((const void*)gemm_mma<64,128,32,32>,
                             cudaFuncAttributeMaxDynamicSharedMemorySize, SM_KV);
        cudaFuncSetAttribute((const void*)gemm_dual,
                             cudaFuncAttributeMaxDynamicSharedMemorySize, SM_DU);
        cudaFuncSetAttribute((const void*)attn_fused,
                             cudaFuncAttributeMaxDynamicSharedMemorySize, 114688);
        cudaStreamCreateWithFlags(&sB, cudaStreamNonBlocking);
        cudaEventCreateWithFlags(&evRoot, cudaEventDisableTiming);
        cudaEventCreateWithFlags(&evW,   cudaEventDisableTiming);
        cudaEventCreateWithFlags(&evQin, cudaEventDisableTiming);
        cudaEventCreateWithFlags(&evKV,  cudaEventDisableTiming);
        cudaEventCreateWithFlags(&evE2,  cudaEventDisableTiming);
    }

    // fork root: side stream joins capture via this event FIRST (R12-proven shape)
    cudaEventRecord(evRoot, 0);
    cudaStreamWaitEvent(sB, evRoot, 0);

    // sB: qin split -> (evQin)
    split_kernel<<<32768, 256, 0, sB>>>(qin, qinH, nullptr, 8388608);
    cudaEventRecord(evQin, sB);

    // s0: weight splits -> (evW) -> sent split -> k-proj -> v-proj -> (evKV)
    split_weights<<<dim3(1024, 4), 256>>>(Wq, Wk, Wv, Wo, W);
    cudaEventRecord(evW, 0);
    split_kernel<<<4096, 256>>>(sent, sentH, sentL, 1048576);
    gemm_mma<64,128,32,32><<<dim3(4, 32, 1), 256, SM_KV>>>(
        sentH, nullptr, nullptr, WkH, nullptr, nullptr, 1, bk,
        nullptr, kH, nullptr, 512, 512, 512, 512,
        1, 0, 0, 0, 0, 0, 0, 1.f, 0);
    gemm_mma<64,128,32,32><<<dim3(4, 32, 1), 256, SM_KV>>>(
        sentH, sentH, sentL, WvH, WvL, WvH, 3, bvv,
        nullptr, vtH, vtL, 512, 512, 512, 512,
        1, 0, 0, 0, 0, 0, 0, 1.f, 1);
    cudaEventRecord(evKV, 0);

    // sB: q-proj half2 (after its own qin split; needs weights)
    cudaStreamWaitEvent(sB, evW, 0);
    gemm_mma<128,128,32,64><<<dim3(4, 64, 1), 256, SM_QO, sB>>>(
        qinH + HALF, nullptr, nullptr, WqH, nullptr, nullptr, 1, bq,
        nullptr, qH + HALF, nullptr, 512, 512, 512, 512,
        1, 0, 0, 0, 0, 0, 0, 1.f, 0);

    // s0: q-proj half1 (needs qin split from sB)
    cudaStreamWaitEvent(0, evQin, 0);
    gemm_mma<128,128,32,64><<<dim3(4, 64, 1), 256, SM_QO>>>(
        qinH, nullptr, nullptr, WqH, nullptr, nullptr, 1, bq,
        nullptr, qH, nullptr, 512, 512, 512, 512,
        1, 0, 0, 0, 0, 0, 0, 1.f, 0);

    // s0: attn1 -> oproj1 -> ln1   (KV already ordered on s0)
    attn_fused<<<dim3(16, 32), 256, 114688>>>(qH, kH, vtH, vtL, ctxH, ns, 0);
    gemm_dual<<<dim3(4, 64), 256, SM_DU>>>(ctxH, WoH, WoL, bo, aoB);
    epilogue_ln<<<dim3(8, 4), 256>>>(qinH, aoB, lnw, lnb, part);

    // sB: attn2 -> oproj2 -> ln2 -> (evE2)   (needs KV from s0)
    cudaStreamWaitEvent(sB, evKV, 0);
    attn_fused<<<dim3(16, 32), 256, 114688, sB>>>(qH, kH, vtH, vtL, ctxH, ns, 32);
    gemm_dual<<<dim3(4, 64), 256, SM_DU, sB>>>(ctxH + HALF, WoH, WoL, bo, aoB + HALF);
    epilogue_ln<<<dim3(8, 4), 256, 0, sB>>>(qinH + HALF, aoB + HALF, lnw, lnb,
                                            part + (size_t)4 * 64 * 512);
    cudaEventRecord(evE2, sB);

    // s0: join + final reduce
    cudaStreamWaitEvent(0, evE2, 0);
    final_reduce<<<8, 512>>>(part, out);
}

// round 16
// speedup vs baseline: 3.2361x; 1.0687x over previous
#include <cuda_runtime.h>
#include <cuda_bf16.h>
#include <cstdint>
#include <cstddef>

typedef __nv_bfloat16 bf16;

// ======================= portable PTX helpers (sm_80+) =======================
__device__ __forceinline__ uint32_t smem_u32(const void* p) {
    uint32_t a;
    asm("{ .reg .u64 t; cvta.to.shared.u64 t, %1; cvt.u32.u64 %0, t; }" : "=r"(a) : "l"(p));
    return a;
}
__device__ __forceinline__ void cp16(uint32_t dst, const void* src) {
    asm volatile("cp.async.cg.shared.global [%0], [%1], 16;" :: "r"(dst), "l"(src));
}
__device__ __forceinline__ void ldsm4(uint32_t* r, uint32_t a) {
    asm volatile("ldmatrix.sync.aligned.m8n8.x4.shared.b16 {%0,%1,%2,%3}, [%4];"
        : "=r"(r[0]), "=r"(r[1]), "=r"(r[2]), "=r"(r[3]) : "r"(a));
}
__device__ __forceinline__ void mma16816(float* c, const uint32_t* a, const uint32_t* b) {
    asm volatile(
        "mma.sync.aligned.m16n8k16.row.col.f32.bf16.bf16.f32 "
        "{%0,%1,%2,%3}, {%4,%5,%6,%7}, {%8,%9}, {%0,%1,%2,%3};"
        : "+f"(c[0]), "+f"(c[1]), "+f"(c[2]), "+f"(c[3])
        : "r"(a[0]), "r"(a[1]), "r"(a[2]), "r"(a[3]), "r"(b[0]), "r"(b[1]));
}
__device__ __forceinline__ uint32_t packbf2(float lo, float hi) {
    __nv_bfloat162 p;
    p.x = __float2bfloat16_rn(lo);
    p.y = __float2bfloat16_rn(hi);
    return *(uint32_t*)&p;
}

// ======================= constants & scratch =======================
static const int Dd = 512, Ll = 2048;

__device__ uint4 g_qinH_[1048576];        // bf16(Qin)             16 MB
__device__ uint4 g_sentHL_[2 * 131072];   // sentH, sentL
__device__ uint4 g_W_[8 * 32768];         // WqH WqL WkH WkL WvH WvL WoH WoL
__device__ uint4 g_qH_[1048576];          // bf16(q)               16 MB
__device__ uint4 g_kH_[131072];           // kH
__device__ uint4 g_vtHL_[2 * 131072];     // vtH, vtL [bh][64][256]
__device__ uint4 g_ctxH_[1048576];        // bf16(ctx)             16 MB
__device__ uint4 g_x_[1048576];           // bf16 x = qin + attn_out  16 MB
__device__ float g_part_[8 * 64 * 512];   // 1 MB LN partials

// ---------------------------------------------------------------------------
// Generic multi-term bf16 GEMM, BK=64 chunks, 3-stage cp.async, 2 CTAs/SM.
// ---------------------------------------------------------------------------
template<int BM, int BN, int WM, int WN>
__global__ __launch_bounds__(256, 2)
void gemm_mma(const bf16* A0, const bf16* A1, const bf16* A2,
              const bf16* B0, const bf16* B1, const bf16* B2,
              int nterms, const float* __restrict__ bias,
              float* __restrict__ Cf, bf16* __restrict__ Chi, bf16* __restrict__ Clo,
              int Ktot, int lda, int ldb, int ldc,
              int HH, long long sAb, long long sAh, long long sBb, long long sBh,
              long long sCb, long long sCh, float alpha, int vmode)
{
    constexpr int BK = 64;
    constexpr int WARPS_N = BN / WN;
    constexpr int MT = WM / 16, NT = WN / 8;
    constexpr int ASZ = BM * BK * 2, BSZ = BN * BK * 2;
    static_assert((BM / WM) * (BN / WN) == 8, "8 warps");

    extern __shared__ char dynsm[];
    const uint32_t sA0 = smem_u32(dynsm);
    const uint32_t sB0 = sA0 + 3 * ASZ;

    const int tid = threadIdx.x, warp = tid >> 5, lane = tid & 31;
    const int wm = warp / WARPS_N, wn = warp % WARPS_N;

    const bf16* Al[3] = {A0, A1, A2};
    const bf16* Bl[3] = {B0, B1, B2};

    const int z = blockIdx.z;
    const int bz = z / HH, hz = z - bz * HH;
    const long long aoff = (long long)bz * sAb + (long long)hz * sAh;
    const long long boff = (long long)bz * sBb + (long long)hz * sBh;
    const long long coff = (long long)bz * sCb + (long long)hz * sCh;

    const int m0 = blockIdx.y * BM;
    const int n0 = blockIdx.x * BN;

    const int kch = Ktot >> 6;
    const int total = nterms * kch;

    const int fr = tid >> 3, fu = tid & 7;

    float acc[MT][NT][4];
#pragma unroll
    for (int i = 0; i < MT; i++)
#pragma unroll
        for (int j = 0; j < NT; j++)
#pragma unroll
            for (int e = 0; e < 4; e++) acc[i][j][e] = 0.f;

    auto prefetch = [&](int chunk, int buf) {
        const int term = chunk / kch;
        const int k0 = (chunk - term * kch) << 6;
        const bf16* Ag = Al[term] + aoff + k0;
        const uint32_t sA = sA0 + buf * ASZ;
#pragma unroll
        for (int p = 0; p < BM / 32; p++) {
            const int r = fr + p * 32;
            cp16(sA + (uint32_t)((r * 8 + (fu ^ (r & 7))) << 4),
                 Ag + (size_t)(m0 + r) * lda + fu * 8);
        }
        const bf16* Bg = Bl[term] + boff + k0;
        const uint32_t sB = sB0 + buf * BSZ;
#pragma unroll
        for (int p = 0; p < BN / 32; p++) {
            const int r = fr + p * 32;
            cp16(sB + (uint32_t)((r * 8 + (fu ^ (r & 7))) << 4),
                 Bg + (size_t)(n0 + r) * ldb + fu * 8);
        }
        asm volatile("cp.async.commit_group;");
    };

    prefetch(0, 0);
    prefetch(1, 1);
    for (int it = 0; it < total; it++) {
        if (it + 1 < total) asm volatile("cp.async.wait_group 1;");
        else                asm volatile("cp.async.wait_group 0;");
        __syncthreads();
        if (it + 2 < total) prefetch(it + 2, (it + 2) % 3);

        const int buf = it % 3;
        const uint32_t sA = sA0 + buf * ASZ;
        const uint32_t sB = sB0 + buf * BSZ;
#pragma unroll
        for (int kk = 0; kk < 4; kk++) {
            uint32_t af[MT][4];
#pragma unroll
            for (int mt = 0; mt < MT; mt++) {
                const int r = wm * WM + mt * 16 + (lane & 15);
                const int u = (kk << 1) + (lane >> 4);
                ldsm4(af[mt], sA + (uint32_t)((r * 8 + (u ^ (r & 7))) << 4));
            }
            uint32_t bfr[NT][2];
#pragma unroll
            for (int np = 0; np < NT / 2; np++) {
                const int r = wn * WN + np * 16 + ((lane >> 4) << 3) + (lane & 7);
                const int u = (kk << 1) + ((lane >> 3) & 1);
                ldsm4(&bfr[np * 2][0], sB + (uint32_t)((r * 8 + (u ^ (r & 7))) << 4));
            }
#pragma unroll
            for (int mt = 0; mt < MT; mt++)
#pragma unroll
                for (int nt = 0; nt < NT; nt++)
                    mma16816(acc[mt][nt], af[mt], bfr[nt]);
        }
    }

    // ---------------- epilogue ----------------
#pragma unroll
    for (int mt = 0; mt < MT; mt++)
#pragma unroll
        for (int nt = 0; nt < NT; nt++) {
            const int gr0 = m0 + wm * WM + mt * 16 + (lane >> 2);
            const int gc = n0 + wn * WN + nt * 8 + ((lane & 3) << 1);
            const float b0v = bias ? bias[gc] : 0.f;
            const float b1v = bias ? bias[gc + 1] : 0.f;
#pragma unroll
            for (int h2 = 0; h2 < 2; h2++) {
                const int gr = gr0 + h2 * 8;
                const float x0 = alpha * acc[mt][nt][h2 * 2 + 0] + b0v;
                const float x1 = alpha * acc[mt][nt][h2 * 2 + 1] + b1v;
                if (!vmode) {
                    const long long idx = coff + (long long)gr * ldc + gc;
                    if (Cf) { Cf[idx] = x0; Cf[idx + 1] = x1; }
                    if (Chi) {
                        bf16 h0 = __float2bfloat16_rn(x0), h1 = __float2bfloat16_rn(x1);
                        Chi[idx] = h0; Chi[idx + 1] = h1;
                        if (Clo) {
                            Clo[idx] = __float2bfloat16_rn(x0 - __bfloat162float(h0));
                            Clo[idx + 1] = __float2bfloat16_rn(x1 - __bfloat162float(h1));
                        }
                    }
                } else {
                    const int bb = gr >> 8, jj = gr & 255;
#pragma unroll
                    for (int e = 0; e < 2; e++) {
                        const float x = e ? x1 : x0;
                        const int n = gc + e, h = n >> 6, d = n & 63;
                        const size_t off = ((size_t)(bb * 8 + h) * 64 + d) * 256 + jj;
                        bf16 hh = __float2bfloat16_rn(x);
                        Chi[off] = hh;
                        Clo[off] = __float2bfloat16_rn(x - __bfloat162float(hh));
                    }
                }
            }
        }
}

// ---------------------------------------------------------------------------
// Dual-B GEMM for o-proj with fused residual: X = A@B0^T + A@B1^T + bias + Qin
// ---------------------------------------------------------------------------
__global__ __launch_bounds__(256, 2)
void gemm_dual(const bf16* __restrict__ A, const bf16* __restrict__ B0,
               const bf16* __restrict__ B1, const float* __restrict__ bias,
               const bf16* __restrict__ Qr, bf16* __restrict__ C)
{
    constexpr int STG = 49152;
    extern __shared__ char dynsm[];
    const uint32_t s0 = smem_u32(dynsm);

    const int tid = threadIdx.x, warp = tid >> 5, lane = tid & 31;
    const int wm = warp >> 1, wn = warp & 1;

    const int m0 = blockIdx.y * 128;
    const int n0 = blockIdx.x * 128;
    const int fr = tid >> 3, fu = tid & 7;

    float acc[2][8][4];
#pragma unroll
    for (int i = 0; i < 2; i++)
#pragma unroll
        for (int j = 0; j < 8; j++)
#pragma unroll
            for (int e = 0; e < 4; e++) acc[i][j][e] = 0.f;

    auto prefetch = [&](int chunk, int buf) {
        const int k0 = chunk << 6;
        const uint32_t base = s0 + buf * STG;
#pragma unroll
        for (int p = 0; p < 4; p++) {
            const int r = fr + p * 32;
            const uint32_t off = (uint32_t)((r * 8 + (fu ^ (r & 7))) << 4);
            cp16(base + off,         A  + (size_t)(m0 + r) * 512 + k0 + fu * 8);
            cp16(base + 16384 + off, B0 + (size_t)(n0 + r) * 512 + k0 + fu * 8);
            cp16(base + 32768 + off, B1 + (size_t)(n0 + r) * 512 + k0 + fu * 8);
        }
        asm volatile("cp.async.commit_group;");
    };

    prefetch(0, 0);
    for (int it = 0; it < 8; it++) {
        asm volatile("cp.async.wait_group 0;");
        __syncthreads();
        if (it + 1 < 8) prefetch(it + 1, (it + 1) & 1);

        const uint32_t base = s0 + (it & 1) * STG;
#pragma unroll
        for (int kk = 0; kk < 4; kk++) {
            uint32_t af[2][4];
#pragma unroll
            for (int mt = 0; mt < 2; mt++) {
                const int r = wm * 32 + mt * 16 + (lane & 15);
                const int u = (kk << 1) + (lane >> 4);
                ldsm4(af[mt], base + (uint32_t)((r * 8 + (u ^ (r & 7))) << 4));
            }
#pragma unroll
            for (int term = 0; term < 2; term++) {
                const uint32_t sB = base + 16384 + term * 16384;
                uint32_t bfr[8][2];
#pragma unroll
                for (int np = 0; np < 4; np++) {
                    const int r = wn * 64 + np * 16 + ((lane >> 4) << 3) + (lane & 7);
                    const int u = (kk << 1) + ((lane >> 3) & 1);
                    ldsm4(&bfr[np * 2][0], sB + (uint32_t)((r * 8 + (u ^ (r & 7))) << 4));
                }
#pragma unroll
                for (int mt = 0; mt < 2; mt++)
#pragma unroll
                    for (int nt = 0; nt < 8; nt++)
                        mma16816(acc[mt][nt], af[mt], bfr[nt]);
            }
        }
    }

    // epilogue: bias + residual(Qin) + bf16 store
#pragma unroll
    for (int mt = 0; mt < 2; mt++)
#pragma unroll
        for (int nt = 0; nt < 8; nt++) {
            const int gr0 = m0 + wm * 32 + mt * 16 + (lane >> 2);
            const int gc = n0 + wn * 64 + nt * 8 + ((lane & 3) << 1);
            const float b0v = bias[gc], b1v = bias[gc + 1];
#pragma unroll
            for (int h2 = 0; h2 < 2; h2++) {
                const int gr = gr0 + h2 * 8;
                const __nv_bfloat162 qp = *(const __nv_bfloat162*)(Qr + (size_t)gr * 512 + gc);
                __nv_bfloat162 o;
                o.x = __float2bfloat16_rn(acc[mt][nt][h2 * 2 + 0] + b0v + __bfloat162float(qp.x));
                o.y = __float2bfloat16_rn(acc[mt][nt][h2 * 2 + 1] + b1v + __bfloat162float(qp.y));
                *(__nv_bfloat162*)(C + (size_t)gr * 512 + gc) = o;
            }
        }
}

// ---------------------------------------------------------------------------
// Fused attention, FA2 register path; bh0 = batch-head offset for halves.
// ---------------------------------------------------------------------------
__global__ __launch_bounds__(256, 1)
void attn_fused(const bf16* __restrict__ qHp, const bf16* __restrict__ kHp,
                const bf16* __restrict__ vtHp, const bf16* __restrict__ vtLp,
                bf16* __restrict__ ctxp, const int* __restrict__ nsp, int bh0)
{
    extern __shared__ char dsm[];
    const uint32_t uQ  = smem_u32(dsm);
    const uint32_t uKH = uQ + 16384;
    const uint32_t uVH = uQ + 49152;
    const uint32_t uVL = uQ + 81920;

    const int tid = threadIdx.x, warp = tid >> 5, lane = tid & 31;
    const int bh = blockIdx.y + bh0, b = bh >> 3, h = bh & 7;
    const int ns = nsp[b];
    const int q0 = blockIdx.x * 128;

    // commit 1: Q + KH (48 KB)
    {
        const bf16* gQ = qHp + ((size_t)b * 2048 + q0) * 512 + h * 64;
#pragma unroll
        for (int t = 0; t < 4; t++) {
            int id = tid + (t << 8);
            int r = id >> 3, u = id & 7;
            cp16(uQ + (uint32_t)((r * 8 + (u ^ (r & 7))) << 4), gQ + (size_t)r * 512 + u * 8);
        }
        const bf16* gKH = kHp + ((size_t)b * 256) * 512 + h * 64;
#pragma unroll
        for (int t = 0; t < 8; t++) {
            int id = tid + (t << 8);
            int r = id >> 3, u = id & 7;
            cp16(uKH + (uint32_t)((r * 8 + (u ^ (r & 7))) << 4), gKH + (size_t)r * 512 + u * 8);
        }
        asm volatile("cp.async.commit_group;");
    }
    // commit 2: VH + VL (64 KB)
    {
        const bf16* gVH = vtHp + (size_t)bh * 16384;
        const bf16* gVL = vtLp + (size_t)bh * 16384;
#pragma unroll
        for (int t = 0; t < 8; t++) {
            int id = tid + (t << 8);
            int r = id >> 5, u = id & 31;
            uint32_t off = (uint32_t)((r * 32 + (u ^ ((r & 7) << 2))) << 4);
            cp16(uVH + off, gVH + (size_t)r * 256 + u * 8);
            cp16(uVL + off, gVL + (size_t)r * 256 + u * 8);
        }
        asm volatile("cp.async.commit_group;");
    }
    asm volatile("cp.async.wait_group 1;");
    __syncthreads();

    float acc[32][4];
#pragma unroll
    for (int j = 0; j < 32; j++)
#pragma unroll
        for (int e = 0; e < 4; e++) acc[j][e] = 0.f;

#pragma unroll
    for (int kk = 0; kk < 4; kk++) {
        uint32_t af[4];
        {
            int r = warp * 16 + (lane & 15);
            int u = kk * 2 + (lane >> 4);
            ldsm4(af, uQ + (uint32_t)((r * 8 + (u ^ (r & 7))) << 4));
        }
#pragma unroll
        for (int nc = 0; nc < 4; nc++) {
            uint32_t bfr[8][2];
#pragma unroll
            for (int np = 0; np < 4; np++) {
                int r = nc * 64 + np * 16 + ((lane >> 4) << 3) + (lane & 7);
                int u = kk * 2 + ((lane >> 3) & 1);
                ldsm4(&bfr[np * 2][0], uKH + (uint32_t)((r * 8 + (u ^ (r & 7))) << 4));
            }
#pragma unroll
            for (int nt = 0; nt < 8; nt++)
                mma16816(acc[nc * 8 + nt], af, bfr[nt]);
        }
    }

    float mx[2] = {-3.0e38f, -3.0e38f};
#pragma unroll
    for (int nt = 0; nt < 32; nt++) {
        const int cb = nt * 8 + ((lane & 3) << 1);
#pragma unroll
        for (int hf = 0; hf < 2; hf++)
#pragma unroll
            for (int e = 0; e < 2; e++) {
                float x = (cb + e < ns) ? 0.125f * acc[nt][hf * 2 + e] : -3.0e38f;
                acc[nt][hf * 2 + e] = x;
                mx[hf] = fmaxf(mx[hf], x);
            }
    }
#pragma unroll
    for (int hf = 0; hf < 2; hf++) {
        mx[hf] = fmaxf(mx[hf], __shfl_xor_sync(0xffffffffu, mx[hf], 1));
        mx[hf] = fmaxf(mx[hf], __shfl_xor_sync(0xffffffffu, mx[hf], 2));
    }
    float sm[2] = {0.f, 0.f};
#pragma unroll
    for (int nt = 0; nt < 32; nt++)
#pragma unroll
        for (int hf = 0; hf < 2; hf++)
#pragma unroll
            for (int e = 0; e < 2; e++) {
                float p = __expf(acc[nt][hf * 2 + e] - mx[hf]);
                acc[nt][hf * 2 + e] = p;
                sm[hf] += p;
            }
#pragma unroll
    for (int hf = 0; hf < 2; hf++) {
        sm[hf] += __shfl_xor_sync(0xffffffffu, sm[hf], 1);
        sm[hf] += __shfl_xor_sync(0xffffffffu, sm[hf], 2);
    }
    const float inv0 = 1.f / sm[0], inv1 = 1.f / sm[1];

    uint32_t pa[64];
#pragma unroll
    for (int kt = 0; kt < 16; kt++) {
        const int t0 = 2 * kt, t1 = 2 * kt + 1;
        pa[kt * 4 + 0] = packbf2(acc[t0][0] * inv0, acc[t0][1] * inv0);
        pa[kt * 4 + 1] = packbf2(acc[t0][2] * inv1, acc[t0][3] * inv1);
        pa[kt * 4 + 2] = packbf2(acc[t1][0] * inv0, acc[t1][1] * inv0);
        pa[kt * 4 + 3] = packbf2(acc[t1][2] * inv1, acc[t1][3] * inv1);
    }

    asm volatile("cp.async.wait_group 0;");
    __syncthreads();

    float cacc[8][4];
#pragma unroll
    for (int j = 0; j < 8; j++)
#pragma unroll
        for (int e = 0; e < 4; e++) cacc[j][e] = 0.f;

#pragma unroll
    for (int term = 0; term < 2; term++) {
        const uint32_t vb = term ? uVL : uVH;
#pragma unroll
        for (int kt = 0; kt < 16; kt++) {
            uint32_t bf2[8][2];
#pragma unroll
            for (int np = 0; np < 4; np++) {
                int r = np * 16 + ((lane >> 4) << 3) + (lane & 7);
                int u = kt * 2 + ((lane >> 3) & 1);
                ldsm4(&bf2[np * 2][0], vb + (uint32_t)((r * 32 + (u ^ ((r & 7) << 2))) << 4));
            }
#pragma unroll
            for (int nt = 0; nt < 8; nt++)
                mma16816(cacc[nt], &pa[kt * 4], bf2[nt]);
        }
    }

#pragma unroll
    for (int nt = 0; nt < 8; nt++)
#pragma unroll
        for (int hf = 0; hf < 2; hf++) {
            const int qrow = q0 + warp * 16 + (lane >> 2) + hf * 8;
            const int d = nt * 8 + ((lane & 3) << 1);
            __nv_bfloat162 o;
            o.x = __float2bfloat16_rn(cacc[nt][hf * 2 + 0]);
            o.y = __float2bfloat16_rn(cacc[nt][hf * 2 + 1]);
            *(__nv_bfloat162*)(ctxp + ((size_t)b * 2048 + qrow) * 512 + h * 64 + d) = o;
        }
}

// ======================= small kernels (vectorized) =======================
// 4 floats per thread; hi (and optional lo) written as packed bf16x2 pairs.
__global__ void split_v4(const float4* __restrict__ in, uint2* __restrict__ hi,
                         uint2* __restrict__ lo, int n4)
{
    int i = blockIdx.x * blockDim.x + threadIdx.x;
    if (i < n4) {
        float4 v = in[i];
        uint2 hh;
        hh.x = packbf2(v.x, v.y);
        hh.y = packbf2(v.z, v.w);
        hi[i] = hh;
        if (lo) {
            const __nv_bfloat162* h2 = (const __nv_bfloat162*)&hh;
            uint2 ll;
            ll.x = packbf2(v.x - __bfloat162float(h2[0].x), v.y - __bfloat162float(h2[0].y));
            ll.y = packbf2(v.z - __bfloat162float(h2[1].x), v.w - __bfloat162float(h2[1].y));
            lo[i] = ll;
        }
    }
}

__global__ void split_weights_v4(const float4* __restrict__ w0, const float4* __restrict__ w1,
                                 const float4* __restrict__ w2, const float4* __restrict__ w3,
                                 uint2* __restrict__ base)
{
    int y = blockIdx.y;
    const float4* src = (y == 0) ? w0 : (y == 1) ? w1 : (y == 2) ? w2 : w3;
    uint2* hi = base + (size_t)y * 2 * 65536;
    uint2* lo = hi + 65536;
    int i = blockIdx.x * blockDim.x + threadIdx.x;
    if (i < 65536) {
        float4 v = src[i];
        uint2 hh;
        hh.x = packbf2(v.x, v.y);
        hh.y = packbf2(v.z, v.w);
        hi[i] = hh;
        const __nv_bfloat162* h2 = (const __nv_bfloat162*)&hh;
        uint2 ll;
        ll.x = packbf2(v.x - __bfloat162float(h2[0].x), v.y - __bfloat162float(h2[0].y));
        ll.y = packbf2(v.z - __bfloat162float(h2[1].x), v.w - __bfloat162float(h2[1].y));
        lo[i] = ll;
    }
}

// Barrier-free LN+partial-mean over pre-summed x (bf16), pointer-shifted per half.
__global__ __launch_bounds__(256) void epilogue_ln(
    const bf16* __restrict__ xB,
    const float* __restrict__ lnw, const float* __restrict__ lnb,
    float* __restrict__ part)
{
    const int b = blockIdx.y;
    const int warp = threadIdx.x >> 5, lane = threadIdx.x & 31;
    const int wg = blockIdx.x * 8 + warp;

    float lw[16], lb_[16];
#pragma unroll
    for (int i = 0; i < 16; i++) { lw[i] = lnw[lane * 16 + i]; lb_[i] = lnb[lane * 16 + i]; }

    float acc[16];
#pragma unroll
    for (int i = 0; i < 16; i++) acc[i] = 0.f;

    for (int rr = 0; rr < 32; rr++) {
        const size_t rowo = ((size_t)b * 2048 + wg * 32 + rr) * 512 + lane * 16;
        float x[16];
        const uint4 xa = *(const uint4*)(xB + rowo);
        const uint4 xb = *(const uint4*)(xB + rowo + 8);
        const bf16* x8a = (const bf16*)&xa; const bf16* x8b = (const bf16*)&xb;
#pragma unroll
        for (int i = 0; i < 8; i++) {
            x[i]     = __bfloat162float(x8a[i]);
            x[i + 8] = __bfloat162float(x8b[i]);
        }
        float s = 0.f, s2 = 0.f;
#pragma unroll
        for (int i = 0; i < 16; i++) { s += x[i]; s2 += x[i] * x[i]; }
#pragma unroll
        for (int o = 16; o; o >>= 1) {
            s  += __shfl_xor_sync(0xffffffffu, s, o);
            s2 += __shfl_xor_sync(0xffffffffu, s2, o);
        }
        const float mu = s * (1.f / 512.f);
        const float var = s2 * (1.f / 512.f) - mu * mu;
        const float rs = rsqrtf(var + 1e-5f);
#pragma unroll
        for (int i = 0; i < 16; i++) acc[i] += (x[i] - mu) * rs * lw[i] + lb_[i];
    }
    float* pp = part + ((size_t)b * 64 + wg) * 512 + lane * 16;
#pragma unroll
    for (int i = 0; i < 16; i++) pp[i] = acc[i];
}

__global__ void final_reduce(const float* __restrict__ part, float* __restrict__ out)
{
    int b = blockIdx.x, col = threadIdx.x;
    float s = 0.f;
#pragma unroll
    for (int c = 0; c < 64; c++) s += part[((size_t)b * 64 + c) * Dd + col];
    out[b * Dd + col] = s * (1.f / 2048.f);
}

// ======================= driver =======================
extern "C" void kernel_launch(void* const* d_in, const int* in_sizes, int n_in,
                              void* d_out, int out_size)
{
    (void)in_sizes; (void)n_in; (void)out_size;
    const float* qin  = (const float*)d_in[0];
    const float* sent = (const float*)d_in[1];
    const int*   ns   = (const int*)  d_in[2];
    const float* Wq   = (const float*)d_in[3];
    const float* bq   = (const float*)d_in[4];
    const float* Wk   = (const float*)d_in[5];
    const float* bk   = (const float*)d_in[6];
    const float* Wv   = (const float*)d_in[7];
    const float* bvv  = (const float*)d_in[8];
    const float* Wo   = (const float*)d_in[9];
    const float* bo   = (const float*)d_in[10];
    const float* lnw  = (const float*)d_in[11];
    const float* lnb  = (const float*)d_in[12];
    float* out = (float*)d_out;

    void* p_;
    cudaGetSymbolAddress(&p_, g_qinH_);   bf16* qinH = (bf16*)p_;
    cudaGetSymbolAddress(&p_, g_sentHL_); bf16* sentH = (bf16*)p_; bf16* sentL = sentH + 1048576;
    cudaGetSymbolAddress(&p_, g_W_);      bf16* W = (bf16*)p_;
    bf16 *WqH = W,            *WkH = W + 2*262144;
    bf16 *WvH = W + 4*262144, *WvL = W + 5*262144, *WoH = W + 6*262144, *WoL = W + 7*262144;
    cudaGetSymbolAddress(&p_, g_qH_);    bf16* qH  = (bf16*)p_;
    cudaGetSymbolAddress(&p_, g_kH_);    bf16* kH  = (bf16*)p_;
    cudaGetSymbolAddress(&p_, g_vtHL_);  bf16* vtH = (bf16*)p_;  bf16* vtL = vtH + 1048576;
    cudaGetSymbolAddress(&p_, g_ctxH_);  bf16* ctxH = (bf16*)p_;
    cudaGetSymbolAddress(&p_, g_x_);     bf16* xB = (bf16*)p_;
    cudaGetSymbolAddress(&p_, g_part_);  float* part = (float*)p_;

    constexpr int SM_QO = 3 * (128 * 128 + 128 * 128);  // 98304
    constexpr int SM_KV = 3 * (64 * 128 + 128 * 128);   // 73728
    constexpr int SM_DU = 2 * 49152;                    // 98304
    const size_t HALF = (size_t)8192 * 512;             // 4 batches of rows

    static cudaStream_t sB = nullptr;
    static cudaEvent_t evRoot = nullptr, evW = nullptr, evQin = nullptr,
                       evKV = nullptr, evE2 = nullptr;
    if (!sB) {
        cudaFuncSetAttribute((const void*)gemm_mma<128,128,32,64>,
                             cudaFuncAttributeMaxDynamicSharedMemorySize, SM_QO);
        cudaFuncSetAttribute((const void*)gemm_mma<64,128,32,32>,
                             cudaFuncAttributeMaxDynamicSharedMemorySize, SM_KV);
        cudaFuncSetAttribute((const void*)gemm_dual,
                             cudaFuncAttributeMaxDynamicSharedMemorySize, SM_DU);
        cudaFuncSetAttribute((const void*)attn_fused,
                             cudaFuncAttributeMaxDynamicSharedMemorySize, 114688);
        cudaStreamCreateWithFlags(&sB, cudaStreamNonBlocking);
        cudaEventCreateWithFlags(&evRoot, cudaEventDisableTiming);
        cudaEventCreateWithFlags(&evW,   cudaEventDisableTiming);
        cudaEventCreateWithFlags(&evQin, cudaEventDisableTiming);
        cudaEventCreateWithFlags(&evKV,  cudaEventDisableTiming);
        cudaEventCreateWithFlags(&evE2,  cudaEventDisableTiming);
    }

    // fork root: side stream joins capture via this event FIRST
    cudaEventRecord(evRoot, 0);
    cudaStreamWaitEvent(sB, evRoot, 0);

    // sB: qin split (vectorized) -> (evQin)
    split_v4<<<8192, 256, 0, sB>>>((const float4*)qin, (uint2*)qinH, nullptr, 2097152);
    cudaEventRecord(evQin, sB);

    // s0: weight splits -> (evW) -> sent split -> k-proj -> v-proj -> (evKV)
    split_weights_v4<<<dim3(256, 4), 256>>>(
        (const float4*)Wq, (const float4*)Wk, (const float4*)Wv, (const float4*)Wo,
        (uint2*)W);
    cudaEventRecord(evW, 0);
    split_v4<<<1024, 256>>>((const float4*)sent, (uint2*)sentH, (uint2*)sentL, 262144);
    gemm_mma<64,128,32,32><<<dim3(4, 32, 1), 256, SM_KV>>>(
        sentH, nullptr, nullptr, WkH, nullptr, nullptr, 1, bk,
        nullptr, kH, nullptr, 512, 512, 512, 512,
        1, 0, 0, 0, 0, 0, 0, 1.f, 0);
    gemm_mma<64,128,32,32><<<dim3(4, 32, 1), 256, SM_KV>>>(
        sentH, sentH, sentL, WvH, WvL, WvH, 3, bvv,
        nullptr, vtH, vtL, 512, 512, 512, 512,
        1, 0, 0, 0, 0, 0, 0, 1.f, 1);
    cudaEventRecord(evKV, 0);

    // sB: q-proj half2 (after its own qin split; needs weights)
    cudaStreamWaitEvent(sB, evW, 0);
    gemm_mma<128,128,32,64><<<dim3(4, 64, 1), 256, SM_QO, sB>>>(
        qinH + HALF, nullptr, nullptr, WqH, nullptr, nullptr, 1, bq,
        nullptr, qH + HALF, nullptr, 512, 512, 512, 512,
        1, 0, 0, 0, 0, 0, 0, 1.f, 0);

    // s0: q-proj half1 (needs qin split from sB)
    cudaStreamWaitEvent(0, evQin, 0);
    gemm_mma<128,128,32,64><<<dim3(4, 64, 1), 256, SM_QO>>>(
        qinH, nullptr, nullptr, WqH, nullptr, nullptr, 1, bq,
        nullptr, qH, nullptr, 512, 512, 512, 512,
        1, 0, 0, 0, 0, 0, 0, 1.f, 0);

    // s0: attn1 -> oproj1(+residual) -> ln1
    attn_fused<<<dim3(16, 32), 256, 114688>>>(qH, kH, vtH, vtL, ctxH, ns, 0);
    gemm_dual<<<dim3(4, 64), 256, SM_DU>>>(ctxH, WoH, WoL, bo, qinH, xB);
    epilogue_ln<<<dim3(8, 4), 256>>>(xB, lnw, lnb, part);

    // sB: attn2 -> oproj2(+residual) -> ln2 -> (evE2)
    cudaStreamWaitEvent(sB, evKV, 0);
    attn_fused<<<dim3(16, 32), 256, 114688, sB>>>(qH, kH, vtH, vtL, ctxH, ns, 32);
    gemm_dual<<<dim3(4, 64), 256, SM_DU, sB>>>(ctxH + HALF, WoH, WoL, bo,
                                               qinH + HALF, xB + HALF);
    epilogue_ln<<<dim3(8, 4), 256, 0, sB>>>(xB + HALF, lnw, lnb,
                                            part + (size_t)4 * 64 * 512);
    cudaEventRecord(evE2, sB);

    // s0: join + final reduce
    cudaStreamWaitEvent(0, evE2, 0);
    final_reduce<<<8, 512>>>(part, out);
}

// round 17
// speedup vs baseline: 3.4470x; 1.0652x over previous
#include <cuda_runtime.h>
#include <cuda_bf16.h>
#include <cstdint>
#include <cstddef>

typedef __nv_bfloat16 bf16;

// ======================= portable PTX helpers (sm_80+) =======================
__device__ __forceinline__ uint32_t smem_u32(const void* p) {
    uint32_t a;
    asm("{ .reg .u64 t; cvta.to.shared.u64 t, %1; cvt.u32.u64 %0, t; }" : "=r"(a) : "l"(p));
    return a;
}
__device__ __forceinline__ void cp16(uint32_t dst, const void* src) {
    asm volatile("cp.async.cg.shared.global [%0], [%1], 16;" :: "r"(dst), "l"(src));
}
__device__ __forceinline__ void ldsm4(uint32_t* r, uint32_t a) {
    asm volatile("ldmatrix.sync.aligned.m8n8.x4.shared.b16 {%0,%1,%2,%3}, [%4];"
        : "=r"(r[0]), "=r"(r[1]), "=r"(r[2]), "=r"(r[3]) : "r"(a));
}
__device__ __forceinline__ void mma16816(float* c, const uint32_t* a, const uint32_t* b) {
    asm volatile(
        "mma.sync.aligned.m16n8k16.row.col.f32.bf16.bf16.f32 "
        "{%0,%1,%2,%3}, {%4,%5,%6,%7}, {%8,%9}, {%0,%1,%2,%3};"
        : "+f"(c[0]), "+f"(c[1]), "+f"(c[2]), "+f"(c[3])
        : "r"(a[0]), "r"(a[1]), "r"(a[2]), "r"(a[3]), "r"(b[0]), "r"(b[1]));
}
__device__ __forceinline__ uint32_t packbf2(float lo, float hi) {
    __nv_bfloat162 p;
    p.x = __float2bfloat16_rn(lo);
    p.y = __float2bfloat16_rn(hi);
    return *(uint32_t*)&p;
}

// ======================= constants & scratch =======================
static const int Dd = 512, Ll = 2048;

__device__ uint4 g_qinH_[1048576];        // bf16(Qin)             16 MB
__device__ uint4 g_sentHL_[2 * 131072];   // sentH, sentL
__device__ uint4 g_W_[8 * 32768];         // WqH WqL WkH WkL WvH WvL WoH WoL
__device__ uint4 g_qH_[1048576];          // bf16(q)               16 MB
__device__ uint4 g_kH_[131072];           // kH
__device__ uint4 g_vtHL_[2 * 131072];     // vtH, vtL [bh][64][256]
__device__ uint4 g_ctxH_[1048576];        // bf16(ctx)             16 MB
__device__ uint4 g_x_[2097152];           // fp32 x = qin + attn_out  32 MB
__device__ float g_part_[8 * 64 * 512];   // 1 MB LN partials

// ---------------------------------------------------------------------------
// Generic multi-term bf16 GEMM, BK=64 chunks, 3-stage cp.async, 2 CTAs/SM.
// ---------------------------------------------------------------------------
template<int BM, int BN, int WM, int WN>
__global__ __launch_bounds__(256, 2)
void gemm_mma(const bf16* A0, const bf16* A1, const bf16* A2,
              const bf16* B0, const bf16* B1, const bf16* B2,
              int nterms, const float* __restrict__ bias,
              float* __restrict__ Cf, bf16* __restrict__ Chi, bf16* __restrict__ Clo,
              int Ktot, int lda, int ldb, int ldc,
              int HH, long long sAb, long long sAh, long long sBb, long long sBh,
              long long sCb, long long sCh, float alpha, int vmode)
{
    constexpr int BK = 64;
    constexpr int WARPS_N = BN / WN;
    constexpr int MT = WM / 16, NT = WN / 8;
    constexpr int ASZ = BM * BK * 2, BSZ = BN * BK * 2;
    static_assert((BM / WM) * (BN / WN) == 8, "8 warps");

    extern __shared__ char dynsm[];
    const uint32_t sA0 = smem_u32(dynsm);
    const uint32_t sB0 = sA0 + 3 * ASZ;

    const int tid = threadIdx.x, warp = tid >> 5, lane = tid & 31;
    const int wm = warp / WARPS_N, wn = warp % WARPS_N;

    const bf16* Al[3] = {A0, A1, A2};
    const bf16* Bl[3] = {B0, B1, B2};

    const int z = blockIdx.z;
    const int bz = z / HH, hz = z - bz * HH;
    const long long aoff = (long long)bz * sAb + (long long)hz * sAh;
    const long long boff = (long long)bz * sBb + (long long)hz * sBh;
    const long long coff = (long long)bz * sCb + (long long)hz * sCh;

    const int m0 = blockIdx.y * BM;
    const int n0 = blockIdx.x * BN;

    const int kch = Ktot >> 6;
    const int total = nterms * kch;

    const int fr = tid >> 3, fu = tid & 7;

    float acc[MT][NT][4];
#pragma unroll
    for (int i = 0; i < MT; i++)
#pragma unroll
        for (int j = 0; j < NT; j++)
#pragma unroll
            for (int e = 0; e < 4; e++) acc[i][j][e] = 0.f;

    auto prefetch = [&](int chunk, int buf) {
        const int term = chunk / kch;
        const int k0 = (chunk - term * kch) << 6;
        const bf16* Ag = Al[term] + aoff + k0;
        const uint32_t sA = sA0 + buf * ASZ;
#pragma unroll
        for (int p = 0; p < BM / 32; p++) {
            const int r = fr + p * 32;
            cp16(sA + (uint32_t)((r * 8 + (fu ^ (r & 7))) << 4),
                 Ag + (size_t)(m0 + r) * lda + fu * 8);
        }
        const bf16* Bg = Bl[term] + boff + k0;
        const uint32_t sB = sB0 + buf * BSZ;
#pragma unroll
        for (int p = 0; p < BN / 32; p++) {
            const int r = fr + p * 32;
            cp16(sB + (uint32_t)((r * 8 + (fu ^ (r & 7))) << 4),
                 Bg + (size_t)(n0 + r) * ldb + fu * 8);
        }
        asm volatile("cp.async.commit_group;");
    };

    prefetch(0, 0);
    prefetch(1, 1);
    for (int it = 0; it < total; it++) {
        if (it + 1 < total) asm volatile("cp.async.wait_group 1;");
        else                asm volatile("cp.async.wait_group 0;");
        __syncthreads();
        if (it + 2 < total) prefetch(it + 2, (it + 2) % 3);

        const int buf = it % 3;
        const uint32_t sA = sA0 + buf * ASZ;
        const uint32_t sB = sB0 + buf * BSZ;
#pragma unroll
        for (int kk = 0; kk < 4; kk++) {
            uint32_t af[MT][4];
#pragma unroll
            for (int mt = 0; mt < MT; mt++) {
                const int r = wm * WM + mt * 16 + (lane & 15);
                const int u = (kk << 1) + (lane >> 4);
                ldsm4(af[mt], sA + (uint32_t)((r * 8 + (u ^ (r & 7))) << 4));
            }
            uint32_t bfr[NT][2];
#pragma unroll
            for (int np = 0; np < NT / 2; np++) {
                const int r = wn * WN + np * 16 + ((lane >> 4) << 3) + (lane & 7);
                const int u = (kk << 1) + ((lane >> 3) & 1);
                ldsm4(&bfr[np * 2][0], sB + (uint32_t)((r * 8 + (u ^ (r & 7))) << 4));
            }
#pragma unroll
            for (int mt = 0; mt < MT; mt++)
#pragma unroll
                for (int nt = 0; nt < NT; nt++)
                    mma16816(acc[mt][nt], af[mt], bfr[nt]);
        }
    }

    // ---------------- epilogue ----------------
#pragma unroll
    for (int mt = 0; mt < MT; mt++)
#pragma unroll
        for (int nt = 0; nt < NT; nt++) {
            const int gr0 = m0 + wm * WM + mt * 16 + (lane >> 2);
            const int gc = n0 + wn * WN + nt * 8 + ((lane & 3) << 1);
            const float b0v = bias ? bias[gc] : 0.f;
            const float b1v = bias ? bias[gc + 1] : 0.f;
#pragma unroll
            for (int h2 = 0; h2 < 2; h2++) {
                const int gr = gr0 + h2 * 8;
                const float x0 = alpha * acc[mt][nt][h2 * 2 + 0] + b0v;
                const float x1 = alpha * acc[mt][nt][h2 * 2 + 1] + b1v;
                if (!vmode) {
                    const long long idx = coff + (long long)gr * ldc + gc;
                    if (Cf) { Cf[idx] = x0; Cf[idx + 1] = x1; }
                    if (Chi) {
                        bf16 h0 = __float2bfloat16_rn(x0), h1 = __float2bfloat16_rn(x1);
                        Chi[idx] = h0; Chi[idx + 1] = h1;
                        if (Clo) {
                            Clo[idx] = __float2bfloat16_rn(x0 - __bfloat162float(h0));
                            Clo[idx + 1] = __float2bfloat16_rn(x1 - __bfloat162float(h1));
                        }
                    }
                } else {
                    const int bb = gr >> 8, jj = gr & 255;
#pragma unroll
                    for (int e = 0; e < 2; e++) {
                        const float x = e ? x1 : x0;
                        const int n = gc + e, h = n >> 6, d = n & 63;
                        const size_t off = ((size_t)(bb * 8 + h) * 64 + d) * 256 + jj;
                        bf16 hh = __float2bfloat16_rn(x);
                        Chi[off] = hh;
                        Clo[off] = __float2bfloat16_rn(x - __bfloat162float(hh));
                    }
                }
            }
        }
}

// ---------------------------------------------------------------------------
// Dual-B GEMM for o-proj, fused residual, fp32 out: X = A@B0^T + A@B1^T + bias + Qin
// ---------------------------------------------------------------------------
__global__ __launch_bounds__(256, 2)
void gemm_dual(const bf16* __restrict__ A, const bf16* __restrict__ B0,
               const bf16* __restrict__ B1, const float* __restrict__ bias,
               const bf16* __restrict__ Qr, float* __restrict__ C)
{
    constexpr int STG = 49152;
    extern __shared__ char dynsm[];
    const uint32_t s0 = smem_u32(dynsm);

    const int tid = threadIdx.x, warp = tid >> 5, lane = tid & 31;
    const int wm = warp >> 1, wn = warp & 1;

    const int m0 = blockIdx.y * 128;
    const int n0 = blockIdx.x * 128;
    const int fr = tid >> 3, fu = tid & 7;

    float acc[2][8][4];
#pragma unroll
    for (int i = 0; i < 2; i++)
#pragma unroll
        for (int j = 0; j < 8; j++)
#pragma unroll
            for (int e = 0; e < 4; e++) acc[i][j][e] = 0.f;

    auto prefetch = [&](int chunk, int buf) {
        const int k0 = chunk << 6;
        const uint32_t base = s0 + buf * STG;
#pragma unroll
        for (int p = 0; p < 4; p++) {
            const int r = fr + p * 32;
            const uint32_t off = (uint32_t)((r * 8 + (fu ^ (r & 7))) << 4);
            cp16(base + off,         A  + (size_t)(m0 + r) * 512 + k0 + fu * 8);
            cp16(base + 16384 + off, B0 + (size_t)(n0 + r) * 512 + k0 + fu * 8);
            cp16(base + 32768 + off, B1 + (size_t)(n0 + r) * 512 + k0 + fu * 8);
        }
        asm volatile("cp.async.commit_group;");
    };

    prefetch(0, 0);
    for (int it = 0; it < 8; it++) {
        asm volatile("cp.async.wait_group 0;");
        __syncthreads();
        if (it + 1 < 8) prefetch(it + 1, (it + 1) & 1);

        const uint32_t base = s0 + (it & 1) * STG;
#pragma unroll
        for (int kk = 0; kk < 4; kk++) {
            uint32_t af[2][4];
#pragma unroll
            for (int mt = 0; mt < 2; mt++) {
                const int r = wm * 32 + mt * 16 + (lane & 15);
                const int u = (kk << 1) + (lane >> 4);
                ldsm4(af[mt], base + (uint32_t)((r * 8 + (u ^ (r & 7))) << 4));
            }
#pragma unroll
            for (int term = 0; term < 2; term++) {
                const uint32_t sB = base + 16384 + term * 16384;
                uint32_t bfr[8][2];
#pragma unroll
                for (int np = 0; np < 4; np++) {
                    const int r = wn * 64 + np * 16 + ((lane >> 4) << 3) + (lane & 7);
                    const int u = (kk << 1) + ((lane >> 3) & 1);
                    ldsm4(&bfr[np * 2][0], sB + (uint32_t)((r * 8 + (u ^ (r & 7))) << 4));
                }
#pragma unroll
                for (int mt = 0; mt < 2; mt++)
#pragma unroll
                    for (int nt = 0; nt < 8; nt++)
                        mma16816(acc[mt][nt], af[mt], bfr[nt]);
            }
        }
    }

    // epilogue: bias + residual(Qin) + fp32 store
#pragma unroll
    for (int mt = 0; mt < 2; mt++)
#pragma unroll
        for (int nt = 0; nt < 8; nt++) {
            const int gr0 = m0 + wm * 32 + mt * 16 + (lane >> 2);
            const int gc = n0 + wn * 64 + nt * 8 + ((lane & 3) << 1);
            const float b0v = bias[gc], b1v = bias[gc + 1];
#pragma unroll
            for (int h2 = 0; h2 < 2; h2++) {
                const int gr = gr0 + h2 * 8;
                const __nv_bfloat162 qp = *(const __nv_bfloat162*)(Qr + (size_t)gr * 512 + gc);
                float2 o;
                o.x = acc[mt][nt][h2 * 2 + 0] + b0v + __bfloat162float(qp.x);
                o.y = acc[mt][nt][h2 * 2 + 1] + b1v + __bfloat162float(qp.y);
                *(float2*)(C + (size_t)gr * 512 + gc) = o;
            }
        }
}

// ---------------------------------------------------------------------------
// Fused attention, FA2 register path; bh0 = batch-head offset for halves.
// ---------------------------------------------------------------------------
__global__ __launch_bounds__(256, 1)
void attn_fused(const bf16* __restrict__ qHp, const bf16* __restrict__ kHp,
                const bf16* __restrict__ vtHp, const bf16* __restrict__ vtLp,
                bf16* __restrict__ ctxp, const int* __restrict__ nsp, int bh0)
{
    extern __shared__ char dsm[];
    const uint32_t uQ  = smem_u32(dsm);
    const uint32_t uKH = uQ + 16384;
    const uint32_t uVH = uQ + 49152;
    const uint32_t uVL = uQ + 81920;

    const int tid = threadIdx.x, warp = tid >> 5, lane = tid & 31;
    const int bh = blockIdx.y + bh0, b = bh >> 3, h = bh & 7;
    const int ns = nsp[b];
    const int q0 = blockIdx.x * 128;

    // commit 1: Q + KH (48 KB)
    {
        const bf16* gQ = qHp + ((size_t)b * 2048 + q0) * 512 + h * 64;
#pragma unroll
        for (int t = 0; t < 4; t++) {
            int id = tid + (t << 8);
            int r = id >> 3, u = id & 7;
            cp16(uQ + (uint32_t)((r * 8 + (u ^ (r & 7))) << 4), gQ + (size_t)r * 512 + u * 8);
        }
        const bf16* gKH = kHp + ((size_t)b * 256) * 512 + h * 64;
#pragma unroll
        for (int t = 0; t < 8; t++) {
            int id = tid + (t << 8);
            int r = id >> 3, u = id & 7;
            cp16(uKH + (uint32_t)((r * 8 + (u ^ (r & 7))) << 4), gKH + (size_t)r * 512 + u * 8);
        }
        asm volatile("cp.async.commit_group;");
    }
    // commit 2: VH + VL (64 KB)
    {
        const bf16* gVH = vtHp + (size_t)bh * 16384;
        const bf16* gVL = vtLp + (size_t)bh * 16384;
#pragma unroll
        for (int t = 0; t < 8; t++) {
            int id = tid + (t << 8);
            int r = id >> 5, u = id & 31;
            uint32_t off = (uint32_t)((r * 32 + (u ^ ((r & 7) << 2))) << 4);
            cp16(uVH + off, gVH + (size_t)r * 256 + u * 8);
            cp16(uVL + off, gVL + (size_t)r * 256 + u * 8);
        }
        asm volatile("cp.async.commit_group;");
    }
    asm volatile("cp.async.wait_group 1;");
    __syncthreads();

    float acc[32][4];
#pragma unroll
    for (int j = 0; j < 32; j++)
#pragma unroll
        for (int e = 0; e < 4; e++) acc[j][e] = 0.f;

#pragma unroll
    for (int kk = 0; kk < 4; kk++) {
        uint32_t af[4];
        {
            int r = warp * 16 + (lane & 15);
            int u = kk * 2 + (lane >> 4);
            ldsm4(af, uQ + (uint32_t)((r * 8 + (u ^ (r & 7))) << 4));
        }
#pragma unroll
        for (int nc = 0; nc < 4; nc++) {
            uint32_t bfr[8][2];
#pragma unroll
            for (int np = 0; np < 4; np++) {
                int r = nc * 64 + np * 16 + ((lane >> 4) << 3) + (lane & 7);
                int u = kk * 2 + ((lane >> 3) & 1);
                ldsm4(&bfr[np * 2][0], uKH + (uint32_t)((r * 8 + (u ^ (r & 7))) << 4));
            }
#pragma unroll
            for (int nt = 0; nt < 8; nt++)
                mma16816(acc[nc * 8 + nt], af, bfr[nt]);
        }
    }

    float mx[2] = {-3.0e38f, -3.0e38f};
#pragma unroll
    for (int nt = 0; nt < 32; nt++) {
        const int cb = nt * 8 + ((lane & 3) << 1);
#pragma unroll
        for (int hf = 0; hf < 2; hf++)
#pragma unroll
            for (int e = 0; e < 2; e++) {
                float x = (cb + e < ns) ? 0.125f * acc[nt][hf * 2 + e] : -3.0e38f;
                acc[nt][hf * 2 + e] = x;
                mx[hf] = fmaxf(mx[hf], x);
            }
    }
#pragma unroll
    for (int hf = 0; hf < 2; hf++) {
        mx[hf] = fmaxf(mx[hf], __shfl_xor_sync(0xffffffffu, mx[hf], 1));
        mx[hf] = fmaxf(mx[hf], __shfl_xor_sync(0xffffffffu, mx[hf], 2));
    }
    float sm[2] = {0.f, 0.f};
#pragma unroll
    for (int nt = 0; nt < 32; nt++)
#pragma unroll
        for (int hf = 0; hf < 2; hf++)
#pragma unroll
            for (int e = 0; e < 2; e++) {
                float p = __expf(acc[nt][hf * 2 + e] - mx[hf]);
                acc[nt][hf * 2 + e] = p;
                sm[hf] += p;
            }
#pragma unroll
    for (int hf = 0; hf < 2; hf++) {
        sm[hf] += __shfl_xor_sync(0xffffffffu, sm[hf], 1);
        sm[hf] += __shfl_xor_sync(0xffffffffu, sm[hf], 2);
    }
    const float inv0 = 1.f / sm[0], inv1 = 1.f / sm[1];

    uint32_t pa[64];
#pragma unroll
    for (int kt = 0; kt < 16; kt++) {
        const int t0 = 2 * kt, t1 = 2 * kt + 1;
        pa[kt * 4 + 0] = packbf2(acc[t0][0] * inv0, acc[t0][1] * inv0);
        pa[kt * 4 + 1] = packbf2(acc[t0][2] * inv1, acc[t0][3] * inv1);
        pa[kt * 4 + 2] = packbf2(acc[t1][0] * inv0, acc[t1][1] * inv0);
        pa[kt * 4 + 3] = packbf2(acc[t1][2] * inv1, acc[t1][3] * inv1);
    }

    asm volatile("cp.async.wait_group 0;");
    __syncthreads();

    float cacc[8][4];
#pragma unroll
    for (int j = 0; j < 8; j++)
#pragma unroll
        for (int e = 0; e < 4; e++) cacc[j][e] = 0.f;

#pragma unroll
    for (int term = 0; term < 2; term++) {
        const uint32_t vb = term ? uVL : uVH;
#pragma unroll
        for (int kt = 0; kt < 16; kt++) {
            uint32_t bf2[8][2];
#pragma unroll
            for (int np = 0; np < 4; np++) {
                int r = np * 16 + ((lane >> 4) << 3) + (lane & 7);
                int u = kt * 2 + ((lane >> 3) & 1);
                ldsm4(&bf2[np * 2][0], vb + (uint32_t)((r * 32 + (u ^ ((r & 7) << 2))) << 4));
            }
#pragma unroll
            for (int nt = 0; nt < 8; nt++)
                mma16816(cacc[nt], &pa[kt * 4], bf2[nt]);
        }
    }

#pragma unroll
    for (int nt = 0; nt < 8; nt++)
#pragma unroll
        for (int hf = 0; hf < 2; hf++) {
            const int qrow = q0 + warp * 16 + (lane >> 2) + hf * 8;
            const int d = nt * 8 + ((lane & 3) << 1);
            __nv_bfloat162 o;
            o.x = __float2bfloat16_rn(cacc[nt][hf * 2 + 0]);
            o.y = __float2bfloat16_rn(cacc[nt][hf * 2 + 1]);
            *(__nv_bfloat162*)(ctxp + ((size_t)b * 2048 + qrow) * 512 + h * 64 + d) = o;
        }
}

// ======================= small kernels (vectorized) =======================
__global__ void split_v4(const float4* __restrict__ in, uint2* __restrict__ hi,
                         uint2* __restrict__ lo, int n4)
{
    int i = blockIdx.x * blockDim.x + threadIdx.x;
    if (i < n4) {
        float4 v = in[i];
        uint2 hh;
        hh.x = packbf2(v.x, v.y);
        hh.y = packbf2(v.z, v.w);
        hi[i] = hh;
        if (lo) {
            const __nv_bfloat162* h2 = (const __nv_bfloat162*)&hh;
            uint2 ll;
            ll.x = packbf2(v.x - __bfloat162float(h2[0].x), v.y - __bfloat162float(h2[0].y));
            ll.y = packbf2(v.z - __bfloat162float(h2[1].x), v.w - __bfloat162float(h2[1].y));
            lo[i] = ll;
        }
    }
}

__global__ void split_weights_v4(const float4* __restrict__ w0, const float4* __restrict__ w1,
                                 const float4* __restrict__ w2, const float4* __restrict__ w3,
                                 uint2* __restrict__ base)
{
    int y = blockIdx.y;
    const float4* src = (y == 0) ? w0 : (y == 1) ? w1 : (y == 2) ? w2 : w3;
    uint2* hi = base + (size_t)y * 2 * 65536;
    uint2* lo = hi + 65536;
    int i = blockIdx.x * blockDim.x + threadIdx.x;
    if (i < 65536) {
        float4 v = src[i];
        uint2 hh;
        hh.x = packbf2(v.x, v.y);
        hh.y = packbf2(v.z, v.w);
        hi[i] = hh;
        const __nv_bfloat162* h2 = (const __nv_bfloat162*)&hh;
        uint2 ll;
        ll.x = packbf2(v.x - __bfloat162float(h2[0].x), v.y - __bfloat162float(h2[0].y));
        ll.y = packbf2(v.z - __bfloat162float(h2[1].x), v.w - __bfloat162float(h2[1].y));
        lo[i] = ll;
    }
}

// Barrier-free LN+partial-mean over fp32 x, pointer-shifted per half.
__global__ __launch_bounds__(256) void epilogue_ln(
    const float* __restrict__ xF,
    const float* __restrict__ lnw, const float* __restrict__ lnb,
    float* __restrict__ part)
{
    const int b = blockIdx.y;
    const int warp = threadIdx.x >> 5, lane = threadIdx.x & 31;
    const int wg = blockIdx.x * 8 + warp;

    float lw[16], lb_[16];
#pragma unroll
    for (int i = 0; i < 16; i++) { lw[i] = lnw[lane * 16 + i]; lb_[i] = lnb[lane * 16 + i]; }

    float acc[16];
#pragma unroll
    for (int i = 0; i < 16; i++) acc[i] = 0.f;

    for (int rr = 0; rr < 32; rr++) {
        const size_t rowo = ((size_t)b * 2048 + wg * 32 + rr) * 512 + lane * 16;
        float x[16];
        const float4 xa = *(const float4*)(xF + rowo);
        const float4 xb = *(const float4*)(xF + rowo + 4);
        const float4 xc = *(const float4*)(xF + rowo + 8);
        const float4 xd = *(const float4*)(xF + rowo + 12);
        x[0] = xa.x;  x[1] = xa.y;  x[2] = xa.z;  x[3] = xa.w;
        x[4] = xb.x;  x[5] = xb.y;  x[6] = xb.z;  x[7] = xb.w;
        x[8] = xc.x;  x[9] = xc.y;  x[10] = xc.z; x[11] = xc.w;
        x[12] = xd.x; x[13] = xd.y; x[14] = xd.z; x[15] = xd.w;
        float s = 0.f, s2 = 0.f;
#pragma unroll
        for (int i = 0; i < 16; i++) { s += x[i]; s2 += x[i] * x[i]; }
#pragma unroll
        for (int o = 16; o; o >>= 1) {
            s  += __shfl_xor_sync(0xffffffffu, s, o);
            s2 += __shfl_xor_sync(0xffffffffu, s2, o);
        }
        const float mu = s * (1.f / 512.f);
        const float var = s2 * (1.f / 512.f) - mu * mu;
        const float rs = rsqrtf(var + 1e-5f);
#pragma unroll
        for (int i = 0; i < 16; i++) acc[i] += (x[i] - mu) * rs * lw[i] + lb_[i];
    }
    float* pp = part + ((size_t)b * 64 + wg) * 512 + lane * 16;
#pragma unroll
    for (int i = 0; i < 16; i++) pp[i] = acc[i];
}

__global__ void final_reduce(const float* __restrict__ part, float* __restrict__ out)
{
    int b = blockIdx.x, col = threadIdx.x;
    float s = 0.f;
#pragma unroll
    for (int c = 0; c < 64; c++) s += part[((size_t)b * 64 + c) * Dd + col];
    out[b * Dd + col] = s * (1.f / 2048.f);
}

// ======================= driver =======================
extern "C" void kernel_launch(void* const* d_in, const int* in_sizes, int n_in,
                              void* d_out, int out_size)
{
    (void)in_sizes; (void)n_in; (void)out_size;
    const float* qin  = (const float*)d_in[0];
    const float* sent = (const float*)d_in[1];
    const int*   ns   = (const int*)  d_in[2];
    const float* Wq   = (const float*)d_in[3];
    const float* bq   = (const float*)d_in[4];
    const float* Wk   = (const float*)d_in[5];
    const float* bk   = (const float*)d_in[6];
    const float* Wv   = (const float*)d_in[7];
    const float* bvv  = (const float*)d_in[8];
    const float* Wo   = (const float*)d_in[9];
    const float* bo   = (const float*)d_in[10];
    const float* lnw  = (const float*)d_in[11];
    const float* lnb  = (const float*)d_in[12];
    float* out = (float*)d_out;

    void* p_;
    cudaGetSymbolAddress(&p_, g_qinH_);   bf16* qinH = (bf16*)p_;
    cudaGetSymbolAddress(&p_, g_sentHL_); bf16* sentH = (bf16*)p_; bf16* sentL = sentH + 1048576;
    cudaGetSymbolAddress(&p_, g_W_);      bf16* W = (bf16*)p_;
    bf16 *WqH = W,            *WkH = W + 2*262144;
    bf16 *WvH = W + 4*262144, *WvL = W + 5*262144, *WoH = W + 6*262144, *WoL = W + 7*262144;
    cudaGetSymbolAddress(&p_, g_qH_);    bf16* qH  = (bf16*)p_;
    cudaGetSymbolAddress(&p_, g_kH_);    bf16* kH  = (bf16*)p_;
    cudaGetSymbolAddress(&p_, g_vtHL_);  bf16* vtH = (bf16*)p_;  bf16* vtL = vtH + 1048576;
    cudaGetSymbolAddress(&p_, g_ctxH_);  bf16* ctxH = (bf16*)p_;
    cudaGetSymbolAddress(&p_, g_x_);     float* xF = (float*)p_;
    cudaGetSymbolAddress(&p_, g_part_);  float* part = (float*)p_;

    constexpr int SM_QO = 3 * (128 * 128 + 128 * 128);  // 98304
    constexpr int SM_KV = 3 * (64 * 128 + 128 * 128);   // 73728
    constexpr int SM_DU = 2 * 49152;                    // 98304
    const size_t HALFB = (size_t)8192 * 512;            // 4 batches, bf16 elems
    const size_t HALFF = (size_t)8192 * 512;            // 4 batches, fp32 elems

    static cudaStream_t sB = nullptr;
    static cudaEvent_t evRoot = nullptr, evW = nullptr, evSent = nullptr,
                       evQin = nullptr, evK = nullptr, evKV = nullptr, evE2 = nullptr;
    if (!sB) {
        cudaFuncSetAttribute((const void*)gemm_mma<128,128,32,64>,
                             cudaFuncAttributeMaxDynamicSharedMemorySize, SM_QO);
        cudaFuncSetAttribute((const void*)gemm_mma<64,128,32,32>,
                             cudaFuncAttributeMaxDynamicSharedMemorySize, SM_KV);
        cudaFuncSetAttribute((const void*)gemm_dual,
                             cudaFuncAttributeMaxDynamicSharedMemorySize, SM_DU);
        cudaFuncSetAttribute((const void*)attn_fused,
                             cudaFuncAttributeMaxDynamicSharedMemorySize, 114688);
        cudaStreamCreateWithFlags(&sB, cudaStreamNonBlocking);
        cudaEventCreateWithFlags(&evRoot, cudaEventDisableTiming);
        cudaEventCreateWithFlags(&evW,    cudaEventDisableTiming);
        cudaEventCreateWithFlags(&evSent, cudaEventDisableTiming);
        cudaEventCreateWithFlags(&evQin,  cudaEventDisableTiming);
        cudaEventCreateWithFlags(&evK,    cudaEventDisableTiming);
        cudaEventCreateWithFlags(&evKV,   cudaEventDisableTiming);
        cudaEventCreateWithFlags(&evE2,   cudaEventDisableTiming);
    }

    // fork root: side stream joins capture via this event FIRST
    cudaEventRecord(evRoot, 0);
    cudaStreamWaitEvent(sB, evRoot, 0);

    // sB: qin split -> (evQin)
    split_v4<<<8192, 256, 0, sB>>>((const float4*)qin, (uint2*)qinH, nullptr, 2097152);
    cudaEventRecord(evQin, sB);

    // s0: weight splits -> (evW) -> sent split -> (evSent) -> v-proj -> (evKV)
    split_weights_v4<<<dim3(256, 4), 256>>>(
        (const float4*)Wq, (const float4*)Wk, (const float4*)Wv, (const float4*)Wo,
        (uint2*)W);
    cudaEventRecord(evW, 0);
    split_v4<<<1024, 256>>>((const float4*)sent, (uint2*)sentH, (uint2*)sentL, 262144);
    cudaEventRecord(evSent, 0);
    gemm_mma<64,128,32,32><<<dim3(4, 32, 1), 256, SM_KV>>>(
        sentH, sentH, sentL, WvH, WvL, WvH, 3, bvv,
        nullptr, vtH, vtL, 512, 512, 512, 512,
        1, 0, 0, 0, 0, 0, 0, 1.f, 1);
    cudaEventRecord(evKV, 0);

    // sB: k-proj (needs weights + sent split), then q-proj half2
    cudaStreamWaitEvent(sB, evW, 0);
    cudaStreamWaitEvent(sB, evSent, 0);
    gemm_mma<64,128,32,32><<<dim3(4, 32, 1), 256, SM_KV, sB>>>(
        sentH, nullptr, nullptr, WkH, nullptr, nullptr, 1, bk,
        nullptr, kH, nullptr, 512, 512, 512, 512,
        1, 0, 0, 0, 0, 0, 0, 1.f, 0);
    cudaEventRecord(evK, sB);
    gemm_mma<128,128,32,64><<<dim3(4, 64, 1), 256, SM_QO, sB>>>(
        qinH + HALFB, nullptr, nullptr, WqH, nullptr, nullptr, 1, bq,
        nullptr, qH + HALFB, nullptr, 512, 512, 512, 512,
        1, 0, 0, 0, 0, 0, 0, 1.f, 0);

    // s0: q-proj half1 (needs qin split from sB)
    cudaStreamWaitEvent(0, evQin, 0);
    gemm_mma<128,128,32,64><<<dim3(4, 64, 1), 256, SM_QO>>>(
        qinH, nullptr, nullptr, WqH, nullptr, nullptr, 1, bq,
        nullptr, qH, nullptr, 512, 512, 512, 512,
        1, 0, 0, 0, 0, 0, 0, 1.f, 0);

    // s0: attn1 (needs kH from sB) -> oproj1(+residual) -> ln1
    cudaStreamWaitEvent(0, evK, 0);
    attn_fused<<<dim3(16, 32), 256, 114688>>>(qH, kH, vtH, vtL, ctxH, ns, 0);
    gemm_dual<<<dim3(4, 64), 256, SM_DU>>>(ctxH, WoH, WoL, bo, qinH, xF);
    epilogue_ln<<<dim3(8, 4), 256>>>(xF, lnw, lnb, part);

    // sB: attn2 (needs vproj from s0) -> oproj2 -> ln2 -> (evE2)
    cudaStreamWaitEvent(sB, evKV, 0);
    attn_fused<<<dim3(16, 32), 256, 114688, sB>>>(qH, kH, vtH, vtL, ctxH, ns, 32);
    gemm_dual<<<dim3(4, 64), 256, SM_DU, sB>>>(ctxH + HALFB, WoH, WoL, bo,
                                               qinH + HALFB, xF + HALFF);
    epilogue_ln<<<dim3(8, 4), 256, 0, sB>>>(xF + HALFF, lnw, lnb,
                                            part + (size_t)4 * 64 * 512);
    cudaEventRecord(evE2, sB);

    // s0: join + final reduce
    cudaStreamWaitEvent(0, evE2, 0);
    final_reduce<<<8, 512>>>(part, out);
}